// round 2
// baseline (speedup 1.0000x reference)
#include <cuda_runtime.h>
#include <math.h>
#include <stdint.h>

#define NL 4
#define BB 4
#define SS_ 512
#define DD 512
#define HH 8
#define KVN 1152

#define EL_X   1048576ull
#define EL_KV  2359296ull

constexpr size_t O_X    = 0;
constexpr size_t O_KV   = O_X    + EL_X;
constexpr size_t O_Q    = O_KV   + EL_KV;
constexpr size_t O_K    = O_Q    + EL_X;
constexpr size_t O_V    = O_K    + EL_KV;
constexpr size_t O_ATT  = O_V    + EL_KV;
constexpr size_t O_A    = O_ATT  + EL_X;
constexpr size_t O_TMP  = O_A    + EL_X;
constexpr size_t O_QR   = O_TMP  + EL_X;
constexpr size_t O_KR   = O_QR   + EL_X;
constexpr size_t O_VR   = O_KR   + EL_X;
constexpr size_t O_KN   = O_VR   + EL_X;
constexpr size_t O_VN   = O_KN   + 262144ull;
constexpr size_t O_TGT  = O_VN   + 262144ull;
constexpr size_t O_RNEW = O_TGT  + EL_X;
constexpr size_t O_NCM  = O_RNEW + EL_X;
constexpr size_t O_CWT  = O_NCM  + 262144ull;
constexpr size_t O_FF   = O_CWT  + EL_X;
constexpr size_t O_Y    = O_FF   + 4194304ull;
constexpr size_t O_X1   = O_Y    + EL_X;
constexpr size_t O_PART = O_X1   + EL_X;
constexpr size_t O_LOSS = O_PART + 1024ull;
constexpr size_t SCRATCH_TOTAL = O_LOSS + 16ull;

__device__ float g_scratch[SCRATCH_TOTAL];

__device__ __forceinline__ float block_sum(float v, float* sbuf, int nthreads) {
    int lane = threadIdx.x & 31, w = threadIdx.x >> 5;
    #pragma unroll
    for (int o = 16; o; o >>= 1) v += __shfl_xor_sync(0xffffffffu, v, o);
    __syncthreads();
    if (lane == 0) sbuf[w] = v;
    __syncthreads();
    int nw = nthreads >> 5;
    float r = 0.f;
    for (int i = 0; i < nw; i++) r += sbuf[i];
    return r;
}

__global__ void zero_loss_kernel(float* loss) { if (threadIdx.x == 0) loss[0] = 0.f; }

__global__ void embed_kernel(const int* __restrict__ trg, const float* __restrict__ emb,
                             float* __restrict__ x) {
    size_t idx = (size_t)blockIdx.x * blockDim.x + threadIdx.x;
    if (idx >= EL_X) return;
    int row = (int)(idx >> 9);
    int d   = (int)(idx & 511);
    x[idx] = emb[(size_t)trg[row] * 512 + d];
}

__global__ void kv_kernel(const float* __restrict__ cm, const float* __restrict__ mem,
                          const float* __restrict__ x, float* __restrict__ kv) {
    size_t idx = (size_t)blockIdx.x * blockDim.x + threadIdx.x;
    if (idx >= EL_KV) return;
    int b   = (int)(idx / ((size_t)KVN * DD));
    int rem = (int)(idx - (size_t)b * KVN * DD);
    int p = rem >> 9, d = rem & 511;
    float val;
    if (p < 128)       val = cm [(size_t)b * 128 * 512 + ((size_t)p << 9) + d];
    else if (p < 640)  val = mem[(size_t)b * 512 * 512 + ((size_t)(p - 128) << 9) + d];
    else               val = x  [(size_t)b * 512 * 512 + ((size_t)(p - 640) << 9) + d];
    kv[idx] = val;
}

// conv_w (O=512, D=512, R=4) -> cwt[k=r*512+d][o]
__global__ void tconv_kernel(const float* __restrict__ cw, float* __restrict__ cwt) {
    size_t idx = (size_t)blockIdx.x * blockDim.x + threadIdx.x;
    if (idx >= 2048ull * 512ull) return;
    int o = (int)(idx & 511);
    int k = (int)(idx >> 9);
    int d = k & 511;
    int r = k >> 9;
    cwt[idx] = cw[((size_t)o * 512 + d) * 4 + r];
}

__global__ void out_kernel(float* __restrict__ o, const float* __restrict__ x,
                           const float* __restrict__ loss, size_t nout) {
    size_t i = (size_t)blockIdx.x * blockDim.x + threadIdx.x;
    if (i >= nout) return;
    if (i < EL_X) o[i] = x[i];
    else          o[i] = loss[0] * (1.f / (1048576.f * 4.f));
}

__global__ void __launch_bounds__(128) ln_kernel(const float* __restrict__ in,
                                                 const float* __restrict__ g,
                                                 const float* __restrict__ bb,
                                                 float* __restrict__ out) {
    __shared__ float sbuf[8];
    const int row = blockIdx.x, tid = threadIdx.x;
    const size_t base = (size_t)row * 512 + (size_t)tid * 4;
    float4 v4 = *(const float4*)(in + base);
    float v[4] = {v4.x, v4.y, v4.z, v4.w};
    float s = v[0] + v[1] + v[2] + v[3];
    s = block_sum(s, sbuf, 128);
    float mu = s * (1.f / 512.f);
    float d2 = 0.f;
    #pragma unroll
    for (int j = 0; j < 4; j++) { float t = v[j] - mu; d2 += t * t; }
    d2 = block_sum(d2, sbuf, 128);
    float rs = rsqrtf(d2 * (1.f / 512.f) + 1e-5f);
    int c = tid * 4;
    float4 o;
    o.x = (v[0] - mu) * rs * g[c + 0] + bb[c + 0];
    o.y = (v[1] - mu) * rs * g[c + 1] + bb[c + 1];
    o.z = (v[2] - mu) * rs * g[c + 2] + bb[c + 2];
    o.w = (v[3] - mu) * rs * g[c + 3] + bb[c + 3];
    *(float4*)(out + base) = o;
}

__global__ void __launch_bounds__(256) loss_part_kernel(const float* __restrict__ a,
                                                        const float* __restrict__ b,
                                                        float* __restrict__ part) {
    __shared__ float sbuf[8];
    size_t base = (size_t)blockIdx.x * 1024 + (size_t)threadIdx.x * 4;
    float4 x = *(const float4*)(a + base);
    float4 y = *(const float4*)(b + base);
    float dx = x.x - y.x, dy = x.y - y.y, dz = x.z - y.z, dw = x.w - y.w;
    float s = dx * dx + dy * dy + dz * dz + dw * dw;
    s = block_sum(s, sbuf, 256);
    if (threadIdx.x == 0) part[blockIdx.x] = s;
}

__global__ void __launch_bounds__(256) loss_acc_kernel(const float* __restrict__ part,
                                                       float* __restrict__ loss) {
    __shared__ float sbuf[8];
    int tid = threadIdx.x;
    float s = part[tid] + part[tid + 256] + part[tid + 512] + part[tid + 768];
    s = block_sum(s, sbuf, 256);
    if (tid == 0) loss[0] += s;
}

// C[M,N] = A[M,K] @ B[K,N] (+bias)(+gelu)(+resid).  M,N %64==0, K%16==0.
__global__ void __launch_bounds__(256) gemm_kernel(const float* __restrict__ A,
                                                   const float* __restrict__ B,
                                                   float* __restrict__ C,
                                                   int M, int N, int K,
                                                   const float* __restrict__ bias,
                                                   const float* __restrict__ resid,
                                                   int act) {
    __shared__ float As[16][68];
    __shared__ float Bs[16][68];
    const int tid = threadIdx.x;
    const int tx = tid & 15, ty = tid >> 4;
    const int m0 = blockIdx.y << 6, n0 = blockIdx.x << 6;
    const int la_m = tid >> 2, la_k = (tid & 3) << 2;
    const int lb_k = tid >> 4, lb_n = (tid & 15) << 2;
    float acc[4][4] = {};
    const float* Aptr = A + (size_t)(m0 + la_m) * K + la_k;
    const float* Bptr = B + (size_t)lb_k * N + n0 + lb_n;
    for (int k0 = 0; k0 < K; k0 += 16) {
        float4 av = *(const float4*)(Aptr + k0);
        float4 bv = *(const float4*)(Bptr + (size_t)k0 * N);
        __syncthreads();
        As[la_k + 0][la_m] = av.x;
        As[la_k + 1][la_m] = av.y;
        As[la_k + 2][la_m] = av.z;
        As[la_k + 3][la_m] = av.w;
        *(float4*)&Bs[lb_k][lb_n] = bv;
        __syncthreads();
        #pragma unroll
        for (int kk = 0; kk < 16; kk++) {
            float4 a = *(const float4*)&As[kk][ty << 2];
            float4 b = *(const float4*)&Bs[kk][tx << 2];
            acc[0][0] += a.x * b.x; acc[0][1] += a.x * b.y; acc[0][2] += a.x * b.z; acc[0][3] += a.x * b.w;
            acc[1][0] += a.y * b.x; acc[1][1] += a.y * b.y; acc[1][2] += a.y * b.z; acc[1][3] += a.y * b.w;
            acc[2][0] += a.z * b.x; acc[2][1] += a.z * b.y; acc[2][2] += a.z * b.z; acc[2][3] += a.z * b.w;
            acc[3][0] += a.w * b.x; acc[3][1] += a.w * b.y; acc[3][2] += a.w * b.z; acc[3][3] += a.w * b.w;
        }
    }
    #pragma unroll
    for (int i = 0; i < 4; i++) {
        int m = m0 + (ty << 2) + i;
        #pragma unroll
        for (int j = 0; j < 4; j++) {
            int n = n0 + (tx << 2) + j;
            float c = acc[i][j];
            if (bias)  c += bias[n];
            if (act)   c = 0.5f * c * (1.f + erff(c * 0.7071067811865475f));
            if (resid) c += resid[(size_t)m * N + n];
            C[(size_t)m * N + n] = c;
        }
    }
}

// fused attention: q(B,qlen,512) k,v(B,klen,512) per-head cols [h*64,h*64+64)
// POS: score[q,m] += sc_pos * (q . pos[h, m+qlen-1-q])  when that index < klen
template <bool POS>
__global__ void __launch_bounds__(256) attn_kernel(const float* __restrict__ q,
                                                   const float* __restrict__ k,
                                                   const float* __restrict__ v,
                                                   float* __restrict__ out,
                                                   const float* __restrict__ pos,
                                                   int qlen, int klen,
                                                   float sc_qk, float sc_pos) {
    extern __shared__ float smf[];
    float* ss = smf;                 // 8*klen
    float* qs = ss + 8 * klen;       // 512
    float* ks = qs + 512;            // 32*65
    float* ps = ks + 32 * 65;        // 40*65 (POS only)
    const int tid = threadIdx.x;
    const int b = blockIdx.z, h = blockIdx.y, q0 = blockIdx.x << 3;

    for (int i = tid; i < 8 * 64; i += 256) {
        int qi = i >> 6, d = i & 63;
        qs[i] = q[(size_t)(b * qlen + q0 + qi) * 512 + h * 64 + d];
    }
    __syncthreads();
    const int sqi = tid >> 5, smm = tid & 31;
    float qreg[64];
    #pragma unroll
    for (int d = 0; d < 64; d++) qreg[d] = qs[sqi * 64 + d];

    for (int kc = 0; kc < klen; kc += 32) {
        __syncthreads();
        for (int i = tid; i < 32 * 64; i += 256) {
            int r = i >> 6, d = i & 63;
            ks[r * 65 + d] = k[(size_t)(b * klen + kc + r) * 512 + h * 64 + d];
        }
        if (POS) {
            int rel0 = kc + qlen - 8 - q0;
            for (int i = tid; i < 40 * 64; i += 256) {
                int r = i >> 6, d = i & 63;
                int rel = rel0 + r;
                ps[r * 65 + d] = (rel < klen && rel >= 0) ? pos[(size_t)(h * klen + rel) * 64 + d] : 0.f;
            }
        }
        __syncthreads();
        float acc = 0.f, pacc = 0.f;
        const float* kr = ks + smm * 65;
        const float* pr = POS ? (ps + (smm + 7 - sqi) * 65) : ks;
        #pragma unroll
        for (int d = 0; d < 64; d++) {
            acc += qreg[d] * kr[d];
            if (POS) pacc += qreg[d] * pr[d];
        }
        ss[sqi * klen + kc + smm] = POS ? (acc * sc_qk + pacc * sc_pos) : (acc * sc_qk);
    }
    __syncthreads();

    {
        int w = tid >> 5, lane = tid & 31;
        float* row = ss + w * klen;
        float mx = -1e30f;
        for (int j = lane; j < klen; j += 32) mx = fmaxf(mx, row[j]);
        #pragma unroll
        for (int o = 16; o; o >>= 1) mx = fmaxf(mx, __shfl_xor_sync(0xffffffffu, mx, o));
        float sum = 0.f;
        for (int j = lane; j < klen; j += 32) { float e = expf(row[j] - mx); row[j] = e; sum += e; }
        #pragma unroll
        for (int o = 16; o; o >>= 1) sum += __shfl_xor_sync(0xffffffffu, sum, o);
        float inv = 1.f / sum;
        for (int j = lane; j < klen; j += 32) row[j] *= inv;
    }

    const int d = tid & 63, g = tid >> 6;
    float o0 = 0.f, o1 = 0.f;
    for (int kc = 0; kc < klen; kc += 32) {
        __syncthreads();
        for (int i = tid; i < 32 * 64; i += 256) {
            int r = i >> 6, dd = i & 63;
            ks[r * 65 + dd] = v[(size_t)(b * klen + kc + r) * 512 + h * 64 + dd];
        }
        __syncthreads();
        #pragma unroll
        for (int mm = 0; mm < 32; mm++) {
            float vv = ks[mm * 65 + d];
            o0 += ss[g * klen + kc + mm] * vv;
            o1 += ss[(g + 4) * klen + kc + mm] * vv;
        }
    }
    out[(size_t)(b * qlen + q0 + g) * 512 + h * 64 + d] = o0;
    out[(size_t)(b * qlen + q0 + g + 4) * 512 + h * 64 + d] = o1;
}

static void gemm(const float* A, const float* B, float* C, int M, int N, int K,
                 const float* bias = nullptr, const float* resid = nullptr, int act = 0) {
    dim3 grid(N / 64, M / 64);
    gemm_kernel<<<grid, 256>>>(A, B, C, M, N, K, bias, resid, act);
}

static void attn(const float* q, const float* k, const float* v, float* o,
                 const float* pos, int qlen, int klen, bool use_pos) {
    dim3 grid(qlen / 8, HH, BB);
    if (use_pos) {
        size_t smem = (size_t)(8 * klen + 512 + 32 * 65 + 40 * 65) * 4;
        attn_kernel<true><<<grid, 256, smem>>>(q, k, v, o, pos, qlen, klen, 0.125f, 8.f);
    } else {
        size_t smem = (size_t)(8 * klen + 512 + 32 * 65) * 4;
        attn_kernel<false><<<grid, 256, smem>>>(q, k, v, o, nullptr, qlen, klen, 0.125f, 0.f);
    }
}

extern "C" void kernel_launch(void* const* d_in, const int* in_sizes, int n_in,
                              void* d_out, int out_size) {
    const int*   trg     = (const int*)  d_in[0];
    const float* latent  = (const float*)d_in[3];
    const float* mems    = (const float*)d_in[4];
    const float* cmems   = (const float*)d_in[5];
    const float* pos_emb = (const float*)d_in[6];
    const float* embed   = (const float*)d_in[7];
    const float* W_self  = (const float*)d_in[8];
    const float* ln1_g   = (const float*)d_in[9];
    const float* ln1_b   = (const float*)d_in[10];
    const float* conv_w  = (const float*)d_in[11];
    const float* conv_b  = (const float*)d_in[12];
    const float* W_src   = (const float*)d_in[13];
    const float* ln2_g   = (const float*)d_in[14];
    const float* ln2_b   = (const float*)d_in[15];
    const float* w1      = (const float*)d_in[16];
    const float* b1      = (const float*)d_in[17];
    const float* w2      = (const float*)d_in[18];
    const float* b2      = (const float*)d_in[19];

    float* S;
    cudaGetSymbolAddress((void**)&S, g_scratch);
    float* X    = S + O_X;
    float* KVb  = S + O_KV;
    float* Q    = S + O_Q;
    float* K    = S + O_K;
    float* V    = S + O_V;
    float* ATT  = S + O_ATT;
    float* A    = S + O_A;
    float* TMP  = S + O_TMP;
    float* QR   = S + O_QR;
    float* KR   = S + O_KR;
    float* VR   = S + O_VR;
    float* KN   = S + O_KN;
    float* VN   = S + O_VN;
    float* TGT  = S + O_TGT;
    float* RNEW = S + O_RNEW;
    float* NCM  = S + O_NCM;
    float* CWT  = S + O_CWT;
    float* FF   = S + O_FF;
    float* Y    = S + O_Y;
    float* X1   = S + O_X1;
    float* PART = S + O_PART;
    float* LOSS = S + O_LOSS;

    cudaFuncSetAttribute(attn_kernel<true>, cudaFuncAttributeMaxDynamicSharedMemorySize, 65536);
    cudaFuncSetAttribute(attn_kernel<false>, cudaFuncAttributeMaxDynamicSharedMemorySize, 65536);

    zero_loss_kernel<<<1, 32>>>(LOSS);
    embed_kernel<<<(int)(EL_X / 256), 256>>>(trg, embed, X);

    for (int i = 0; i < NL; i++) {
        const float* mem = mems  + (size_t)i * BB * 512 * 512;
        const float* cm  = cmems + (size_t)i * BB * 128 * 512;
        const float* W0 = W_self + ((size_t)i * 4 + 0) * 512 * 512;
        const float* W1 = W_self + ((size_t)i * 4 + 1) * 512 * 512;
        const float* W2 = W_self + ((size_t)i * 4 + 2) * 512 * 512;
        const float* W3 = W_self + ((size_t)i * 4 + 3) * 512 * 512;
        const float* Ws0 = W_src + ((size_t)i * 4 + 0) * 512 * 512;
        const float* Ws1 = W_src + ((size_t)i * 4 + 1) * 512 * 512;
        const float* Ws2 = W_src + ((size_t)i * 4 + 2) * 512 * 512;
        const float* Ws3 = W_src + ((size_t)i * 4 + 3) * 512 * 512;

        // self-attention over kv = [cmem, mem, x]
        kv_kernel<<<(int)(EL_KV / 256), 256>>>(cm, mem, X, KVb);
        gemm(X,   W0, Q, 2048, 512, 512);
        gemm(KVb, W1, K, 4608, 512, 512);
        gemm(KVb, W2, V, 4608, 512, 512);
        attn(Q, K, V, ATT, pos_emb, 512, KVN, true);
        gemm(ATT, W3, TMP, 2048, 512, 512, nullptr, X, 0);
        ln_kernel<<<2048, 128>>>(TMP, ln1_g + i * 512, ln1_b + i * 512, A);

        // compressed-memory reconstruction loss
        tconv_kernel<<<4096, 256>>>(conv_w + (size_t)i * 512 * 512 * 4, CWT);
        gemm(mem, CWT, NCM, 512, 512, 2048, conv_b + i * 512);
        gemm(A,   W0, QR, 2048, 512, 512);
        gemm(mem, W1, KR, 2048, 512, 512);
        gemm(mem, W2, VR, 2048, 512, 512);
        attn(QR, KR, VR, TGT, nullptr, 512, 512, false);
        gemm(NCM, W1, KN, 512, 512, 512);
        gemm(NCM, W2, VN, 512, 512, 512);
        attn(QR, KN, VN, RNEW, nullptr, 512, 128, false);
        loss_part_kernel<<<1024, 256>>>(RNEW, TGT, PART);
        loss_acc_kernel<<<1, 256>>>(PART, LOSS);

        // cross-attention to latent (no residual on output!)
        gemm(A,      Ws0, QR, 2048, 512, 512);
        gemm(latent, Ws1, KR, 1024, 512, 512);
        gemm(latent, Ws2, VR, 1024, 512, 512);
        attn(QR, KR, VR, TMP, nullptr, 512, 256, false);
        gemm(TMP, Ws3, X1, 2048, 512, 512);

        // FFN with pre-LN branch: x = x1 + gelu(LN(x1)@w1+b1)@w2 + b2
        ln_kernel<<<2048, 128>>>(X1, ln2_g + i * 512, ln2_b + i * 512, Y);
        gemm(Y,  w1 + (size_t)i * 512 * 2048, FF, 2048, 2048, 512,  b1 + (size_t)i * 2048, nullptr, 1);
        gemm(FF, w2 + (size_t)i * 2048 * 512, X,  2048, 512,  2048, b2 + (size_t)i * 512,  X1,      0);
    }

    size_t nout = (size_t)out_size;
    out_kernel<<<(int)((nout + 255) / 256), 256>>>((float*)d_out, X, LOSS, nout);
}

// round 3
// speedup vs baseline: 1.0437x; 1.0437x over previous
#include <cuda_runtime.h>
#include <math.h>
#include <stdint.h>

#define NL 4
#define BB 4
#define DD 512
#define HH 8
#define KVN 1152

#define EL_X   1048576ull
#define EL_KV  2359296ull

constexpr size_t O_X    = 0;
constexpr size_t O_KV   = O_X    + EL_X;
constexpr size_t O_Q    = O_KV   + EL_KV;
constexpr size_t O_K    = O_Q    + EL_X;
constexpr size_t O_V    = O_K    + EL_KV;
constexpr size_t O_ATT  = O_V    + EL_KV;
constexpr size_t O_A    = O_ATT  + EL_X;
constexpr size_t O_TMP  = O_A    + EL_X;
constexpr size_t O_QR   = O_TMP  + EL_X;
constexpr size_t O_KR   = O_QR   + EL_X;
constexpr size_t O_VR   = O_KR   + EL_X;
constexpr size_t O_KN   = O_VR   + EL_X;
constexpr size_t O_VN   = O_KN   + 262144ull;
constexpr size_t O_TGT  = O_VN   + 262144ull;
constexpr size_t O_RNEW = O_TGT  + EL_X;
constexpr size_t O_NCM  = O_RNEW + EL_X;
constexpr size_t O_CWT  = O_NCM  + 262144ull;
constexpr size_t O_FF   = O_CWT  + EL_X;
constexpr size_t O_Y    = O_FF   + 4194304ull;
constexpr size_t O_X1   = O_Y    + EL_X;
constexpr size_t O_PART = O_X1   + EL_X;
constexpr size_t O_LOSS = O_PART + 1024ull;
constexpr size_t SCRATCH_TOTAL = O_LOSS + 16ull;

__device__ float g_scratch[SCRATCH_TOTAL];

__device__ __forceinline__ uint32_t f2tf32(float f) {
    uint32_t u;
    asm("cvt.rna.tf32.f32 %0, %1;" : "=r"(u) : "f"(f));
    return u;
}

__device__ __forceinline__ float block_sum(float v, float* sbuf, int nthreads) {
    int lane = threadIdx.x & 31, w = threadIdx.x >> 5;
    #pragma unroll
    for (int o = 16; o; o >>= 1) v += __shfl_xor_sync(0xffffffffu, v, o);
    __syncthreads();
    if (lane == 0) sbuf[w] = v;
    __syncthreads();
    int nw = nthreads >> 5;
    float r = 0.f;
    for (int i = 0; i < nw; i++) r += sbuf[i];
    return r;
}

__global__ void zero_loss_kernel(float* loss) { if (threadIdx.x == 0) loss[0] = 0.f; }

__global__ void embed_kernel(const int* __restrict__ trg, const float* __restrict__ emb,
                             float* __restrict__ x) {
    size_t idx = (size_t)blockIdx.x * blockDim.x + threadIdx.x;
    if (idx >= EL_X) return;
    int row = (int)(idx >> 9);
    int d   = (int)(idx & 511);
    x[idx] = emb[(size_t)trg[row] * 512 + d];
}

__global__ void kv_kernel(const float* __restrict__ cm, const float* __restrict__ mem,
                          const float* __restrict__ x, float* __restrict__ kv) {
    size_t idx = (size_t)blockIdx.x * blockDim.x + threadIdx.x;
    if (idx >= EL_KV) return;
    int b   = (int)(idx / ((size_t)KVN * DD));
    int rem = (int)(idx - (size_t)b * KVN * DD);
    int p = rem >> 9, d = rem & 511;
    float val;
    if (p < 128)       val = cm [(size_t)b * 128 * 512 + ((size_t)p << 9) + d];
    else if (p < 640)  val = mem[(size_t)b * 512 * 512 + ((size_t)(p - 128) << 9) + d];
    else               val = x  [(size_t)b * 512 * 512 + ((size_t)(p - 640) << 9) + d];
    kv[idx] = val;
}

__global__ void tconv_kernel(const float* __restrict__ cw, float* __restrict__ cwt) {
    size_t idx = (size_t)blockIdx.x * blockDim.x + threadIdx.x;
    if (idx >= 2048ull * 512ull) return;
    int o = (int)(idx & 511);
    int k = (int)(idx >> 9);
    int d = k & 511;
    int r = k >> 9;
    cwt[idx] = cw[((size_t)o * 512 + d) * 4 + r];
}

__global__ void out_kernel(float* __restrict__ o, const float* __restrict__ x,
                           const float* __restrict__ loss, size_t nout) {
    size_t i = (size_t)blockIdx.x * blockDim.x + threadIdx.x;
    if (i >= nout) return;
    if (i < EL_X) o[i] = x[i];
    else          o[i] = loss[0] * (1.f / (1048576.f * 4.f));
}

__global__ void __launch_bounds__(128) ln_kernel(const float* __restrict__ in,
                                                 const float* __restrict__ g,
                                                 const float* __restrict__ bb,
                                                 float* __restrict__ out) {
    __shared__ float sbuf[8];
    const int row = blockIdx.x, tid = threadIdx.x;
    const size_t base = (size_t)row * 512 + (size_t)tid * 4;
    float4 v4 = *(const float4*)(in + base);
    float v[4] = {v4.x, v4.y, v4.z, v4.w};
    float s = v[0] + v[1] + v[2] + v[3];
    s = block_sum(s, sbuf, 128);
    float mu = s * (1.f / 512.f);
    float d2 = 0.f;
    #pragma unroll
    for (int j = 0; j < 4; j++) { float t = v[j] - mu; d2 += t * t; }
    d2 = block_sum(d2, sbuf, 128);
    float rs = rsqrtf(d2 * (1.f / 512.f) + 1e-5f);
    int c = tid * 4;
    float4 o;
    o.x = (v[0] - mu) * rs * g[c + 0] + bb[c + 0];
    o.y = (v[1] - mu) * rs * g[c + 1] + bb[c + 1];
    o.z = (v[2] - mu) * rs * g[c + 2] + bb[c + 2];
    o.w = (v[3] - mu) * rs * g[c + 3] + bb[c + 3];
    *(float4*)(out + base) = o;
}

__global__ void __launch_bounds__(256) loss_part_kernel(const float* __restrict__ a,
                                                        const float* __restrict__ b,
                                                        float* __restrict__ part) {
    __shared__ float sbuf[8];
    size_t base = (size_t)blockIdx.x * 1024 + (size_t)threadIdx.x * 4;
    float4 x = *(const float4*)(a + base);
    float4 y = *(const float4*)(b + base);
    float dx = x.x - y.x, dy = x.y - y.y, dz = x.z - y.z, dw = x.w - y.w;
    float s = dx * dx + dy * dy + dz * dz + dw * dw;
    s = block_sum(s, sbuf, 256);
    if (threadIdx.x == 0) part[blockIdx.x] = s;
}

__global__ void __launch_bounds__(256) loss_acc_kernel(const float* __restrict__ part,
                                                       float* __restrict__ loss) {
    __shared__ float sbuf[8];
    int tid = threadIdx.x;
    float s = part[tid] + part[tid + 256] + part[tid + 512] + part[tid + 768];
    s = block_sum(s, sbuf, 256);
    if (tid == 0) loss[0] += s;
}

// ---------------- TF32 tensor-core GEMM ----------------
// C[M,N] = A[M,K] @ B[K,N] (+bias)(+gelu)(+resid)
// Block tile TM x TN, 256 threads = 8 warps (2 m x 4 n), k-chunk 16.
template<int TM, int TN>
__global__ void __launch_bounds__(256) gemm_tc_kernel(const float* __restrict__ A,
                                                      const float* __restrict__ B,
                                                      float* __restrict__ C,
                                                      int M, int N, int K,
                                                      const float* __restrict__ bias,
                                                      const float* __restrict__ resid,
                                                      int act) {
    constexpr int MT = TM / 32;   // m16 tiles per warp (warp covers TM/2 rows)
    constexpr int NT = TN / 32;   // n8 tiles per warp (warp covers TN/4 cols)
    constexpr int AV = TM / 64;   // float4 loads per thread for A chunk
    constexpr int BV = TN / 64;
    __shared__ uint32_t As[TM][20];
    __shared__ uint32_t Bs[TN][20];
    const int tid = threadIdx.x;
    const int wid = tid >> 5, lane = tid & 31;
    const int wm = wid >> 2, wn = wid & 3;
    const int g = lane >> 2, tg = lane & 3;
    const int m0 = blockIdx.y * TM, n0 = blockIdx.x * TN;

    float acc[MT][NT][4];
    #pragma unroll
    for (int i = 0; i < MT; i++)
        #pragma unroll
        for (int j = 0; j < NT; j++)
            #pragma unroll
            for (int c = 0; c < 4; c++) acc[i][j][c] = 0.f;

    float4 pa[AV], pb[BV];
    // prefetch chunk 0
    #pragma unroll
    for (int v = 0; v < AV; v++) {
        int idx4 = tid + v * 256;
        int row = idx4 >> 2, kg = (idx4 & 3) << 2;
        pa[v] = *(const float4*)(A + (size_t)(m0 + row) * K + kg);
    }
    #pragma unroll
    for (int v = 0; v < BV; v++) {
        int idx4 = tid + v * 256;
        int k = idx4 / (TN / 4), c = (idx4 % (TN / 4)) << 2;
        pb[v] = *(const float4*)(B + (size_t)k * N + n0 + c);
    }

    for (int k0 = 0;; k0 += 16) {
        __syncthreads();
        #pragma unroll
        for (int v = 0; v < AV; v++) {
            int idx4 = tid + v * 256;
            int row = idx4 >> 2, kg = (idx4 & 3) << 2;
            As[row][kg + 0] = f2tf32(pa[v].x);
            As[row][kg + 1] = f2tf32(pa[v].y);
            As[row][kg + 2] = f2tf32(pa[v].z);
            As[row][kg + 3] = f2tf32(pa[v].w);
        }
        #pragma unroll
        for (int v = 0; v < BV; v++) {
            int idx4 = tid + v * 256;
            int k = idx4 / (TN / 4), c = (idx4 % (TN / 4)) << 2;
            Bs[c + 0][k] = f2tf32(pb[v].x);
            Bs[c + 1][k] = f2tf32(pb[v].y);
            Bs[c + 2][k] = f2tf32(pb[v].z);
            Bs[c + 3][k] = f2tf32(pb[v].w);
        }
        __syncthreads();
        bool more = (k0 + 16 < K);
        if (more) {
            int kn = k0 + 16;
            #pragma unroll
            for (int v = 0; v < AV; v++) {
                int idx4 = tid + v * 256;
                int row = idx4 >> 2, kg = (idx4 & 3) << 2;
                pa[v] = *(const float4*)(A + (size_t)(m0 + row) * K + kn + kg);
            }
            #pragma unroll
            for (int v = 0; v < BV; v++) {
                int idx4 = tid + v * 256;
                int k = idx4 / (TN / 4), c = (idx4 % (TN / 4)) << 2;
                pb[v] = *(const float4*)(B + (size_t)(kn + k) * N + n0 + c);
            }
        }
        #pragma unroll
        for (int kk = 0; kk < 16; kk += 8) {
            uint32_t af[MT][4], bf[NT][2];
            #pragma unroll
            for (int i = 0; i < MT; i++) {
                int r = wm * (TM / 2) + i * 16 + g;
                af[i][0] = As[r][kk + tg];
                af[i][1] = As[r + 8][kk + tg];
                af[i][2] = As[r][kk + tg + 4];
                af[i][3] = As[r + 8][kk + tg + 4];
            }
            #pragma unroll
            for (int j = 0; j < NT; j++) {
                int n = wn * (TN / 4) + j * 8 + g;
                bf[j][0] = Bs[n][kk + tg];
                bf[j][1] = Bs[n][kk + tg + 4];
            }
            #pragma unroll
            for (int i = 0; i < MT; i++)
                #pragma unroll
                for (int j = 0; j < NT; j++) {
                    asm volatile(
                        "mma.sync.aligned.m16n8k8.row.col.f32.tf32.tf32.f32 "
                        "{%0,%1,%2,%3}, {%4,%5,%6,%7}, {%8,%9}, {%0,%1,%2,%3};\n"
                        : "+f"(acc[i][j][0]), "+f"(acc[i][j][1]),
                          "+f"(acc[i][j][2]), "+f"(acc[i][j][3])
                        : "r"(af[i][0]), "r"(af[i][1]), "r"(af[i][2]), "r"(af[i][3]),
                          "r"(bf[j][0]), "r"(bf[j][1]));
                }
        }
        if (!more) break;
    }

    #pragma unroll
    for (int i = 0; i < MT; i++) {
        int m = m0 + wm * (TM / 2) + i * 16 + g;
        #pragma unroll
        for (int j = 0; j < NT; j++) {
            int n = n0 + wn * (TN / 4) + j * 8 + 2 * tg;
            float c0 = acc[i][j][0], c1 = acc[i][j][1];
            float c2 = acc[i][j][2], c3 = acc[i][j][3];
            if (bias) {
                float b0 = bias[n], b1 = bias[n + 1];
                c0 += b0; c1 += b1; c2 += b0; c3 += b1;
            }
            if (act) {
                c0 = 0.5f * c0 * (1.f + erff(c0 * 0.7071067811865475f));
                c1 = 0.5f * c1 * (1.f + erff(c1 * 0.7071067811865475f));
                c2 = 0.5f * c2 * (1.f + erff(c2 * 0.7071067811865475f));
                c3 = 0.5f * c3 * (1.f + erff(c3 * 0.7071067811865475f));
            }
            if (resid) {
                c0 += resid[(size_t)m * N + n];
                c1 += resid[(size_t)m * N + n + 1];
                c2 += resid[(size_t)(m + 8) * N + n];
                c3 += resid[(size_t)(m + 8) * N + n + 1];
            }
            float2 lo = {c0, c1}, hi = {c2, c3};
            *(float2*)(C + (size_t)m * N + n) = lo;
            *(float2*)(C + (size_t)(m + 8) * N + n) = hi;
        }
    }
}

// ---------------- fused attention ----------------
// 8 queries per block; thread = (qsel 0..3) x (ksel 0..63); 2 queries in registers.
template <bool POS>
__global__ void __launch_bounds__(256) attn_kernel(const float* __restrict__ q,
                                                   const float* __restrict__ k,
                                                   const float* __restrict__ v,
                                                   float* __restrict__ out,
                                                   const float* __restrict__ pos,
                                                   int qlen, int klen,
                                                   float sc_qk, float sc_pos) {
    extern __shared__ float smf[];
    float* ss = smf;                 // 8*klen
    float* qs = ss + 8 * klen;       // 512
    float* ks = qs + 512;            // 64*65
    float* ps = ks + 64 * 65;        // 71*65 (POS only)
    const int tid = threadIdx.x;
    const int b = blockIdx.z, h = blockIdx.y, q0 = blockIdx.x << 3;

    for (int i = tid; i < 8 * 64; i += 256) {
        int qi = i >> 6, d = i & 63;
        qs[i] = q[(size_t)(b * qlen + q0 + qi) * 512 + h * 64 + d];
    }
    __syncthreads();
    const int qsel = tid >> 6, ksel = tid & 63;
    float q1[64], q2[64];
    #pragma unroll
    for (int d = 0; d < 64; d++) {
        q1[d] = qs[qsel * 64 + d];
        q2[d] = qs[(qsel + 4) * 64 + d];
    }

    // ---- scores (64-key chunks) ----
    for (int kc = 0; kc < klen; kc += 64) {
        __syncthreads();
        for (int i = tid; i < 64 * 16; i += 256) {
            int r = i >> 4, d4 = (i & 15) << 2;
            float4 kv4 = *(const float4*)(k + (size_t)(b * klen + kc + r) * 512 + h * 64 + d4);
            ks[r * 65 + d4 + 0] = kv4.x;
            ks[r * 65 + d4 + 1] = kv4.y;
            ks[r * 65 + d4 + 2] = kv4.z;
            ks[r * 65 + d4 + 3] = kv4.w;
        }
        if (POS) {
            int rel0 = kc + qlen - 8 - q0;
            for (int i = tid; i < 71 * 16; i += 256) {
                int r = i >> 4, d4 = (i & 15) << 2;
                int rel = rel0 + r;
                if (rel < klen) {
                    float4 p4 = *(const float4*)(pos + (size_t)(h * klen + rel) * 64 + d4);
                    ps[r * 65 + d4 + 0] = p4.x;
                    ps[r * 65 + d4 + 1] = p4.y;
                    ps[r * 65 + d4 + 2] = p4.z;
                    ps[r * 65 + d4 + 3] = p4.w;
                } else {
                    ps[r * 65 + d4 + 0] = 0.f;
                    ps[r * 65 + d4 + 1] = 0.f;
                    ps[r * 65 + d4 + 2] = 0.f;
                    ps[r * 65 + d4 + 3] = 0.f;
                }
            }
        }
        __syncthreads();
        float a1 = 0.f, a2 = 0.f, p1 = 0.f, p2 = 0.f;
        const float* kr = ks + ksel * 65;
        const float* pr1 = POS ? (ps + (ksel + 7 - qsel) * 65) : ks;
        const float* pr2 = POS ? (ps + (ksel + 3 - qsel) * 65) : ks;
        #pragma unroll
        for (int d = 0; d < 64; d++) {
            float kv = kr[d];
            a1 += q1[d] * kv;
            a2 += q2[d] * kv;
            if (POS) { p1 += q1[d] * pr1[d]; p2 += q2[d] * pr2[d]; }
        }
        ss[qsel * klen + kc + ksel]       = POS ? (a1 * sc_qk + p1 * sc_pos) : (a1 * sc_qk);
        ss[(qsel + 4) * klen + kc + ksel] = POS ? (a2 * sc_qk + p2 * sc_pos) : (a2 * sc_qk);
    }
    __syncthreads();

    // ---- softmax (one warp per query row) ----
    {
        int w = tid >> 5, lane = tid & 31;
        float* row = ss + w * klen;
        float mx = -1e30f;
        for (int j = lane; j < klen; j += 32) mx = fmaxf(mx, row[j]);
        #pragma unroll
        for (int o = 16; o; o >>= 1) mx = fmaxf(mx, __shfl_xor_sync(0xffffffffu, mx, o));
        float sum = 0.f;
        for (int j = lane; j < klen; j += 32) { float e = expf(row[j] - mx); row[j] = e; sum += e; }
        #pragma unroll
        for (int o = 16; o; o >>= 1) sum += __shfl_xor_sync(0xffffffffu, sum, o);
        float inv = 1.f / sum;
        for (int j = lane; j < klen; j += 32) row[j] *= inv;
    }

    // ---- AV ----
    const int d = tid & 63, g = tid >> 6;
    float o0 = 0.f, o1 = 0.f;
    for (int kc = 0; kc < klen; kc += 64) {
        __syncthreads();
        for (int i = tid; i < 64 * 16; i += 256) {
            int r = i >> 4, d4 = (i & 15) << 2;
            float4 v4 = *(const float4*)(v + (size_t)(b * klen + kc + r) * 512 + h * 64 + d4);
            ks[r * 65 + d4 + 0] = v4.x;
            ks[r * 65 + d4 + 1] = v4.y;
            ks[r * 65 + d4 + 2] = v4.z;
            ks[r * 65 + d4 + 3] = v4.w;
        }
        __syncthreads();
        const float* s1 = ss + (size_t)g * klen + kc;
        const float* s2 = ss + (size_t)(g + 4) * klen + kc;
        #pragma unroll
        for (int m4 = 0; m4 < 16; m4++) {
            float4 w1 = *(const float4*)(s1 + 4 * m4);
            float4 w2 = *(const float4*)(s2 + 4 * m4);
            float v0 = ks[(4 * m4 + 0) * 65 + d];
            float v1 = ks[(4 * m4 + 1) * 65 + d];
            float v2 = ks[(4 * m4 + 2) * 65 + d];
            float v3 = ks[(4 * m4 + 3) * 65 + d];
            o0 += w1.x * v0 + w1.y * v1 + w1.z * v2 + w1.w * v3;
            o1 += w2.x * v0 + w2.y * v1 + w2.z * v2 + w2.w * v3;
        }
    }
    out[(size_t)(b * qlen + q0 + g) * 512 + h * 64 + d] = o0;
    out[(size_t)(b * qlen + q0 + g + 4) * 512 + h * 64 + d] = o1;
}

static void gemm(const float* A, const float* B, float* C, int M, int N, int K,
                 const float* bias = nullptr, const float* resid = nullptr, int act = 0) {
    if ((M % 128 == 0) && (N % 128 == 0) && ((M >> 7) * (N >> 7) >= 128)) {
        dim3 grid(N / 128, M / 128);
        gemm_tc_kernel<128, 128><<<grid, 256>>>(A, B, C, M, N, K, bias, resid, act);
    } else {
        dim3 grid(N / 64, M / 64);
        gemm_tc_kernel<64, 64><<<grid, 256>>>(A, B, C, M, N, K, bias, resid, act);
    }
}

static void attn(const float* q, const float* k, const float* v, float* o,
                 const float* pos, int qlen, int klen, bool use_pos) {
    dim3 grid(qlen / 8, HH, BB);
    if (use_pos) {
        size_t smem = (size_t)(8 * klen + 512 + 64 * 65 + 71 * 65) * 4;
        attn_kernel<true><<<grid, 256, smem>>>(q, k, v, o, pos, qlen, klen, 0.125f, 8.f);
    } else {
        size_t smem = (size_t)(8 * klen + 512 + 64 * 65) * 4;
        attn_kernel<false><<<grid, 256, smem>>>(q, k, v, o, nullptr, qlen, klen, 0.125f, 0.f);
    }
}

extern "C" void kernel_launch(void* const* d_in, const int* in_sizes, int n_in,
                              void* d_out, int out_size) {
    const int*   trg     = (const int*)  d_in[0];
    const float* latent  = (const float*)d_in[3];
    const float* mems    = (const float*)d_in[4];
    const float* cmems   = (const float*)d_in[5];
    const float* pos_emb = (const float*)d_in[6];
    const float* embed   = (const float*)d_in[7];
    const float* W_self  = (const float*)d_in[8];
    const float* ln1_g   = (const float*)d_in[9];
    const float* ln1_b   = (const float*)d_in[10];
    const float* conv_w  = (const float*)d_in[11];
    const float* conv_b  = (const float*)d_in[12];
    const float* W_src   = (const float*)d_in[13];
    const float* ln2_g   = (const float*)d_in[14];
    const float* ln2_b   = (const float*)d_in[15];
    const float* w1      = (const float*)d_in[16];
    const float* b1      = (const float*)d_in[17];
    const float* w2      = (const float*)d_in[18];
    const float* b2      = (const float*)d_in[19];

    float* S;
    cudaGetSymbolAddress((void**)&S, g_scratch);
    float* X    = S + O_X;
    float* KVb  = S + O_KV;
    float* Q    = S + O_Q;
    float* K    = S + O_K;
    float* V    = S + O_V;
    float* ATT  = S + O_ATT;
    float* A    = S + O_A;
    float* TMP  = S + O_TMP;
    float* QR   = S + O_QR;
    float* KR   = S + O_KR;
    float* VR   = S + O_VR;
    float* KN   = S + O_KN;
    float* VN   = S + O_VN;
    float* TGT  = S + O_TGT;
    float* RNEW = S + O_RNEW;
    float* NCM  = S + O_NCM;
    float* CWT  = S + O_CWT;
    float* FF   = S + O_FF;
    float* Y    = S + O_Y;
    float* X1   = S + O_X1;
    float* PART = S + O_PART;
    float* LOSS = S + O_LOSS;

    cudaFuncSetAttribute(attn_kernel<true>,  cudaFuncAttributeMaxDynamicSharedMemorySize, 100000);
    cudaFuncSetAttribute(attn_kernel<false>, cudaFuncAttributeMaxDynamicSharedMemorySize, 65536);

    zero_loss_kernel<<<1, 32>>>(LOSS);
    embed_kernel<<<(int)(EL_X / 256), 256>>>(trg, embed, X);

    for (int i = 0; i < NL; i++) {
        const float* mem = mems  + (size_t)i * BB * 512 * 512;
        const float* cm  = cmems + (size_t)i * BB * 128 * 512;
        const float* W0 = W_self + ((size_t)i * 4 + 0) * 512 * 512;
        const float* W1 = W_self + ((size_t)i * 4 + 1) * 512 * 512;
        const float* W2 = W_self + ((size_t)i * 4 + 2) * 512 * 512;
        const float* W3 = W_self + ((size_t)i * 4 + 3) * 512 * 512;
        const float* Ws0 = W_src + ((size_t)i * 4 + 0) * 512 * 512;
        const float* Ws1 = W_src + ((size_t)i * 4 + 1) * 512 * 512;
        const float* Ws2 = W_src + ((size_t)i * 4 + 2) * 512 * 512;
        const float* Ws3 = W_src + ((size_t)i * 4 + 3) * 512 * 512;

        // self-attention over kv = [cmem, mem, x]
        kv_kernel<<<(int)(EL_KV / 256), 256>>>(cm, mem, X, KVb);
        gemm(X,   W0, Q, 2048, 512, 512);
        gemm(KVb, W1, K, 4608, 512, 512);
        gemm(KVb, W2, V, 4608, 512, 512);
        attn(Q, K, V, ATT, pos_emb, 512, KVN, true);
        gemm(ATT, W3, TMP, 2048, 512, 512, nullptr, X, 0);
        ln_kernel<<<2048, 128>>>(TMP, ln1_g + i * 512, ln1_b + i * 512, A);

        // compressed-memory reconstruction loss
        tconv_kernel<<<4096, 256>>>(conv_w + (size_t)i * 512 * 512 * 4, CWT);
        gemm(mem, CWT, NCM, 512, 512, 2048, conv_b + i * 512);
        gemm(A,   W0, QR, 2048, 512, 512);
        gemm(mem, W1, KR, 2048, 512, 512);
        gemm(mem, W2, VR, 2048, 512, 512);
        attn(QR, KR, VR, TGT, nullptr, 512, 512, false);
        gemm(NCM, W1, KN, 512, 512, 512);
        gemm(NCM, W2, VN, 512, 512, 512);
        attn(QR, KN, VN, RNEW, nullptr, 512, 128, false);
        loss_part_kernel<<<1024, 256>>>(RNEW, TGT, PART);
        loss_acc_kernel<<<1, 256>>>(PART, LOSS);

        // cross-attention to latent (no residual on output)
        gemm(A,      Ws0, QR, 2048, 512, 512);
        gemm(latent, Ws1, KR, 1024, 512, 512);
        gemm(latent, Ws2, VR, 1024, 512, 512);
        attn(QR, KR, VR, TMP, nullptr, 512, 256, false);
        gemm(TMP, Ws3, X1, 2048, 512, 512);

        // FFN: x = x1 + gelu(LN(x1)@w1+b1)@w2 + b2
        ln_kernel<<<2048, 128>>>(X1, ln2_g + i * 512, ln2_b + i * 512, Y);
        gemm(Y,  w1 + (size_t)i * 512 * 2048, FF, 2048, 2048, 512,  b1 + (size_t)i * 2048, nullptr, 1);
        gemm(FF, w2 + (size_t)i * 2048 * 512, X,  2048, 512,  2048, b2 + (size_t)i * 512,  X1,      0);
    }

    size_t nout = (size_t)out_size;
    out_kernel<<<(int)((nout + 255) / 256), 256>>>((float*)d_out, X, LOSS, nout);
}

// round 4
// speedup vs baseline: 1.9937x; 1.9103x over previous
#include <cuda_runtime.h>
#include <math.h>
#include <stdint.h>

#define NL 4
#define BB 4
#define DD 512
#define HH 8
#define KVN 1152

#define EL_X   1048576ull
#define EL_KV  2359296ull
#define EL_S   18874368ull   // 32 * 512 * 1152

constexpr size_t O_X    = 0;
constexpr size_t O_KV   = O_X    + EL_X;
constexpr size_t O_Q    = O_KV   + EL_KV;
constexpr size_t O_K    = O_Q    + EL_X;
constexpr size_t O_V    = O_K    + EL_KV;
constexpr size_t O_ATT  = O_V    + EL_KV;
constexpr size_t O_A    = O_ATT  + EL_X;
constexpr size_t O_TMP  = O_A    + EL_X;
constexpr size_t O_QR   = O_TMP  + EL_X;
constexpr size_t O_KR   = O_QR   + EL_X;
constexpr size_t O_VR   = O_KR   + EL_X;
constexpr size_t O_KN   = O_VR   + EL_X;
constexpr size_t O_VN   = O_KN   + 262144ull;
constexpr size_t O_TGT  = O_VN   + 262144ull;
constexpr size_t O_RNEW = O_TGT  + EL_X;
constexpr size_t O_NCM  = O_RNEW + EL_X;
constexpr size_t O_CWT  = O_NCM  + 262144ull;
constexpr size_t O_FF   = O_CWT  + EL_X;
constexpr size_t O_Y    = O_FF   + 4194304ull;
constexpr size_t O_X1   = O_Y    + EL_X;
constexpr size_t O_PART = O_X1   + EL_X;
constexpr size_t O_LOSS = O_PART + 1024ull;
constexpr size_t O_S    = O_LOSS + 16ull;
constexpr size_t O_P    = O_S    + EL_S;
constexpr size_t SCRATCH_TOTAL = O_P + EL_S;

__device__ float g_scratch[SCRATCH_TOTAL];

__device__ __forceinline__ uint32_t f2tf32(float f) {
    uint32_t u;
    asm("cvt.rna.tf32.f32 %0, %1;" : "=r"(u) : "f"(f));
    return u;
}

__device__ __forceinline__ float block_red_sum(float v, float* sbuf, int nthreads) {
    int lane = threadIdx.x & 31, w = threadIdx.x >> 5;
    #pragma unroll
    for (int o = 16; o; o >>= 1) v += __shfl_xor_sync(0xffffffffu, v, o);
    __syncthreads();
    if (lane == 0) sbuf[w] = v;
    __syncthreads();
    int nw = nthreads >> 5;
    float r = 0.f;
    for (int i = 0; i < nw; i++) r += sbuf[i];
    return r;
}

__device__ __forceinline__ float block_red_max(float v, float* sbuf, int nthreads) {
    int lane = threadIdx.x & 31, w = threadIdx.x >> 5;
    #pragma unroll
    for (int o = 16; o; o >>= 1) v = fmaxf(v, __shfl_xor_sync(0xffffffffu, v, o));
    __syncthreads();
    if (lane == 0) sbuf[w] = v;
    __syncthreads();
    int nw = nthreads >> 5;
    float r = -1e30f;
    for (int i = 0; i < nw; i++) r = fmaxf(r, sbuf[i]);
    return r;
}

__global__ void zero_loss_kernel(float* loss) { if (threadIdx.x == 0) loss[0] = 0.f; }

__global__ void embed_kernel(const int* __restrict__ trg, const float* __restrict__ emb,
                             float* __restrict__ x) {
    size_t idx = (size_t)blockIdx.x * blockDim.x + threadIdx.x;
    if (idx >= EL_X) return;
    int row = (int)(idx >> 9);
    int d   = (int)(idx & 511);
    x[idx] = emb[(size_t)trg[row] * 512 + d];
}

__global__ void kv_kernel(const float* __restrict__ cm, const float* __restrict__ mem,
                          const float* __restrict__ x, float* __restrict__ kv) {
    size_t idx = (size_t)blockIdx.x * blockDim.x + threadIdx.x;
    if (idx >= EL_KV) return;
    int b   = (int)(idx / ((size_t)KVN * DD));
    int rem = (int)(idx - (size_t)b * KVN * DD);
    int p = rem >> 9, d = rem & 511;
    float val;
    if (p < 128)       val = cm [(size_t)b * 128 * 512 + ((size_t)p << 9) + d];
    else if (p < 640)  val = mem[(size_t)b * 512 * 512 + ((size_t)(p - 128) << 9) + d];
    else               val = x  [(size_t)b * 512 * 512 + ((size_t)(p - 640) << 9) + d];
    kv[idx] = val;
}

__global__ void tconv_kernel(const float* __restrict__ cw, float* __restrict__ cwt) {
    size_t idx = (size_t)blockIdx.x * blockDim.x + threadIdx.x;
    if (idx >= 2048ull * 512ull) return;
    int o = (int)(idx & 511);
    int k = (int)(idx >> 9);
    int d = k & 511;
    int r = k >> 9;
    cwt[idx] = cw[((size_t)o * 512 + d) * 4 + r];
}

__global__ void out_kernel(float* __restrict__ o, const float* __restrict__ x,
                           const float* __restrict__ loss, size_t nout) {
    size_t i = (size_t)blockIdx.x * blockDim.x + threadIdx.x;
    if (i >= nout) return;
    if (i < EL_X) o[i] = x[i];
    else          o[i] = loss[0] * (1.f / (1048576.f * 4.f));
}

__global__ void __launch_bounds__(128) ln_kernel(const float* __restrict__ in,
                                                 const float* __restrict__ g,
                                                 const float* __restrict__ bb,
                                                 float* __restrict__ out) {
    __shared__ float sbuf[8];
    const int row = blockIdx.x, tid = threadIdx.x;
    const size_t base = (size_t)row * 512 + (size_t)tid * 4;
    float4 v4 = *(const float4*)(in + base);
    float v[4] = {v4.x, v4.y, v4.z, v4.w};
    float s = v[0] + v[1] + v[2] + v[3];
    s = block_red_sum(s, sbuf, 128);
    float mu = s * (1.f / 512.f);
    float d2 = 0.f;
    #pragma unroll
    for (int j = 0; j < 4; j++) { float t = v[j] - mu; d2 += t * t; }
    d2 = block_red_sum(d2, sbuf, 128);
    float rs = rsqrtf(d2 * (1.f / 512.f) + 1e-5f);
    int c = tid * 4;
    float4 o;
    o.x = (v[0] - mu) * rs * g[c + 0] + bb[c + 0];
    o.y = (v[1] - mu) * rs * g[c + 1] + bb[c + 1];
    o.z = (v[2] - mu) * rs * g[c + 2] + bb[c + 2];
    o.w = (v[3] - mu) * rs * g[c + 3] + bb[c + 3];
    *(float4*)(out + base) = o;
}

__global__ void __launch_bounds__(256) loss_part_kernel(const float* __restrict__ a,
                                                        const float* __restrict__ b,
                                                        float* __restrict__ part) {
    __shared__ float sbuf[8];
    size_t base = (size_t)blockIdx.x * 1024 + (size_t)threadIdx.x * 4;
    float4 x = *(const float4*)(a + base);
    float4 y = *(const float4*)(b + base);
    float dx = x.x - y.x, dy = x.y - y.y, dz = x.z - y.z, dw = x.w - y.w;
    float s = dx * dx + dy * dy + dz * dz + dw * dw;
    s = block_red_sum(s, sbuf, 256);
    if (threadIdx.x == 0) part[blockIdx.x] = s;
}

__global__ void __launch_bounds__(256) loss_acc_kernel(const float* __restrict__ part,
                                                       float* __restrict__ loss) {
    __shared__ float sbuf[8];
    int tid = threadIdx.x;
    float s = part[tid] + part[tid + 256] + part[tid + 512] + part[tid + 768];
    s = block_red_sum(s, sbuf, 256);
    if (tid == 0) loss[0] += s;
}

// ---------------- generalized batched TF32 tensor-core GEMM ----------------
// C = alpha * A @ B (+bias)(+gelu)(+resid)
// A row-major [M,K] (row stride lda); B: BNM ? B[n][k] (row stride ldb)
//                                          : B[k][n] (row stride ldb)
// batch z: offset(tensor) = (z/mod)*Outer + (z%mod)*Inner
// X3: 3xTF32 split (hi/lo) for ~fp32 accuracy.
template<int TM, int TN, bool BNM, bool X3>
__global__ void __launch_bounds__(256) gmma_kernel(
    const float* __restrict__ A, const float* __restrict__ B, float* __restrict__ C,
    int M, int N, int K, int lda, int ldb, int ldc,
    size_t aO, size_t aI, size_t bO, size_t bI, size_t cO, size_t cI, int mod,
    float alpha, const float* __restrict__ bias,
    const float* __restrict__ resid, int act)
{
    constexpr int MT = TM / 32;
    constexpr int NT = TN / 32;
    constexpr int AVN = TM / 64;
    constexpr int BVN = TN / 64;
    __shared__ uint32_t AsH[TM][20];
    __shared__ uint32_t BsH[TN][20];
    __shared__ uint32_t AsL[X3 ? TM : 1][X3 ? 20 : 4];
    __shared__ uint32_t BsL[X3 ? TN : 1][X3 ? 20 : 4];

    const int z = blockIdx.z;
    const size_t aOff = (size_t)(z / mod) * aO + (size_t)(z % mod) * aI;
    const size_t bOff = (size_t)(z / mod) * bO + (size_t)(z % mod) * bI;
    const size_t cOff = (size_t)(z / mod) * cO + (size_t)(z % mod) * cI;
    const float* Ab = A + aOff;
    const float* Bb = B + bOff;
    float* Cb = C + cOff;

    const int tid = threadIdx.x;
    const int wid = tid >> 5, lane = tid & 31;
    const int wm = wid >> 2, wn = wid & 3;
    const int g = lane >> 2, tg = lane & 3;
    const int m0 = blockIdx.y * TM, n0 = blockIdx.x * TN;

    float acc[MT][NT][4];
    #pragma unroll
    for (int i = 0; i < MT; i++)
        #pragma unroll
        for (int j = 0; j < NT; j++)
            #pragma unroll
            for (int c = 0; c < 4; c++) acc[i][j][c] = 0.f;

    float4 pa[AVN], pb[BVN];
    #pragma unroll
    for (int v = 0; v < AVN; v++) {
        int idx4 = tid + v * 256;
        int row = idx4 >> 2, kg = (idx4 & 3) << 2;
        pa[v] = *(const float4*)(Ab + (size_t)(m0 + row) * lda + kg);
    }
    #pragma unroll
    for (int v = 0; v < BVN; v++) {
        int idx4 = tid + v * 256;
        if (BNM) {
            int row = idx4 >> 2, kg = (idx4 & 3) << 2;
            pb[v] = *(const float4*)(Bb + (size_t)(n0 + row) * ldb + kg);
        } else {
            int k = idx4 / (TN / 4), c = (idx4 % (TN / 4)) << 2;
            pb[v] = *(const float4*)(Bb + (size_t)k * ldb + n0 + c);
        }
    }

    for (int k0 = 0;; k0 += 16) {
        __syncthreads();
        #pragma unroll
        for (int v = 0; v < AVN; v++) {
            int idx4 = tid + v * 256;
            int row = idx4 >> 2, kg = (idx4 & 3) << 2;
            float f[4] = {pa[v].x, pa[v].y, pa[v].z, pa[v].w};
            #pragma unroll
            for (int j = 0; j < 4; j++) {
                uint32_t hi = f2tf32(f[j]);
                AsH[row][kg + j] = hi;
                if (X3) AsL[row][kg + j] = f2tf32(f[j] - __uint_as_float(hi));
            }
        }
        #pragma unroll
        for (int v = 0; v < BVN; v++) {
            int idx4 = tid + v * 256;
            float f[4] = {pb[v].x, pb[v].y, pb[v].z, pb[v].w};
            if (BNM) {
                int row = idx4 >> 2, kg = (idx4 & 3) << 2;
                #pragma unroll
                for (int j = 0; j < 4; j++) {
                    uint32_t hi = f2tf32(f[j]);
                    BsH[row][kg + j] = hi;
                    if (X3) BsL[row][kg + j] = f2tf32(f[j] - __uint_as_float(hi));
                }
            } else {
                int k = idx4 / (TN / 4), c = (idx4 % (TN / 4)) << 2;
                #pragma unroll
                for (int j = 0; j < 4; j++) {
                    uint32_t hi = f2tf32(f[j]);
                    BsH[c + j][k] = hi;
                    if (X3) BsL[c + j][k] = f2tf32(f[j] - __uint_as_float(hi));
                }
            }
        }
        __syncthreads();
        bool more = (k0 + 16 < K);
        if (more) {
            int kn = k0 + 16;
            #pragma unroll
            for (int v = 0; v < AVN; v++) {
                int idx4 = tid + v * 256;
                int row = idx4 >> 2, kg = (idx4 & 3) << 2;
                pa[v] = *(const float4*)(Ab + (size_t)(m0 + row) * lda + kn + kg);
            }
            #pragma unroll
            for (int v = 0; v < BVN; v++) {
                int idx4 = tid + v * 256;
                if (BNM) {
                    int row = idx4 >> 2, kg = (idx4 & 3) << 2;
                    pb[v] = *(const float4*)(Bb + (size_t)(n0 + row) * ldb + kn + kg);
                } else {
                    int k = idx4 / (TN / 4), c = (idx4 % (TN / 4)) << 2;
                    pb[v] = *(const float4*)(Bb + (size_t)(kn + k) * ldb + n0 + c);
                }
            }
        }
        #pragma unroll
        for (int kk = 0; kk < 16; kk += 8) {
            uint32_t afH[MT][4], bfH[NT][2];
            uint32_t afL[X3 ? MT : 1][4], bfL[X3 ? NT : 1][2];
            #pragma unroll
            for (int i = 0; i < MT; i++) {
                int r = wm * (TM / 2) + i * 16 + g;
                afH[i][0] = AsH[r][kk + tg];
                afH[i][1] = AsH[r + 8][kk + tg];
                afH[i][2] = AsH[r][kk + tg + 4];
                afH[i][3] = AsH[r + 8][kk + tg + 4];
                if (X3) {
                    afL[i][0] = AsL[r][kk + tg];
                    afL[i][1] = AsL[r + 8][kk + tg];
                    afL[i][2] = AsL[r][kk + tg + 4];
                    afL[i][3] = AsL[r + 8][kk + tg + 4];
                }
            }
            #pragma unroll
            for (int j = 0; j < NT; j++) {
                int n = wn * (TN / 4) + j * 8 + g;
                bfH[j][0] = BsH[n][kk + tg];
                bfH[j][1] = BsH[n][kk + tg + 4];
                if (X3) {
                    bfL[j][0] = BsL[n][kk + tg];
                    bfL[j][1] = BsL[n][kk + tg + 4];
                }
            }
            #pragma unroll
            for (int i = 0; i < MT; i++)
                #pragma unroll
                for (int j = 0; j < NT; j++) {
                    asm volatile(
                        "mma.sync.aligned.m16n8k8.row.col.f32.tf32.tf32.f32 "
                        "{%0,%1,%2,%3}, {%4,%5,%6,%7}, {%8,%9}, {%0,%1,%2,%3};\n"
                        : "+f"(acc[i][j][0]), "+f"(acc[i][j][1]),
                          "+f"(acc[i][j][2]), "+f"(acc[i][j][3])
                        : "r"(afH[i][0]), "r"(afH[i][1]), "r"(afH[i][2]), "r"(afH[i][3]),
                          "r"(bfH[j][0]), "r"(bfH[j][1]));
                    if (X3) {
                        asm volatile(
                            "mma.sync.aligned.m16n8k8.row.col.f32.tf32.tf32.f32 "
                            "{%0,%1,%2,%3}, {%4,%5,%6,%7}, {%8,%9}, {%0,%1,%2,%3};\n"
                            : "+f"(acc[i][j][0]), "+f"(acc[i][j][1]),
                              "+f"(acc[i][j][2]), "+f"(acc[i][j][3])
                            : "r"(afL[i][0]), "r"(afL[i][1]), "r"(afL[i][2]), "r"(afL[i][3]),
                              "r"(bfH[j][0]), "r"(bfH[j][1]));
                        asm volatile(
                            "mma.sync.aligned.m16n8k8.row.col.f32.tf32.tf32.f32 "
                            "{%0,%1,%2,%3}, {%4,%5,%6,%7}, {%8,%9}, {%0,%1,%2,%3};\n"
                            : "+f"(acc[i][j][0]), "+f"(acc[i][j][1]),
                              "+f"(acc[i][j][2]), "+f"(acc[i][j][3])
                            : "r"(afH[i][0]), "r"(afH[i][1]), "r"(afH[i][2]), "r"(afH[i][3]),
                              "r"(bfL[j][0]), "r"(bfL[j][1]));
                    }
                }
        }
        if (!more) break;
    }

    #pragma unroll
    for (int i = 0; i < MT; i++) {
        int m = m0 + wm * (TM / 2) + i * 16 + g;
        #pragma unroll
        for (int j = 0; j < NT; j++) {
            int n = n0 + wn * (TN / 4) + j * 8 + 2 * tg;
            float c0 = acc[i][j][0] * alpha, c1 = acc[i][j][1] * alpha;
            float c2 = acc[i][j][2] * alpha, c3 = acc[i][j][3] * alpha;
            if (bias) {
                float b0 = bias[n], b1 = bias[n + 1];
                c0 += b0; c1 += b1; c2 += b0; c3 += b1;
            }
            if (act) {
                c0 = 0.5f * c0 * (1.f + erff(c0 * 0.7071067811865475f));
                c1 = 0.5f * c1 * (1.f + erff(c1 * 0.7071067811865475f));
                c2 = 0.5f * c2 * (1.f + erff(c2 * 0.7071067811865475f));
                c3 = 0.5f * c3 * (1.f + erff(c3 * 0.7071067811865475f));
            }
            if (resid) {
                const float* Rb = resid + cOff;
                c0 += Rb[(size_t)m * ldc + n];
                c1 += Rb[(size_t)m * ldc + n + 1];
                c2 += Rb[(size_t)(m + 8) * ldc + n];
                c3 += Rb[(size_t)(m + 8) * ldc + n + 1];
            }
            float2 lo = {c0, c1}, hi = {c2, c3};
            *(float2*)(Cb + (size_t)m * ldc + n) = lo;
            *(float2*)(Cb + (size_t)(m + 8) * ldc + n) = hi;
        }
    }
}

// ---------------- softmax with optional fused shift()+pos add ----------------
template<bool POS>
__global__ void __launch_bounds__(128) softmax_kernel(float* __restrict__ S,
                                                      const float* __restrict__ P,
                                                      int klen) {
    __shared__ float sbuf[4];
    const int i = blockIdx.x, z = blockIdx.y, tid = threadIdx.x;
    float* row = S + ((size_t)z * 512 + i) * klen;
    const float* prow = POS ? (P + ((size_t)z * 512 + i) * KVN) : nullptr;
    float mx = -1e30f;
    for (int j = tid; j < klen; j += 128) {
        float v = row[j];
        if (POS) {
            int r = j + 511 - i;
            if (r < KVN) v += prow[r];
        }
        row[j] = v;
        mx = fmaxf(mx, v);
    }
    mx = block_red_max(mx, sbuf, 128);
    float sum = 0.f;
    for (int j = tid; j < klen; j += 128) {
        float e = expf(row[j] - mx);
        row[j] = e;
        sum += e;
    }
    sum = block_red_sum(sum, sbuf, 128);
    float inv = 1.f / sum;
    for (int j = tid; j < klen; j += 128) row[j] *= inv;
}

// ---------------- host wrappers ----------------
static void gemm_proj(const float* A, const float* B, float* C, int M, int N, int K,
                      const float* bias = nullptr, const float* resid = nullptr, int act = 0) {
    if ((M % 128 == 0) && (N % 128 == 0) && ((M >> 7) * (N >> 7) >= 128)) {
        dim3 grid(N / 128, M / 128, 1);
        gmma_kernel<128, 128, false, false><<<grid, 256>>>(A, B, C, M, N, K, K, N, N,
            0, 0, 0, 0, 0, 0, 1, 1.f, bias, resid, act);
    } else {
        dim3 grid(N / 64, M / 64, 1);
        gmma_kernel<64, 64, false, false><<<grid, 256>>>(A, B, C, M, N, K, K, N, N,
            0, 0, 0, 0, 0, 0, 1, 1.f, bias, resid, act);
    }
}

// S[z][512][klen] = alpha * Q_h @ K_h^T ; z = b*8+h
static void gemm_scores(const float* q, const float* kbase, float* Sb,
                        int klen, size_t kOuter, float alpha) {
    dim3 grid(klen / 64, 512 / 64, 32);
    gmma_kernel<64, 64, true, true><<<grid, 256>>>(q, kbase, Sb, 512, klen, 64,
        512, 512, klen,
        (size_t)512 * 512, 64, kOuter, 64, (size_t)8 * 512 * klen, (size_t)512 * klen, 8,
        alpha, nullptr, nullptr, 0);
}

// P[z][512][1152] = 8 * Q_h @ pos[h]^T
static void gemm_pos(const float* q, const float* pos, float* Pb) {
    dim3 grid(KVN / 64, 512 / 64, 32);
    gmma_kernel<64, 64, true, true><<<grid, 256>>>(q, pos, Pb, 512, KVN, 64,
        512, 64, KVN,
        (size_t)512 * 512, 64, 0, (size_t)KVN * 64, (size_t)8 * 512 * KVN, (size_t)512 * KVN, 8,
        8.f, nullptr, nullptr, 0);
}

// out[b][i][h*64+d] = S_z @ V_h
static void gemm_av(const float* Sb, const float* vbase, float* out,
                    int klen, size_t vOuter) {
    dim3 grid(64 / 64, 512 / 64, 32);
    gmma_kernel<64, 64, false, true><<<grid, 256>>>(Sb, vbase, out, 512, 64, klen,
        klen, 512, 512,
        (size_t)8 * 512 * klen, (size_t)512 * klen, vOuter, 64, (size_t)512 * 512, 64, 8,
        1.f, nullptr, nullptr, 0);
}

static void run_softmax(float* Sb, const float* Pb, int klen, bool pos) {
    dim3 grid(512, 32);
    if (pos) softmax_kernel<true><<<grid, 128>>>(Sb, Pb, klen);
    else     softmax_kernel<false><<<grid, 128>>>(Sb, nullptr, klen);
}

extern "C" void kernel_launch(void* const* d_in, const int* in_sizes, int n_in,
                              void* d_out, int out_size) {
    const int*   trg     = (const int*)  d_in[0];
    const float* latent  = (const float*)d_in[3];
    const float* mems    = (const float*)d_in[4];
    const float* cmems   = (const float*)d_in[5];
    const float* pos_emb = (const float*)d_in[6];
    const float* embed   = (const float*)d_in[7];
    const float* W_self  = (const float*)d_in[8];
    const float* ln1_g   = (const float*)d_in[9];
    const float* ln1_b   = (const float*)d_in[10];
    const float* conv_w  = (const float*)d_in[11];
    const float* conv_b  = (const float*)d_in[12];
    const float* W_src   = (const float*)d_in[13];
    const float* ln2_g   = (const float*)d_in[14];
    const float* ln2_b   = (const float*)d_in[15];
    const float* w1      = (const float*)d_in[16];
    const float* b1      = (const float*)d_in[17];
    const float* w2      = (const float*)d_in[18];
    const float* b2      = (const float*)d_in[19];

    float* Sc;
    cudaGetSymbolAddress((void**)&Sc, g_scratch);
    float* X    = Sc + O_X;
    float* KVb  = Sc + O_KV;
    float* Q    = Sc + O_Q;
    float* K    = Sc + O_K;
    float* V    = Sc + O_V;
    float* ATT  = Sc + O_ATT;
    float* A    = Sc + O_A;
    float* TMP  = Sc + O_TMP;
    float* QR   = Sc + O_QR;
    float* KR   = Sc + O_KR;
    float* VR   = Sc + O_VR;
    float* KN   = Sc + O_KN;
    float* VN   = Sc + O_VN;
    float* TGT  = Sc + O_TGT;
    float* RNEW = Sc + O_RNEW;
    float* NCM  = Sc + O_NCM;
    float* CWT  = Sc + O_CWT;
    float* FF   = Sc + O_FF;
    float* Y    = Sc + O_Y;
    float* X1   = Sc + O_X1;
    float* PART = Sc + O_PART;
    float* LOSS = Sc + O_LOSS;
    float* SS   = Sc + O_S;
    float* PP   = Sc + O_P;

    zero_loss_kernel<<<1, 32>>>(LOSS);
    embed_kernel<<<(int)(EL_X / 256), 256>>>(trg, embed, X);

    for (int i = 0; i < NL; i++) {
        const float* mem = mems  + (size_t)i * BB * 512 * 512;
        const float* cm  = cmems + (size_t)i * BB * 128 * 512;
        const float* W0 = W_self + ((size_t)i * 4 + 0) * 512 * 512;
        const float* W1 = W_self + ((size_t)i * 4 + 1) * 512 * 512;
        const float* W2 = W_self + ((size_t)i * 4 + 2) * 512 * 512;
        const float* W3 = W_self + ((size_t)i * 4 + 3) * 512 * 512;
        const float* Ws0 = W_src + ((size_t)i * 4 + 0) * 512 * 512;
        const float* Ws1 = W_src + ((size_t)i * 4 + 1) * 512 * 512;
        const float* Ws2 = W_src + ((size_t)i * 4 + 2) * 512 * 512;
        const float* Ws3 = W_src + ((size_t)i * 4 + 3) * 512 * 512;

        // ---- self-attention over kv = [cmem, mem, x] ----
        kv_kernel<<<(int)(EL_KV / 256), 256>>>(cm, mem, X, KVb);
        gemm_proj(X,   W0, Q, 2048, 512, 512);
        gemm_proj(KVb, W1, K, 4608, 512, 512);
        gemm_proj(KVb, W2, V, 4608, 512, 512);
        gemm_pos(Q, pos_emb, PP);
        gemm_scores(Q, K, SS, KVN, (size_t)KVN * 512, 0.125f);
        run_softmax(SS, PP, KVN, true);
        gemm_av(SS, V, ATT, KVN, (size_t)KVN * 512);
        gemm_proj(ATT, W3, TMP, 2048, 512, 512, nullptr, X, 0);
        ln_kernel<<<2048, 128>>>(TMP, ln1_g + i * 512, ln1_b + i * 512, A);

        // ---- compressed-memory reconstruction loss ----
        tconv_kernel<<<4096, 256>>>(conv_w + (size_t)i * 512 * 512 * 4, CWT);
        gemm_proj(mem, CWT, NCM, 512, 512, 2048, conv_b + i * 512);
        gemm_proj(A, W0, QR, 2048, 512, 512);
        // target: K/V over old_mem = rows [128,640) of K/V (same weights!)
        gemm_scores(QR, K + 128 * 512, SS, 512, (size_t)KVN * 512, 0.125f);
        run_softmax(SS, nullptr, 512, false);
        gemm_av(SS, V + 128 * 512, TGT, 512, (size_t)KVN * 512);
        // rnew: K/V over NCM
        gemm_proj(NCM, W1, KN, 512, 512, 512);
        gemm_proj(NCM, W2, VN, 512, 512, 512);
        gemm_scores(QR, KN, SS, 128, (size_t)128 * 512, 0.125f);
        run_softmax(SS, nullptr, 128, false);
        gemm_av(SS, VN, RNEW, 128, (size_t)128 * 512);
        loss_part_kernel<<<1024, 256>>>(RNEW, TGT, PART);
        loss_acc_kernel<<<1, 256>>>(PART, LOSS);

        // ---- cross-attention to latent (no residual) ----
        gemm_proj(A,      Ws0, QR, 2048, 512, 512);
        gemm_proj(latent, Ws1, KR, 1024, 512, 512);
        gemm_proj(latent, Ws2, VR, 1024, 512, 512);
        gemm_scores(QR, KR, SS, 256, (size_t)256 * 512, 0.125f);
        run_softmax(SS, nullptr, 256, false);
        gemm_av(SS, VR, TMP, 256, (size_t)256 * 512);
        gemm_proj(TMP, Ws3, X1, 2048, 512, 512);

        // ---- FFN: x = x1 + gelu(LN(x1)@w1+b1)@w2 + b2 ----
        ln_kernel<<<2048, 128>>>(X1, ln2_g + i * 512, ln2_b + i * 512, Y);
        gemm_proj(Y,  w1 + (size_t)i * 512 * 2048, FF, 2048, 2048, 512,  b1 + (size_t)i * 2048, nullptr, 1);
        gemm_proj(FF, w2 + (size_t)i * 2048 * 512, X,  2048, 512,  2048, b2 + (size_t)i * 512,  X1,      0);
    }

    size_t nout = (size_t)out_size;
    out_kernel<<<(int)((nout + 255) / 256), 256>>>((float*)d_out, X, LOSS, nout);
}

// round 5
// speedup vs baseline: 2.1571x; 1.0819x over previous
#include <cuda_runtime.h>
#include <math.h>
#include <stdint.h>

#define NL 4
#define BB 4
#define DD 512
#define HH 8
#define KVN 1152

#define EL_X   1048576ull
#define EL_KV  2359296ull
#define EL_S   18874368ull   // 32 * 512 * 1152

constexpr size_t O_X    = 0;
constexpr size_t O_KV   = O_X    + EL_X;
constexpr size_t O_QKV  = O_KV   + EL_KV;          // 3 x [4608,512]
constexpr size_t O_ATT  = O_QKV  + 3ull * EL_KV;
constexpr size_t O_A    = O_ATT  + EL_X;
constexpr size_t O_TMP  = O_A    + EL_X;
constexpr size_t O_QR   = O_TMP  + EL_X;
constexpr size_t O_QR2  = O_QR   + EL_X;
constexpr size_t O_KR   = O_QR2  + EL_X;
constexpr size_t O_VR   = O_KR   + EL_X;
constexpr size_t O_KN   = O_VR   + EL_X;
constexpr size_t O_VN   = O_KN   + 262144ull;
constexpr size_t O_TGT  = O_VN   + 262144ull;
constexpr size_t O_RNEW = O_TGT  + EL_X;
constexpr size_t O_NCM  = O_RNEW + EL_X;
constexpr size_t O_CWT  = O_NCM  + 262144ull;
constexpr size_t O_FF   = O_CWT  + EL_X;
constexpr size_t O_Y    = O_FF   + 4194304ull;
constexpr size_t O_X1   = O_Y    + EL_X;
constexpr size_t O_PART = O_X1   + EL_X;
constexpr size_t O_LOSS = O_PART + 1024ull;
constexpr size_t O_S    = O_LOSS + 16ull;
constexpr size_t O_P    = O_S    + EL_S;
constexpr size_t SCRATCH_TOTAL = O_P + EL_S;

__device__ float g_scratch[SCRATCH_TOTAL];

__device__ __forceinline__ uint32_t f2tf32(float f) {
    uint32_t u;
    asm("cvt.rna.tf32.f32 %0, %1;" : "=r"(u) : "f"(f));
    return u;
}

__device__ __forceinline__ float block_red_sum(float v, float* sbuf, int nthreads) {
    int lane = threadIdx.x & 31, w = threadIdx.x >> 5;
    #pragma unroll
    for (int o = 16; o; o >>= 1) v += __shfl_xor_sync(0xffffffffu, v, o);
    __syncthreads();
    if (lane == 0) sbuf[w] = v;
    __syncthreads();
    int nw = nthreads >> 5;
    float r = 0.f;
    for (int i = 0; i < nw; i++) r += sbuf[i];
    return r;
}

__device__ __forceinline__ float block_red_max(float v, float* sbuf, int nthreads) {
    int lane = threadIdx.x & 31, w = threadIdx.x >> 5;
    #pragma unroll
    for (int o = 16; o; o >>= 1) v = fmaxf(v, __shfl_xor_sync(0xffffffffu, v, o));
    __syncthreads();
    if (lane == 0) sbuf[w] = v;
    __syncthreads();
    int nw = nthreads >> 5;
    float r = -1e30f;
    for (int i = 0; i < nw; i++) r = fmaxf(r, sbuf[i]);
    return r;
}

__global__ void zero_loss_kernel(float* loss) { if (threadIdx.x == 0) loss[0] = 0.f; }

__global__ void embed_kernel(const int* __restrict__ trg, const float* __restrict__ emb,
                             float* __restrict__ x) {
    size_t idx = (size_t)blockIdx.x * blockDim.x + threadIdx.x;
    if (idx >= EL_X) return;
    int row = (int)(idx >> 9);
    int d   = (int)(idx & 511);
    x[idx] = emb[(size_t)trg[row] * 512 + d];
}

__global__ void kv_kernel(const float* __restrict__ cm, const float* __restrict__ mem,
                          const float* __restrict__ x, float* __restrict__ kv) {
    size_t idx = (size_t)blockIdx.x * blockDim.x + threadIdx.x;
    if (idx >= EL_KV) return;
    int b   = (int)(idx / ((size_t)KVN * DD));
    int rem = (int)(idx - (size_t)b * KVN * DD);
    int p = rem >> 9, d = rem & 511;
    float val;
    if (p < 128)       val = cm [(size_t)b * 128 * 512 + ((size_t)p << 9) + d];
    else if (p < 640)  val = mem[(size_t)b * 512 * 512 + ((size_t)(p - 128) << 9) + d];
    else               val = x  [(size_t)b * 512 * 512 + ((size_t)(p - 640) << 9) + d];
    kv[idx] = val;
}

__global__ void tconv_kernel(const float* __restrict__ cw, float* __restrict__ cwt) {
    size_t idx = (size_t)blockIdx.x * blockDim.x + threadIdx.x;
    if (idx >= 2048ull * 512ull) return;
    int o = (int)(idx & 511);
    int k = (int)(idx >> 9);
    int d = k & 511;
    int r = k >> 9;
    cwt[idx] = cw[((size_t)o * 512 + d) * 4 + r];
}

__global__ void out_kernel(float* __restrict__ o, const float* __restrict__ x,
                           const float* __restrict__ loss, size_t nout) {
    size_t i = (size_t)blockIdx.x * blockDim.x + threadIdx.x;
    if (i >= nout) return;
    if (i < EL_X) o[i] = x[i];
    else          o[i] = loss[0] * (1.f / (1048576.f * 4.f));
}

__global__ void __launch_bounds__(128) ln_kernel(const float* __restrict__ in,
                                                 const float* __restrict__ g,
                                                 const float* __restrict__ bb,
                                                 float* __restrict__ out) {
    __shared__ float sbuf[8];
    const int row = blockIdx.x, tid = threadIdx.x;
    const size_t base = (size_t)row * 512 + (size_t)tid * 4;
    float4 v4 = *(const float4*)(in + base);
    float v[4] = {v4.x, v4.y, v4.z, v4.w};
    float s = v[0] + v[1] + v[2] + v[3];
    s = block_red_sum(s, sbuf, 128);
    float mu = s * (1.f / 512.f);
    float d2 = 0.f;
    #pragma unroll
    for (int j = 0; j < 4; j++) { float t = v[j] - mu; d2 += t * t; }
    d2 = block_red_sum(d2, sbuf, 128);
    float rs = rsqrtf(d2 * (1.f / 512.f) + 1e-5f);
    int c = tid * 4;
    float4 o;
    o.x = (v[0] - mu) * rs * g[c + 0] + bb[c + 0];
    o.y = (v[1] - mu) * rs * g[c + 1] + bb[c + 1];
    o.z = (v[2] - mu) * rs * g[c + 2] + bb[c + 2];
    o.w = (v[3] - mu) * rs * g[c + 3] + bb[c + 3];
    *(float4*)(out + base) = o;
}

__global__ void __launch_bounds__(256) loss_part_kernel(const float* __restrict__ a,
                                                        const float* __restrict__ b,
                                                        float* __restrict__ part) {
    __shared__ float sbuf[8];
    size_t base = (size_t)blockIdx.x * 1024 + (size_t)threadIdx.x * 4;
    float4 x = *(const float4*)(a + base);
    float4 y = *(const float4*)(b + base);
    float dx = x.x - y.x, dy = x.y - y.y, dz = x.z - y.z, dw = x.w - y.w;
    float s = dx * dx + dy * dy + dz * dz + dw * dw;
    s = block_red_sum(s, sbuf, 256);
    if (threadIdx.x == 0) part[blockIdx.x] = s;
}

__global__ void __launch_bounds__(256) loss_acc_kernel(const float* __restrict__ part,
                                                       float* __restrict__ loss) {
    __shared__ float sbuf[8];
    int tid = threadIdx.x;
    float s = part[tid] + part[tid + 256] + part[tid + 512] + part[tid + 768];
    s = block_red_sum(s, sbuf, 256);
    if (tid == 0) loss[0] += s;
}

// ---------------- generalized batched TF32 tensor-core GEMM ----------------
// C = alpha * A @ B (+bias)(+gelu)(+resid)
// A row-major [M,K] (row stride lda); B: BNM ? B[n][k] : B[k][n] (row stride ldb)
// batch z: offset(tensor) = (z/mod)*Outer + (z%mod)*Inner
// X3: 3xTF32 split (hi/lo) for ~fp32 accuracy.
// 8 warps as 2(m) x 4(n); warp tile = (TM/2) x (TN/4); MT=TM/32, NT=TN/32.
template<int TM, int TN, bool BNM, bool X3>
__global__ void __launch_bounds__(256) gmma_kernel(
    const float* __restrict__ A, const float* __restrict__ B, float* __restrict__ C,
    int M, int N, int K, int lda, int ldb, int ldc,
    size_t aO, size_t aI, size_t bO, size_t bI, size_t cO, size_t cI, int mod,
    float alpha, const float* __restrict__ bias,
    const float* __restrict__ resid, int act)
{
    constexpr int MT = TM / 32;
    constexpr int NT = TN / 32;
    constexpr int AVN = TM / 64;
    constexpr int BVN = TN / 64;
    __shared__ uint32_t AsH[TM][20];
    __shared__ uint32_t BsH[TN][20];
    __shared__ uint32_t AsL[X3 ? TM : 1][X3 ? 20 : 4];
    __shared__ uint32_t BsL[X3 ? TN : 1][X3 ? 20 : 4];

    const int z = blockIdx.z;
    const size_t aOff = (size_t)(z / mod) * aO + (size_t)(z % mod) * aI;
    const size_t bOff = (size_t)(z / mod) * bO + (size_t)(z % mod) * bI;
    const size_t cOff = (size_t)(z / mod) * cO + (size_t)(z % mod) * cI;
    const float* Ab = A + aOff;
    const float* Bb = B + bOff;
    float* Cb = C + cOff;

    const int tid = threadIdx.x;
    const int wid = tid >> 5, lane = tid & 31;
    const int wm = wid >> 2, wn = wid & 3;
    const int g = lane >> 2, tg = lane & 3;
    const int m0 = blockIdx.y * TM, n0 = blockIdx.x * TN;

    float acc[MT][NT][4];
    #pragma unroll
    for (int i = 0; i < MT; i++)
        #pragma unroll
        for (int j = 0; j < NT; j++)
            #pragma unroll
            for (int c = 0; c < 4; c++) acc[i][j][c] = 0.f;

    float4 pa[AVN], pb[BVN];
    #pragma unroll
    for (int v = 0; v < AVN; v++) {
        int idx4 = tid + v * 256;
        int row = idx4 >> 2, kg = (idx4 & 3) << 2;
        pa[v] = *(const float4*)(Ab + (size_t)(m0 + row) * lda + kg);
    }
    #pragma unroll
    for (int v = 0; v < BVN; v++) {
        int idx4 = tid + v * 256;
        if (BNM) {
            int row = idx4 >> 2, kg = (idx4 & 3) << 2;
            pb[v] = *(const float4*)(Bb + (size_t)(n0 + row) * ldb + kg);
        } else {
            int k = idx4 / (TN / 4), c = (idx4 % (TN / 4)) << 2;
            pb[v] = *(const float4*)(Bb + (size_t)k * ldb + n0 + c);
        }
    }

    for (int k0 = 0;; k0 += 16) {
        __syncthreads();
        #pragma unroll
        for (int v = 0; v < AVN; v++) {
            int idx4 = tid + v * 256;
            int row = idx4 >> 2, kg = (idx4 & 3) << 2;
            float f[4] = {pa[v].x, pa[v].y, pa[v].z, pa[v].w};
            #pragma unroll
            for (int j = 0; j < 4; j++) {
                uint32_t hi = f2tf32(f[j]);
                AsH[row][kg + j] = hi;
                if (X3) AsL[row][kg + j] = f2tf32(f[j] - __uint_as_float(hi));
            }
        }
        #pragma unroll
        for (int v = 0; v < BVN; v++) {
            int idx4 = tid + v * 256;
            float f[4] = {pb[v].x, pb[v].y, pb[v].z, pb[v].w};
            if (BNM) {
                int row = idx4 >> 2, kg = (idx4 & 3) << 2;
                #pragma unroll
                for (int j = 0; j < 4; j++) {
                    uint32_t hi = f2tf32(f[j]);
                    BsH[row][kg + j] = hi;
                    if (X3) BsL[row][kg + j] = f2tf32(f[j] - __uint_as_float(hi));
                }
            } else {
                int k = idx4 / (TN / 4), c = (idx4 % (TN / 4)) << 2;
                #pragma unroll
                for (int j = 0; j < 4; j++) {
                    uint32_t hi = f2tf32(f[j]);
                    BsH[c + j][k] = hi;
                    if (X3) BsL[c + j][k] = f2tf32(f[j] - __uint_as_float(hi));
                }
            }
        }
        __syncthreads();
        bool more = (k0 + 16 < K);
        if (more) {
            int kn = k0 + 16;
            #pragma unroll
            for (int v = 0; v < AVN; v++) {
                int idx4 = tid + v * 256;
                int row = idx4 >> 2, kg = (idx4 & 3) << 2;
                pa[v] = *(const float4*)(Ab + (size_t)(m0 + row) * lda + kn + kg);
            }
            #pragma unroll
            for (int v = 0; v < BVN; v++) {
                int idx4 = tid + v * 256;
                if (BNM) {
                    int row = idx4 >> 2, kg = (idx4 & 3) << 2;
                    pb[v] = *(const float4*)(Bb + (size_t)(n0 + row) * ldb + kn + kg);
                } else {
                    int k = idx4 / (TN / 4), c = (idx4 % (TN / 4)) << 2;
                    pb[v] = *(const float4*)(Bb + (size_t)(kn + k) * ldb + n0 + c);
                }
            }
        }
        #pragma unroll
        for (int kk = 0; kk < 16; kk += 8) {
            uint32_t afH[MT][4], bfH[NT][2];
            uint32_t afL[X3 ? MT : 1][4], bfL[X3 ? NT : 1][2];
            #pragma unroll
            for (int i = 0; i < MT; i++) {
                int r = wm * (TM / 2) + i * 16 + g;
                afH[i][0] = AsH[r][kk + tg];
                afH[i][1] = AsH[r + 8][kk + tg];
                afH[i][2] = AsH[r][kk + tg + 4];
                afH[i][3] = AsH[r + 8][kk + tg + 4];
                if (X3) {
                    afL[i][0] = AsL[r][kk + tg];
                    afL[i][1] = AsL[r + 8][kk + tg];
                    afL[i][2] = AsL[r][kk + tg + 4];
                    afL[i][3] = AsL[r + 8][kk + tg + 4];
                }
            }
            #pragma unroll
            for (int j = 0; j < NT; j++) {
                int n = wn * (TN / 4) + j * 8 + g;
                bfH[j][0] = BsH[n][kk + tg];
                bfH[j][1] = BsH[n][kk + tg + 4];
                if (X3) {
                    bfL[j][0] = BsL[n][kk + tg];
                    bfL[j][1] = BsL[n][kk + tg + 4];
                }
            }
            #pragma unroll
            for (int i = 0; i < MT; i++)
                #pragma unroll
                for (int j = 0; j < NT; j++) {
                    asm volatile(
                        "mma.sync.aligned.m16n8k8.row.col.f32.tf32.tf32.f32 "
                        "{%0,%1,%2,%3}, {%4,%5,%6,%7}, {%8,%9}, {%0,%1,%2,%3};\n"
                        : "+f"(acc[i][j][0]), "+f"(acc[i][j][1]),
                          "+f"(acc[i][j][2]), "+f"(acc[i][j][3])
                        : "r"(afH[i][0]), "r"(afH[i][1]), "r"(afH[i][2]), "r"(afH[i][3]),
                          "r"(bfH[j][0]), "r"(bfH[j][1]));
                    if (X3) {
                        asm volatile(
                            "mma.sync.aligned.m16n8k8.row.col.f32.tf32.tf32.f32 "
                            "{%0,%1,%2,%3}, {%4,%5,%6,%7}, {%8,%9}, {%0,%1,%2,%3};\n"
                            : "+f"(acc[i][j][0]), "+f"(acc[i][j][1]),
                              "+f"(acc[i][j][2]), "+f"(acc[i][j][3])
                            : "r"(afL[i][0]), "r"(afL[i][1]), "r"(afL[i][2]), "r"(afL[i][3]),
                              "r"(bfH[j][0]), "r"(bfH[j][1]));
                        asm volatile(
                            "mma.sync.aligned.m16n8k8.row.col.f32.tf32.tf32.f32 "
                            "{%0,%1,%2,%3}, {%4,%5,%6,%7}, {%8,%9}, {%0,%1,%2,%3};\n"
                            : "+f"(acc[i][j][0]), "+f"(acc[i][j][1]),
                              "+f"(acc[i][j][2]), "+f"(acc[i][j][3])
                            : "r"(afH[i][0]), "r"(afH[i][1]), "r"(afH[i][2]), "r"(afH[i][3]),
                              "r"(bfL[j][0]), "r"(bfL[j][1]));
                    }
                }
        }
        if (!more) break;
    }

    #pragma unroll
    for (int i = 0; i < MT; i++) {
        int m = m0 + wm * (TM / 2) + i * 16 + g;
        #pragma unroll
        for (int j = 0; j < NT; j++) {
            int n = n0 + wn * (TN / 4) + j * 8 + 2 * tg;
            float c0 = acc[i][j][0] * alpha, c1 = acc[i][j][1] * alpha;
            float c2 = acc[i][j][2] * alpha, c3 = acc[i][j][3] * alpha;
            if (bias) {
                float b0 = bias[n], b1 = bias[n + 1];
                c0 += b0; c1 += b1; c2 += b0; c3 += b1;
            }
            if (act) {
                c0 = 0.5f * c0 * (1.f + erff(c0 * 0.7071067811865475f));
                c1 = 0.5f * c1 * (1.f + erff(c1 * 0.7071067811865475f));
                c2 = 0.5f * c2 * (1.f + erff(c2 * 0.7071067811865475f));
                c3 = 0.5f * c3 * (1.f + erff(c3 * 0.7071067811865475f));
            }
            if (resid) {
                const float* Rb = resid + cOff;
                c0 += Rb[(size_t)m * ldc + n];
                c1 += Rb[(size_t)m * ldc + n + 1];
                c2 += Rb[(size_t)(m + 8) * ldc + n];
                c3 += Rb[(size_t)(m + 8) * ldc + n + 1];
            }
            float2 lo = {c0, c1}, hi = {c2, c3};
            *(float2*)(Cb + (size_t)m * ldc + n) = lo;
            *(float2*)(Cb + (size_t)(m + 8) * ldc + n) = hi;
        }
    }
}

// ---------------- softmax with optional fused shift()+pos add ----------------
template<bool POS>
__global__ void __launch_bounds__(128) softmax_kernel(float* __restrict__ S,
                                                      const float* __restrict__ P,
                                                      int klen) {
    __shared__ float sbuf[4];
    const int i = blockIdx.x, z = blockIdx.y, tid = threadIdx.x;
    float* row = S + ((size_t)z * 512 + i) * klen;
    const float* prow = POS ? (P + ((size_t)z * 512 + i) * KVN) : nullptr;
    float mx = -1e30f;
    for (int j = tid; j < klen; j += 128) {
        float v = row[j];
        if (POS) {
            int r = j + 511 - i;
            if (r < KVN) v += prow[r];
        }
        row[j] = v;
        mx = fmaxf(mx, v);
    }
    mx = block_red_max(mx, sbuf, 128);
    float sum = 0.f;
    for (int j = tid; j < klen; j += 128) {
        float e = expf(row[j] - mx);
        row[j] = e;
        sum += e;
    }
    sum = block_red_sum(sum, sbuf, 128);
    float inv = 1.f / sum;
    for (int j = tid; j < klen; j += 128) row[j] *= inv;
}

// ---------------- host wrappers ----------------
static void gemm_batched(const float* A, const float* B, float* C, int M, int N, int K,
                         int lda, int ldb, int ldc,
                         size_t aO, size_t aI, size_t bO, size_t bI, size_t cO, size_t cI,
                         int mod, int z, float alpha,
                         const float* bias, const float* resid, int act) {
    if ((M % 128 == 0) && (N % 128 == 0) && (size_t)(M / 128) * (N / 128) * z >= 120) {
        dim3 grid(N / 128, M / 128, z);
        gmma_kernel<128, 128, false, false><<<grid, 256>>>(A, B, C, M, N, K, lda, ldb, ldc,
            aO, aI, bO, bI, cO, cI, mod, alpha, bias, resid, act);
    } else if ((M % 128 == 0) && (N % 64 == 0) && (size_t)(M / 128) * (N / 64) * z >= 120) {
        dim3 grid(N / 64, M / 128, z);
        gmma_kernel<128, 64, false, false><<<grid, 256>>>(A, B, C, M, N, K, lda, ldb, ldc,
            aO, aI, bO, bI, cO, cI, mod, alpha, bias, resid, act);
    } else {
        dim3 grid(N / 64, M / 64, z);
        gmma_kernel<64, 64, false, false><<<grid, 256>>>(A, B, C, M, N, K, lda, ldb, ldc,
            aO, aI, bO, bI, cO, cI, mod, alpha, bias, resid, act);
    }
}

static void gemm_proj(const float* A, const float* B, float* C, int M, int N, int K,
                      const float* bias = nullptr, const float* resid = nullptr, int act = 0) {
    gemm_batched(A, B, C, M, N, K, K, N, N, 0, 0, 0, 0, 0, 0, 1, 1, 1.f, bias, resid, act);
}

// S[z][512][klen] = alpha * Q_h @ K_h^T ; z = b*8+h
static void gemm_scores(const float* q, size_t qOuter, const float* kbase, size_t kOuter,
                        float* Sb, int klen, float alpha) {
    dim3 grid(klen / 64, 512 / 128, 32);
    gmma_kernel<128, 64, true, true><<<grid, 256>>>(q, kbase, Sb, 512, klen, 64,
        512, 512, klen,
        qOuter, 64, kOuter, 64, (size_t)8 * 512 * klen, (size_t)512 * klen, 8,
        alpha, nullptr, nullptr, 0);
}

// P[z][512][1152] = 8 * Q_h @ pos[h]^T
static void gemm_pos(const float* q, size_t qOuter, const float* pos, float* Pb) {
    dim3 grid(KVN / 64, 512 / 128, 32);
    gmma_kernel<128, 64, true, true><<<grid, 256>>>(q, pos, Pb, 512, KVN, 64,
        512, 64, KVN,
        qOuter, 64, 0, (size_t)KVN * 64, (size_t)8 * 512 * KVN, (size_t)512 * KVN, 8,
        8.f, nullptr, nullptr, 0);
}

// out[b][i][h*64+d] = S_z @ V_h
static void gemm_av(const float* Sb, const float* vbase, size_t vOuter, float* out, int klen) {
    dim3 grid(1, 512 / 128, 32);
    gmma_kernel<128, 64, false, true><<<grid, 256>>>(Sb, vbase, out, 512, 64, klen,
        klen, 512, 512,
        (size_t)8 * 512 * klen, (size_t)512 * klen, vOuter, 64, (size_t)512 * 512, 64, 8,
        1.f, nullptr, nullptr, 0);
}

static void run_softmax(float* Sb, const float* Pb, int klen, bool pos) {
    dim3 grid(512, 32);
    if (pos) softmax_kernel<true><<<grid, 128>>>(Sb, Pb, klen);
    else     softmax_kernel<false><<<grid, 128>>>(Sb, nullptr, klen);
}

extern "C" void kernel_launch(void* const* d_in, const int* in_sizes, int n_in,
                              void* d_out, int out_size) {
    const int*   trg     = (const int*)  d_in[0];
    const float* latent  = (const float*)d_in[3];
    const float* mems    = (const float*)d_in[4];
    const float* cmems   = (const float*)d_in[5];
    const float* pos_emb = (const float*)d_in[6];
    const float* embed   = (const float*)d_in[7];
    const float* W_self  = (const float*)d_in[8];
    const float* ln1_g   = (const float*)d_in[9];
    const float* ln1_b   = (const float*)d_in[10];
    const float* conv_w  = (const float*)d_in[11];
    const float* conv_b  = (const float*)d_in[12];
    const float* W_src   = (const float*)d_in[13];
    const float* ln2_g   = (const float*)d_in[14];
    const float* ln2_b   = (const float*)d_in[15];
    const float* w1      = (const float*)d_in[16];
    const float* b1      = (const float*)d_in[17];
    const float* w2      = (const float*)d_in[18];
    const float* b2      = (const float*)d_in[19];

    float* Sc;
    cudaGetSymbolAddress((void**)&Sc, g_scratch);
    float* X    = Sc + O_X;
    float* KVb  = Sc + O_KV;
    float* QKV  = Sc + O_QKV;           // Q slab [4608,512]
    float* Kp   = QKV + EL_KV;          // K slab
    float* Vp   = QKV + 2 * EL_KV;      // V slab
    float* ATT  = Sc + O_ATT;
    float* A    = Sc + O_A;
    float* TMP  = Sc + O_TMP;
    float* QR   = Sc + O_QR;
    float* QR2  = Sc + O_QR2;
    float* KR   = Sc + O_KR;
    float* VR   = Sc + O_VR;
    float* KN   = Sc + O_KN;
    float* VN   = Sc + O_VN;
    float* TGT  = Sc + O_TGT;
    float* RNEW = Sc + O_RNEW;
    float* NCM  = Sc + O_NCM;
    float* CWT  = Sc + O_CWT;
    float* FF   = Sc + O_FF;
    float* Y    = Sc + O_Y;
    float* X1   = Sc + O_X1;
    float* PART = Sc + O_PART;
    float* LOSS = Sc + O_LOSS;
    float* SS   = Sc + O_S;
    float* PP   = Sc + O_P;

    zero_loss_kernel<<<1, 32>>>(LOSS);
    embed_kernel<<<(int)(EL_X / 256), 256>>>(trg, embed, X);

    for (int i = 0; i < NL; i++) {
        const float* mem = mems  + (size_t)i * BB * 512 * 512;
        const float* cm  = cmems + (size_t)i * BB * 128 * 512;
        const float* W0 = W_self + ((size_t)i * 4 + 0) * 512 * 512;
        const float* W1 = W_self + ((size_t)i * 4 + 1) * 512 * 512;
        const float* Ws0 = W_src + ((size_t)i * 4 + 0) * 512 * 512;
        const float* Ws1 = W_src + ((size_t)i * 4 + 1) * 512 * 512;
        const float* Ws3 = W_src + ((size_t)i * 4 + 3) * 512 * 512;
        const float* W3  = W_self + ((size_t)i * 4 + 3) * 512 * 512;

        // ---- self-attention over kv = [cmem, mem, x] ----
        kv_kernel<<<(int)(EL_KV / 256), 256>>>(cm, mem, X, KVb);
        // fused QKV: z=3 over contiguous weights {W0,W1,W2}; Q slab covers ALL kv rows,
        // the x-rows (640..1151 per batch) are the real queries.
        gemm_batched(KVb, W0, QKV, 4608, 512, 512, 512, 512, 512,
                     0, 0, 0, 262144ull, 0, EL_KV, 3, 3, 1.f, nullptr, nullptr, 0);
        const float* Qx = QKV + 640ull * 512;   // Q rows of x, aO = 1152*512 per batch
        gemm_pos(Qx, (size_t)KVN * 512, pos_emb, PP);
        gemm_scores(Qx, (size_t)KVN * 512, Kp, (size_t)KVN * 512, SS, KVN, 0.125f);
        run_softmax(SS, PP, KVN, true);
        gemm_av(SS, Vp, (size_t)KVN * 512, ATT, KVN);
        gemm_proj(ATT, W3, TMP, 2048, 512, 512, nullptr, X, 0);
        ln_kernel<<<2048, 128>>>(TMP, ln1_g + i * 512, ln1_b + i * 512, A);

        // ---- compressed-memory reconstruction loss ----
        tconv_kernel<<<4096, 256>>>(conv_w + (size_t)i * 512 * 512 * 4, CWT);
        gemm_proj(mem, CWT, NCM, 512, 512, 2048, conv_b + i * 512);
        // batched QR: z=0 -> A@W0 (rattn), z=1 -> A@Ws0 (cross)
        gemm_batched(A, W0, QR, 2048, 512, 512, 512, 512, 512,
                     0, 0, 0, (size_t)(Ws0 - W0), 0, (size_t)(QR2 - QR),
                     2, 2, 1.f, nullptr, nullptr, 0);
        // target: K/V over old_mem = kv rows [128,640) (same weights)
        gemm_scores(QR, (size_t)512 * 512, Kp + 128 * 512, (size_t)KVN * 512, SS, 512, 0.125f);
        run_softmax(SS, nullptr, 512, false);
        gemm_av(SS, Vp + 128 * 512, (size_t)KVN * 512, TGT, 512);
        // rnew: K/V over NCM (z=2 over contiguous {W1,W2})
        gemm_batched(NCM, W1, KN, 512, 512, 512, 512, 512, 512,
                     0, 0, 0, 262144ull, 0, 262144ull, 2, 2, 1.f, nullptr, nullptr, 0);
        gemm_scores(QR, (size_t)512 * 512, KN, (size_t)128 * 512, SS, 128, 0.125f);
        run_softmax(SS, nullptr, 128, false);
        gemm_av(SS, VN, (size_t)128 * 512, RNEW, 128);
        loss_part_kernel<<<1024, 256>>>(RNEW, TGT, PART);
        loss_acc_kernel<<<1, 256>>>(PART, LOSS);

        // ---- cross-attention to latent (no residual) ----
        gemm_batched(latent, Ws1, KR, 1024, 512, 512, 512, 512, 512,
                     0, 0, 0, 262144ull, 0, (size_t)(VR - KR), 2, 2, 1.f, nullptr, nullptr, 0);
        gemm_scores(QR2, (size_t)512 * 512, KR, (size_t)256 * 512, SS, 256, 0.125f);
        run_softmax(SS, nullptr, 256, false);
        gemm_av(SS, VR, (size_t)256 * 512, TMP, 256);
        gemm_proj(TMP, Ws3, X1, 2048, 512, 512);

        // ---- FFN: x = x1 + gelu(LN(x1)@w1+b1)@w2 + b2 ----
        ln_kernel<<<2048, 128>>>(X1, ln2_g + i * 512, ln2_b + i * 512, Y);
        gemm_proj(Y,  w1 + (size_t)i * 512 * 2048, FF, 2048, 2048, 512,  b1 + (size_t)i * 2048, nullptr, 1);
        gemm_proj(FF, w2 + (size_t)i * 2048 * 512, X,  2048, 512,  2048, b2 + (size_t)i * 512,  X1,      0);
    }

    size_t nout = (size_t)out_size;
    out_kernel<<<(int)((nout + 255) / 256), 256>>>((float*)d_out, X, LOSS, nout);
}

// round 6
// speedup vs baseline: 2.1577x; 1.0003x over previous
#include <cuda_runtime.h>
#include <math.h>
#include <stdint.h>

#define NL 4
#define BB 4
#define DD 512
#define HH 8
#define KVN 1152

#define EL_X   1048576ull
#define EL_KV  2359296ull
#define EL_S   18874368ull   // 32 * 512 * 1152

constexpr size_t O_X    = 0;
constexpr size_t O_KV   = O_X    + EL_X;
constexpr size_t O_QKV  = O_KV   + EL_KV;          // 3 x [4608,512]
constexpr size_t O_ATT  = O_QKV  + 3ull * EL_KV;
constexpr size_t O_A    = O_ATT  + EL_X;
constexpr size_t O_TMP  = O_A    + EL_X;
constexpr size_t O_QR   = O_TMP  + EL_X;
constexpr size_t O_QR2  = O_QR   + EL_X;
constexpr size_t O_KR   = O_QR2  + EL_X;
constexpr size_t O_VR   = O_KR   + EL_X;
constexpr size_t O_KN   = O_VR   + EL_X;
constexpr size_t O_VN   = O_KN   + 262144ull;
constexpr size_t O_TGT  = O_VN   + 262144ull;
constexpr size_t O_RNEW = O_TGT  + EL_X;
constexpr size_t O_NCM  = O_RNEW + EL_X;
constexpr size_t O_CWT  = O_NCM  + 262144ull;
constexpr size_t O_FF   = O_CWT  + EL_X;
constexpr size_t O_Y    = O_FF   + 4194304ull;
constexpr size_t O_X1   = O_Y    + EL_X;
constexpr size_t O_PART = O_X1   + EL_X;
constexpr size_t O_LOSS = O_PART + 1024ull;
constexpr size_t O_S    = O_LOSS + 16ull;
constexpr size_t O_P    = O_S    + EL_S;
constexpr size_t SCRATCH_TOTAL = O_P + EL_S;

__device__ float g_scratch[SCRATCH_TOTAL];

__device__ __forceinline__ uint32_t f2tf32(float f) {
    uint32_t u;
    asm("cvt.rna.tf32.f32 %0, %1;" : "=r"(u) : "f"(f));
    return u;
}

__device__ __forceinline__ float block_red_sum(float v, float* sbuf, int nthreads) {
    int lane = threadIdx.x & 31, w = threadIdx.x >> 5;
    #pragma unroll
    for (int o = 16; o; o >>= 1) v += __shfl_xor_sync(0xffffffffu, v, o);
    __syncthreads();
    if (lane == 0) sbuf[w] = v;
    __syncthreads();
    int nw = nthreads >> 5;
    float r = 0.f;
    for (int i = 0; i < nw; i++) r += sbuf[i];
    return r;
}

__device__ __forceinline__ float block_red_max(float v, float* sbuf, int nthreads) {
    int lane = threadIdx.x & 31, w = threadIdx.x >> 5;
    #pragma unroll
    for (int o = 16; o; o >>= 1) v = fmaxf(v, __shfl_xor_sync(0xffffffffu, v, o));
    __syncthreads();
    if (lane == 0) sbuf[w] = v;
    __syncthreads();
    int nw = nthreads >> 5;
    float r = -1e30f;
    for (int i = 0; i < nw; i++) r = fmaxf(r, sbuf[i]);
    return r;
}

__global__ void zero_loss_kernel(float* loss) { if (threadIdx.x == 0) loss[0] = 0.f; }

__global__ void embed_kernel(const int* __restrict__ trg, const float* __restrict__ emb,
                             float* __restrict__ x) {
    size_t idx = (size_t)blockIdx.x * blockDim.x + threadIdx.x;
    if (idx >= EL_X) return;
    int row = (int)(idx >> 9);
    int d   = (int)(idx & 511);
    x[idx] = emb[(size_t)trg[row] * 512 + d];
}

__global__ void kv_kernel(const float* __restrict__ cm, const float* __restrict__ mem,
                          const float* __restrict__ x, float* __restrict__ kv) {
    size_t idx = (size_t)blockIdx.x * blockDim.x + threadIdx.x;
    if (idx >= EL_KV) return;
    int b   = (int)(idx / ((size_t)KVN * DD));
    int rem = (int)(idx - (size_t)b * KVN * DD);
    int p = rem >> 9, d = rem & 511;
    float val;
    if (p < 128)       val = cm [(size_t)b * 128 * 512 + ((size_t)p << 9) + d];
    else if (p < 640)  val = mem[(size_t)b * 512 * 512 + ((size_t)(p - 128) << 9) + d];
    else               val = x  [(size_t)b * 512 * 512 + ((size_t)(p - 640) << 9) + d];
    kv[idx] = val;
}

__global__ void tconv_kernel(const float* __restrict__ cw, float* __restrict__ cwt) {
    size_t idx = (size_t)blockIdx.x * blockDim.x + threadIdx.x;
    if (idx >= 2048ull * 512ull) return;
    int o = (int)(idx & 511);
    int k = (int)(idx >> 9);
    int d = k & 511;
    int r = k >> 9;
    cwt[idx] = cw[((size_t)o * 512 + d) * 4 + r];
}

__global__ void out_kernel(float* __restrict__ o, const float* __restrict__ x,
                           const float* __restrict__ loss, size_t nout) {
    size_t i = (size_t)blockIdx.x * blockDim.x + threadIdx.x;
    if (i >= nout) return;
    if (i < EL_X) o[i] = x[i];
    else          o[i] = loss[0] * (1.f / (1048576.f * 4.f));
}

__global__ void __launch_bounds__(128) ln_kernel(const float* __restrict__ in,
                                                 const float* __restrict__ g,
                                                 const float* __restrict__ bb,
                                                 float* __restrict__ out) {
    __shared__ float sbuf[8];
    const int row = blockIdx.x, tid = threadIdx.x;
    const size_t base = (size_t)row * 512 + (size_t)tid * 4;
    float4 v4 = *(const float4*)(in + base);
    float v[4] = {v4.x, v4.y, v4.z, v4.w};
    float s = v[0] + v[1] + v[2] + v[3];
    s = block_red_sum(s, sbuf, 128);
    float mu = s * (1.f / 512.f);
    float d2 = 0.f;
    #pragma unroll
    for (int j = 0; j < 4; j++) { float t = v[j] - mu; d2 += t * t; }
    d2 = block_red_sum(d2, sbuf, 128);
    float rs = rsqrtf(d2 * (1.f / 512.f) + 1e-5f);
    int c = tid * 4;
    float4 o;
    o.x = (v[0] - mu) * rs * g[c + 0] + bb[c + 0];
    o.y = (v[1] - mu) * rs * g[c + 1] + bb[c + 1];
    o.z = (v[2] - mu) * rs * g[c + 2] + bb[c + 2];
    o.w = (v[3] - mu) * rs * g[c + 3] + bb[c + 3];
    *(float4*)(out + base) = o;
}

__global__ void __launch_bounds__(256) loss_part_kernel(const float* __restrict__ a,
                                                        const float* __restrict__ b,
                                                        float* __restrict__ part) {
    __shared__ float sbuf[8];
    size_t base = (size_t)blockIdx.x * 1024 + (size_t)threadIdx.x * 4;
    float4 x = *(const float4*)(a + base);
    float4 y = *(const float4*)(b + base);
    float dx = x.x - y.x, dy = x.y - y.y, dz = x.z - y.z, dw = x.w - y.w;
    float s = dx * dx + dy * dy + dz * dz + dw * dw;
    s = block_red_sum(s, sbuf, 256);
    if (threadIdx.x == 0) part[blockIdx.x] = s;
}

__global__ void __launch_bounds__(256) loss_acc_kernel(const float* __restrict__ part,
                                                       float* __restrict__ loss) {
    __shared__ float sbuf[8];
    int tid = threadIdx.x;
    float s = part[tid] + part[tid + 256] + part[tid + 512] + part[tid + 768];
    s = block_red_sum(s, sbuf, 256);
    if (tid == 0) loss[0] += s;
}

// ---------------- generalized batched TF32 tensor-core GEMM ----------------
// C = alpha * A @ B (+bias)(+gelu)(+resid)
// A row-major [M,K] (row stride lda); B: BNM ? B[n][k] : B[k][n] (row stride ldb)
// batch z: offset(tensor) = (z/mod)*Outer + (z%mod)*Inner
// X3: 3xTF32 split (hi/lo) for ~fp32 accuracy.
// 8 warps as 2(m) x 4(n); warp tile = (TM/2) x (TN/4); MT=TM/32, NT=TN/32.
template<int TM, int TN, bool BNM, bool X3>
__global__ void __launch_bounds__(256) gmma_kernel(
    const float* __restrict__ A, const float* __restrict__ B, float* __restrict__ C,
    int M, int N, int K, int lda, int ldb, int ldc,
    size_t aO, size_t aI, size_t bO, size_t bI, size_t cO, size_t cI, int mod,
    float alpha, const float* __restrict__ bias,
    const float* __restrict__ resid, int act)
{
    constexpr int MT = TM / 32;
    constexpr int NT = TN / 32;
    constexpr int AVN = TM / 64;
    constexpr int BVN = TN / 64;
    __shared__ uint32_t AsH[TM][20];
    __shared__ uint32_t BsH[TN][20];
    __shared__ uint32_t AsL[X3 ? TM : 1][X3 ? 20 : 4];
    __shared__ uint32_t BsL[X3 ? TN : 1][X3 ? 20 : 4];

    const int z = blockIdx.z;
    const size_t aOff = (size_t)(z / mod) * aO + (size_t)(z % mod) * aI;
    const size_t bOff = (size_t)(z / mod) * bO + (size_t)(z % mod) * bI;
    const size_t cOff = (size_t)(z / mod) * cO + (size_t)(z % mod) * cI;
    const float* Ab = A + aOff;
    const float* Bb = B + bOff;
    float* Cb = C + cOff;

    const int tid = threadIdx.x;
    const int wid = tid >> 5, lane = tid & 31;
    const int wm = wid >> 2, wn = wid & 3;
    const int g = lane >> 2, tg = lane & 3;
    const int m0 = blockIdx.y * TM, n0 = blockIdx.x * TN;

    float acc[MT][NT][4];
    #pragma unroll
    for (int i = 0; i < MT; i++)
        #pragma unroll
        for (int j = 0; j < NT; j++)
            #pragma unroll
            for (int c = 0; c < 4; c++) acc[i][j][c] = 0.f;

    float4 pa[AVN], pb[BVN];
    #pragma unroll
    for (int v = 0; v < AVN; v++) {
        int idx4 = tid + v * 256;
        int row = idx4 >> 2, kg = (idx4 & 3) << 2;
        pa[v] = *(const float4*)(Ab + (size_t)(m0 + row) * lda + kg);
    }
    #pragma unroll
    for (int v = 0; v < BVN; v++) {
        int idx4 = tid + v * 256;
        if (BNM) {
            int row = idx4 >> 2, kg = (idx4 & 3) << 2;
            pb[v] = *(const float4*)(Bb + (size_t)(n0 + row) * ldb + kg);
        } else {
            int k = idx4 / (TN / 4), c = (idx4 % (TN / 4)) << 2;
            pb[v] = *(const float4*)(Bb + (size_t)k * ldb + n0 + c);
        }
    }

    for (int k0 = 0;; k0 += 16) {
        __syncthreads();
        #pragma unroll
        for (int v = 0; v < AVN; v++) {
            int idx4 = tid + v * 256;
            int row = idx4 >> 2, kg = (idx4 & 3) << 2;
            float f[4] = {pa[v].x, pa[v].y, pa[v].z, pa[v].w};
            #pragma unroll
            for (int j = 0; j < 4; j++) {
                uint32_t hi = f2tf32(f[j]);
                AsH[row][kg + j] = hi;
                if (X3) AsL[row][kg + j] = f2tf32(f[j] - __uint_as_float(hi));
            }
        }
        #pragma unroll
        for (int v = 0; v < BVN; v++) {
            int idx4 = tid + v * 256;
            float f[4] = {pb[v].x, pb[v].y, pb[v].z, pb[v].w};
            if (BNM) {
                int row = idx4 >> 2, kg = (idx4 & 3) << 2;
                #pragma unroll
                for (int j = 0; j < 4; j++) {
                    uint32_t hi = f2tf32(f[j]);
                    BsH[row][kg + j] = hi;
                    if (X3) BsL[row][kg + j] = f2tf32(f[j] - __uint_as_float(hi));
                }
            } else {
                int k = idx4 / (TN / 4), c = (idx4 % (TN / 4)) << 2;
                #pragma unroll
                for (int j = 0; j < 4; j++) {
                    uint32_t hi = f2tf32(f[j]);
                    BsH[c + j][k] = hi;
                    if (X3) BsL[c + j][k] = f2tf32(f[j] - __uint_as_float(hi));
                }
            }
        }
        __syncthreads();
        bool more = (k0 + 16 < K);
        if (more) {
            int kn = k0 + 16;
            #pragma unroll
            for (int v = 0; v < AVN; v++) {
                int idx4 = tid + v * 256;
                int row = idx4 >> 2, kg = (idx4 & 3) << 2;
                pa[v] = *(const float4*)(Ab + (size_t)(m0 + row) * lda + kn + kg);
            }
            #pragma unroll
            for (int v = 0; v < BVN; v++) {
                int idx4 = tid + v * 256;
                if (BNM) {
                    int row = idx4 >> 2, kg = (idx4 & 3) << 2;
                    pb[v] = *(const float4*)(Bb + (size_t)(n0 + row) * ldb + kn + kg);
                } else {
                    int k = idx4 / (TN / 4), c = (idx4 % (TN / 4)) << 2;
                    pb[v] = *(const float4*)(Bb + (size_t)(kn + k) * ldb + n0 + c);
                }
            }
        }
        #pragma unroll
        for (int kk = 0; kk < 16; kk += 8) {
            uint32_t afH[MT][4], bfH[NT][2];
            uint32_t afL[X3 ? MT : 1][4], bfL[X3 ? NT : 1][2];
            #pragma unroll
            for (int i = 0; i < MT; i++) {
                int r = wm * (TM / 2) + i * 16 + g;
                afH[i][0] = AsH[r][kk + tg];
                afH[i][1] = AsH[r + 8][kk + tg];
                afH[i][2] = AsH[r][kk + tg + 4];
                afH[i][3] = AsH[r + 8][kk + tg + 4];
                if (X3) {
                    afL[i][0] = AsL[r][kk + tg];
                    afL[i][1] = AsL[r + 8][kk + tg];
                    afL[i][2] = AsL[r][kk + tg + 4];
                    afL[i][3] = AsL[r + 8][kk + tg + 4];
                }
            }
            #pragma unroll
            for (int j = 0; j < NT; j++) {
                int n = wn * (TN / 4) + j * 8 + g;
                bfH[j][0] = BsH[n][kk + tg];
                bfH[j][1] = BsH[n][kk + tg + 4];
                if (X3) {
                    bfL[j][0] = BsL[n][kk + tg];
                    bfL[j][1] = BsL[n][kk + tg + 4];
                }
            }
            #pragma unroll
            for (int i = 0; i < MT; i++)
                #pragma unroll
                for (int j = 0; j < NT; j++) {
                    asm volatile(
                        "mma.sync.aligned.m16n8k8.row.col.f32.tf32.tf32.f32 "
                        "{%0,%1,%2,%3}, {%4,%5,%6,%7}, {%8,%9}, {%0,%1,%2,%3};\n"
                        : "+f"(acc[i][j][0]), "+f"(acc[i][j][1]),
                          "+f"(acc[i][j][2]), "+f"(acc[i][j][3])
                        : "r"(afH[i][0]), "r"(afH[i][1]), "r"(afH[i][2]), "r"(afH[i][3]),
                          "r"(bfH[j][0]), "r"(bfH[j][1]));
                    if (X3) {
                        asm volatile(
                            "mma.sync.aligned.m16n8k8.row.col.f32.tf32.tf32.f32 "
                            "{%0,%1,%2,%3}, {%4,%5,%6,%7}, {%8,%9}, {%0,%1,%2,%3};\n"
                            : "+f"(acc[i][j][0]), "+f"(acc[i][j][1]),
                              "+f"(acc[i][j][2]), "+f"(acc[i][j][3])
                            : "r"(afL[i][0]), "r"(afL[i][1]), "r"(afL[i][2]), "r"(afL[i][3]),
                              "r"(bfH[j][0]), "r"(bfH[j][1]));
                        asm volatile(
                            "mma.sync.aligned.m16n8k8.row.col.f32.tf32.tf32.f32 "
                            "{%0,%1,%2,%3}, {%4,%5,%6,%7}, {%8,%9}, {%0,%1,%2,%3};\n"
                            : "+f"(acc[i][j][0]), "+f"(acc[i][j][1]),
                              "+f"(acc[i][j][2]), "+f"(acc[i][j][3])
                            : "r"(afH[i][0]), "r"(afH[i][1]), "r"(afH[i][2]), "r"(afH[i][3]),
                              "r"(bfL[j][0]), "r"(bfL[j][1]));
                    }
                }
        }
        if (!more) break;
    }

    #pragma unroll
    for (int i = 0; i < MT; i++) {
        int m = m0 + wm * (TM / 2) + i * 16 + g;
        #pragma unroll
        for (int j = 0; j < NT; j++) {
            int n = n0 + wn * (TN / 4) + j * 8 + 2 * tg;
            float c0 = acc[i][j][0] * alpha, c1 = acc[i][j][1] * alpha;
            float c2 = acc[i][j][2] * alpha, c3 = acc[i][j][3] * alpha;
            if (bias) {
                float b0 = bias[n], b1 = bias[n + 1];
                c0 += b0; c1 += b1; c2 += b0; c3 += b1;
            }
            if (act) {
                c0 = 0.5f * c0 * (1.f + erff(c0 * 0.7071067811865475f));
                c1 = 0.5f * c1 * (1.f + erff(c1 * 0.7071067811865475f));
                c2 = 0.5f * c2 * (1.f + erff(c2 * 0.7071067811865475f));
                c3 = 0.5f * c3 * (1.f + erff(c3 * 0.7071067811865475f));
            }
            if (resid) {
                const float* Rb = resid + cOff;
                c0 += Rb[(size_t)m * ldc + n];
                c1 += Rb[(size_t)m * ldc + n + 1];
                c2 += Rb[(size_t)(m + 8) * ldc + n];
                c3 += Rb[(size_t)(m + 8) * ldc + n + 1];
            }
            float2 lo = {c0, c1}, hi = {c2, c3};
            *(float2*)(Cb + (size_t)m * ldc + n) = lo;
            *(float2*)(Cb + (size_t)(m + 8) * ldc + n) = hi;
        }
    }
}

// ---------------- softmax with optional fused shift()+pos add ----------------
template<bool POS>
__global__ void __launch_bounds__(128) softmax_kernel(float* __restrict__ S,
                                                      const float* __restrict__ P,
                                                      int klen) {
    __shared__ float sbuf[4];
    const int i = blockIdx.x, z = blockIdx.y, tid = threadIdx.x;
    float* row = S + ((size_t)z * 512 + i) * klen;
    const float* prow = POS ? (P + ((size_t)z * 512 + i) * KVN) : nullptr;
    float mx = -1e30f;
    for (int j = tid; j < klen; j += 128) {
        float v = row[j];
        if (POS) {
            int r = j + 511 - i;
            if (r < KVN) v += prow[r];
        }
        row[j] = v;
        mx = fmaxf(mx, v);
    }
    mx = block_red_max(mx, sbuf, 128);
    float sum = 0.f;
    for (int j = tid; j < klen; j += 128) {
        float e = expf(row[j] - mx);
        row[j] = e;
        sum += e;
    }
    sum = block_red_sum(sum, sbuf, 128);
    float inv = 1.f / sum;
    for (int j = tid; j < klen; j += 128) row[j] *= inv;
}

// ---------------- host wrappers ----------------
static void gemm_batched(const float* A, const float* B, float* C, int M, int N, int K,
                         int lda, int ldb, int ldc,
                         size_t aO, size_t aI, size_t bO, size_t bI, size_t cO, size_t cI,
                         int mod, int z, float alpha,
                         const float* bias, const float* resid, int act) {
    if ((M % 128 == 0) && (N % 128 == 0) && (size_t)(M / 128) * (N / 128) * z >= 120) {
        dim3 grid(N / 128, M / 128, z);
        gmma_kernel<128, 128, false, false><<<grid, 256>>>(A, B, C, M, N, K, lda, ldb, ldc,
            aO, aI, bO, bI, cO, cI, mod, alpha, bias, resid, act);
    } else if ((M % 128 == 0) && (N % 64 == 0) && (size_t)(M / 128) * (N / 64) * z >= 120) {
        dim3 grid(N / 64, M / 128, z);
        gmma_kernel<128, 64, false, false><<<grid, 256>>>(A, B, C, M, N, K, lda, ldb, ldc,
            aO, aI, bO, bI, cO, cI, mod, alpha, bias, resid, act);
    } else {
        dim3 grid(N / 64, M / 64, z);
        gmma_kernel<64, 64, false, false><<<grid, 256>>>(A, B, C, M, N, K, lda, ldb, ldc,
            aO, aI, bO, bI, cO, cI, mod, alpha, bias, resid, act);
    }
}

static void gemm_proj(const float* A, const float* B, float* C, int M, int N, int K,
                      const float* bias = nullptr, const float* resid = nullptr, int act = 0) {
    gemm_batched(A, B, C, M, N, K, K, N, N, 0, 0, 0, 0, 0, 0, 1, 1, 1.f, bias, resid, act);
}

// S[z][512][klen] = alpha * Q_h @ K_h^T ; z = b*8+h
static void gemm_scores(const float* q, size_t qOuter, const float* kbase, size_t kOuter,
                        float* Sb, int klen, float alpha) {
    dim3 grid(klen / 64, 512 / 128, 32);
    gmma_kernel<128, 64, true, true><<<grid, 256>>>(q, kbase, Sb, 512, klen, 64,
        512, 512, klen,
        qOuter, 64, kOuter, 64, (size_t)8 * 512 * klen, (size_t)512 * klen, 8,
        alpha, nullptr, nullptr, 0);
}

// P[z][512][1152] = 8 * Q_h @ pos[h]^T
static void gemm_pos(const float* q, size_t qOuter, const float* pos, float* Pb) {
    dim3 grid(KVN / 64, 512 / 128, 32);
    gmma_kernel<128, 64, true, true><<<grid, 256>>>(q, pos, Pb, 512, KVN, 64,
        512, 64, KVN,
        qOuter, 64, 0, (size_t)KVN * 64, (size_t)8 * 512 * KVN, (size_t)512 * KVN, 8,
        8.f, nullptr, nullptr, 0);
}

// out[b][i][h*64+d] = S_z @ V_h
static void gemm_av(const float* Sb, const float* vbase, size_t vOuter, float* out, int klen) {
    dim3 grid(1, 512 / 128, 32);
    gmma_kernel<128, 64, false, true><<<grid, 256>>>(Sb, vbase, out, 512, 64, klen,
        klen, 512, 512,
        (size_t)8 * 512 * klen, (size_t)512 * klen, vOuter, 64, (size_t)512 * 512, 64, 8,
        1.f, nullptr, nullptr, 0);
}

static void run_softmax(float* Sb, const float* Pb, int klen, bool pos) {
    dim3 grid(512, 32);
    if (pos) softmax_kernel<true><<<grid, 128>>>(Sb, Pb, klen);
    else     softmax_kernel<false><<<grid, 128>>>(Sb, nullptr, klen);
}

extern "C" void kernel_launch(void* const* d_in, const int* in_sizes, int n_in,
                              void* d_out, int out_size) {
    const int*   trg     = (const int*)  d_in[0];
    const float* latent  = (const float*)d_in[3];
    const float* mems    = (const float*)d_in[4];
    const float* cmems   = (const float*)d_in[5];
    const float* pos_emb = (const float*)d_in[6];
    const float* embed   = (const float*)d_in[7];
    const float* W_self  = (const float*)d_in[8];
    const float* ln1_g   = (const float*)d_in[9];
    const float* ln1_b   = (const float*)d_in[10];
    const float* conv_w  = (const float*)d_in[11];
    const float* conv_b  = (const float*)d_in[12];
    const float* W_src   = (const float*)d_in[13];
    const float* ln2_g   = (const float*)d_in[14];
    const float* ln2_b   = (const float*)d_in[15];
    const float* w1      = (const float*)d_in[16];
    const float* b1      = (const float*)d_in[17];
    const float* w2      = (const float*)d_in[18];
    const float* b2      = (const float*)d_in[19];

    float* Sc;
    cudaGetSymbolAddress((void**)&Sc, g_scratch);
    float* X    = Sc + O_X;
    float* KVb  = Sc + O_KV;
    float* QKV  = Sc + O_QKV;           // Q slab [4608,512]
    float* Kp   = QKV + EL_KV;          // K slab
    float* Vp   = QKV + 2 * EL_KV;      // V slab
    float* ATT  = Sc + O_ATT;
    float* A    = Sc + O_A;
    float* TMP  = Sc + O_TMP;
    float* QR   = Sc + O_QR;
    float* QR2  = Sc + O_QR2;
    float* KR   = Sc + O_KR;
    float* VR   = Sc + O_VR;
    float* KN   = Sc + O_KN;
    float* VN   = Sc + O_VN;
    float* TGT  = Sc + O_TGT;
    float* RNEW = Sc + O_RNEW;
    float* NCM  = Sc + O_NCM;
    float* CWT  = Sc + O_CWT;
    float* FF   = Sc + O_FF;
    float* Y    = Sc + O_Y;
    float* X1   = Sc + O_X1;
    float* PART = Sc + O_PART;
    float* LOSS = Sc + O_LOSS;
    float* SS   = Sc + O_S;
    float* PP   = Sc + O_P;

    zero_loss_kernel<<<1, 32>>>(LOSS);
    embed_kernel<<<(int)(EL_X / 256), 256>>>(trg, embed, X);

    for (int i = 0; i < NL; i++) {
        const float* mem = mems  + (size_t)i * BB * 512 * 512;
        const float* cm  = cmems + (size_t)i * BB * 128 * 512;
        const float* W0 = W_self + ((size_t)i * 4 + 0) * 512 * 512;
        const float* W1 = W_self + ((size_t)i * 4 + 1) * 512 * 512;
        const float* Ws0 = W_src + ((size_t)i * 4 + 0) * 512 * 512;
        const float* Ws1 = W_src + ((size_t)i * 4 + 1) * 512 * 512;
        const float* Ws3 = W_src + ((size_t)i * 4 + 3) * 512 * 512;
        const float* W3  = W_self + ((size_t)i * 4 + 3) * 512 * 512;

        // ---- self-attention over kv = [cmem, mem, x] ----
        kv_kernel<<<(int)(EL_KV / 256), 256>>>(cm, mem, X, KVb);
        // fused QKV: z=3 over contiguous weights {W0,W1,W2}; Q slab covers ALL kv rows,
        // the x-rows (640..1151 per batch) are the real queries.
        gemm_batched(KVb, W0, QKV, 4608, 512, 512, 512, 512, 512,
                     0, 0, 0, 262144ull, 0, EL_KV, 3, 3, 1.f, nullptr, nullptr, 0);
        const float* Qx = QKV + 640ull * 512;   // Q rows of x, aO = 1152*512 per batch
        gemm_pos(Qx, (size_t)KVN * 512, pos_emb, PP);
        gemm_scores(Qx, (size_t)KVN * 512, Kp, (size_t)KVN * 512, SS, KVN, 0.125f);
        run_softmax(SS, PP, KVN, true);
        gemm_av(SS, Vp, (size_t)KVN * 512, ATT, KVN);
        gemm_proj(ATT, W3, TMP, 2048, 512, 512, nullptr, X, 0);
        ln_kernel<<<2048, 128>>>(TMP, ln1_g + i * 512, ln1_b + i * 512, A);

        // ---- compressed-memory reconstruction loss ----
        tconv_kernel<<<4096, 256>>>(conv_w + (size_t)i * 512 * 512 * 4, CWT);
        gemm_proj(mem, CWT, NCM, 512, 512, 2048, conv_b + i * 512);
        // batched QR: z=0 -> A@W0 (rattn), z=1 -> A@Ws0 (cross)
        gemm_batched(A, W0, QR, 2048, 512, 512, 512, 512, 512,
                     0, 0, 0, (size_t)(Ws0 - W0), 0, (size_t)(QR2 - QR),
                     2, 2, 1.f, nullptr, nullptr, 0);
        // target: K/V over old_mem = kv rows [128,640) (same weights)
        gemm_scores(QR, (size_t)512 * 512, Kp + 128 * 512, (size_t)KVN * 512, SS, 512, 0.125f);
        run_softmax(SS, nullptr, 512, false);
        gemm_av(SS, Vp + 128 * 512, (size_t)KVN * 512, TGT, 512);
        // rnew: K/V over NCM (z=2 over contiguous {W1,W2})
        gemm_batched(NCM, W1, KN, 512, 512, 512, 512, 512, 512,
                     0, 0, 0, 262144ull, 0, 262144ull, 2, 2, 1.f, nullptr, nullptr, 0);
        gemm_scores(QR, (size_t)512 * 512, KN, (size_t)128 * 512, SS, 128, 0.125f);
        run_softmax(SS, nullptr, 128, false);
        gemm_av(SS, VN, (size_t)128 * 512, RNEW, 128);
        loss_part_kernel<<<1024, 256>>>(RNEW, TGT, PART);
        loss_acc_kernel<<<1, 256>>>(PART, LOSS);

        // ---- cross-attention to latent (no residual) ----
        gemm_batched(latent, Ws1, KR, 1024, 512, 512, 512, 512, 512,
                     0, 0, 0, 262144ull, 0, (size_t)(VR - KR), 2, 2, 1.f, nullptr, nullptr, 0);
        gemm_scores(QR2, (size_t)512 * 512, KR, (size_t)256 * 512, SS, 256, 0.125f);
        run_softmax(SS, nullptr, 256, false);
        gemm_av(SS, VR, (size_t)256 * 512, TMP, 256);
        gemm_proj(TMP, Ws3, X1, 2048, 512, 512);

        // ---- FFN: x = x1 + gelu(LN(x1)@w1+b1)@w2 + b2 ----
        ln_kernel<<<2048, 128>>>(X1, ln2_g + i * 512, ln2_b + i * 512, Y);
        gemm_proj(Y,  w1 + (size_t)i * 512 * 2048, FF, 2048, 2048, 512,  b1 + (size_t)i * 2048, nullptr, 1);
        gemm_proj(FF, w2 + (size_t)i * 2048 * 512, X,  2048, 512,  2048, b2 + (size_t)i * 512,  X1,      0);
    }

    size_t nout = (size_t)out_size;
    out_kernel<<<(int)((nout + 255) / 256), 256>>>((float*)d_out, X, LOSS, nout);
}

// round 7
// speedup vs baseline: 2.1712x; 1.0063x over previous
#include <cuda_runtime.h>
#include <math.h>
#include <stdint.h>

#define NL 4
#define BB 4
#define DD 512
#define HH 8
#define KVN 1152

#define EL_X   1048576ull
#define EL_KV  2359296ull
#define EL_S   18874368ull   // 32 * 512 * 1152

constexpr size_t O_X    = 0;
constexpr size_t O_KV   = O_X    + EL_X;
constexpr size_t O_QKV  = O_KV   + EL_KV;          // 3 x [4608,512]
constexpr size_t O_ATT  = O_QKV  + 3ull * EL_KV;
constexpr size_t O_A    = O_ATT  + EL_X;
constexpr size_t O_TMP  = O_A    + EL_X;
constexpr size_t O_QR   = O_TMP  + EL_X;
constexpr size_t O_QR2  = O_QR   + EL_X;
constexpr size_t O_KR   = O_QR2  + EL_X;
constexpr size_t O_VR   = O_KR   + EL_X;
constexpr size_t O_KN   = O_VR   + EL_X;
constexpr size_t O_VN   = O_KN   + 262144ull;
constexpr size_t O_TGT  = O_VN   + 262144ull;
constexpr size_t O_RNEW = O_TGT  + EL_X;
constexpr size_t O_NCM  = O_RNEW + EL_X;
constexpr size_t O_CWT  = O_NCM  + 262144ull;
constexpr size_t O_FF   = O_CWT  + EL_X;
constexpr size_t O_Y    = O_FF   + 4194304ull;
constexpr size_t O_X1   = O_Y    + EL_X;
constexpr size_t O_PART = O_X1   + EL_X;
constexpr size_t O_LOSS = O_PART + 1024ull;
constexpr size_t O_S    = O_LOSS + 16ull;
constexpr size_t O_P    = O_S    + EL_S;
constexpr size_t SCRATCH_TOTAL = O_P + EL_S;

__device__ float g_scratch[SCRATCH_TOTAL];

__device__ __forceinline__ uint32_t f2tf32(float f) {
    uint32_t u;
    asm("cvt.rna.tf32.f32 %0, %1;" : "=r"(u) : "f"(f));
    return u;
}

__device__ __forceinline__ float block_red_sum(float v, float* sbuf, int nthreads) {
    int lane = threadIdx.x & 31, w = threadIdx.x >> 5;
    #pragma unroll
    for (int o = 16; o; o >>= 1) v += __shfl_xor_sync(0xffffffffu, v, o);
    __syncthreads();
    if (lane == 0) sbuf[w] = v;
    __syncthreads();
    int nw = nthreads >> 5;
    float r = 0.f;
    for (int i = 0; i < nw; i++) r += sbuf[i];
    return r;
}

__device__ __forceinline__ float block_red_max(float v, float* sbuf, int nthreads) {
    int lane = threadIdx.x & 31, w = threadIdx.x >> 5;
    #pragma unroll
    for (int o = 16; o; o >>= 1) v = fmaxf(v, __shfl_xor_sync(0xffffffffu, v, o));
    __syncthreads();
    if (lane == 0) sbuf[w] = v;
    __syncthreads();
    int nw = nthreads >> 5;
    float r = -1e30f;
    for (int i = 0; i < nw; i++) r = fmaxf(r, sbuf[i]);
    return r;
}

__global__ void zero_loss_kernel(float* loss) { if (threadIdx.x == 0) loss[0] = 0.f; }

__global__ void embed_kernel(const int* __restrict__ trg, const float* __restrict__ emb,
                             float* __restrict__ x) {
    size_t idx = (size_t)blockIdx.x * blockDim.x + threadIdx.x;
    if (idx >= EL_X) return;
    int row = (int)(idx >> 9);
    int d   = (int)(idx & 511);
    x[idx] = emb[(size_t)trg[row] * 512 + d];
}

__global__ void kv_kernel(const float* __restrict__ cm, const float* __restrict__ mem,
                          const float* __restrict__ x, float* __restrict__ kv) {
    size_t idx = (size_t)blockIdx.x * blockDim.x + threadIdx.x;
    if (idx >= EL_KV) return;
    int b   = (int)(idx / ((size_t)KVN * DD));
    int rem = (int)(idx - (size_t)b * KVN * DD);
    int p = rem >> 9, d = rem & 511;
    float val;
    if (p < 128)       val = cm [(size_t)b * 128 * 512 + ((size_t)p << 9) + d];
    else if (p < 640)  val = mem[(size_t)b * 512 * 512 + ((size_t)(p - 128) << 9) + d];
    else               val = x  [(size_t)b * 512 * 512 + ((size_t)(p - 640) << 9) + d];
    kv[idx] = val;
}

__global__ void tconv_kernel(const float* __restrict__ cw, float* __restrict__ cwt) {
    size_t idx = (size_t)blockIdx.x * blockDim.x + threadIdx.x;
    if (idx >= 2048ull * 512ull) return;
    int o = (int)(idx & 511);
    int k = (int)(idx >> 9);
    int d = k & 511;
    int r = k >> 9;
    cwt[idx] = cw[((size_t)o * 512 + d) * 4 + r];
}

__global__ void out_kernel(float* __restrict__ o, const float* __restrict__ x,
                           const float* __restrict__ loss, size_t nout) {
    size_t i = (size_t)blockIdx.x * blockDim.x + threadIdx.x;
    if (i >= nout) return;
    if (i < EL_X) o[i] = x[i];
    else          o[i] = loss[0] * (1.f / (1048576.f * 4.f));
}

__global__ void __launch_bounds__(128) ln_kernel(const float* __restrict__ in,
                                                 const float* __restrict__ g,
                                                 const float* __restrict__ bb,
                                                 float* __restrict__ out) {
    __shared__ float sbuf[8];
    const int row = blockIdx.x, tid = threadIdx.x;
    const size_t base = (size_t)row * 512 + (size_t)tid * 4;
    float4 v4 = *(const float4*)(in + base);
    float v[4] = {v4.x, v4.y, v4.z, v4.w};
    float s = v[0] + v[1] + v[2] + v[3];
    s = block_red_sum(s, sbuf, 128);
    float mu = s * (1.f / 512.f);
    float d2 = 0.f;
    #pragma unroll
    for (int j = 0; j < 4; j++) { float t = v[j] - mu; d2 += t * t; }
    d2 = block_red_sum(d2, sbuf, 128);
    float rs = rsqrtf(d2 * (1.f / 512.f) + 1e-5f);
    int c = tid * 4;
    float4 o;
    o.x = (v[0] - mu) * rs * g[c + 0] + bb[c + 0];
    o.y = (v[1] - mu) * rs * g[c + 1] + bb[c + 1];
    o.z = (v[2] - mu) * rs * g[c + 2] + bb[c + 2];
    o.w = (v[3] - mu) * rs * g[c + 3] + bb[c + 3];
    *(float4*)(out + base) = o;
}

__global__ void __launch_bounds__(256) loss_part_kernel(const float* __restrict__ a,
                                                        const float* __restrict__ b,
                                                        float* __restrict__ part) {
    __shared__ float sbuf[8];
    size_t base = (size_t)blockIdx.x * 1024 + (size_t)threadIdx.x * 4;
    float4 x = *(const float4*)(a + base);
    float4 y = *(const float4*)(b + base);
    float dx = x.x - y.x, dy = x.y - y.y, dz = x.z - y.z, dw = x.w - y.w;
    float s = dx * dx + dy * dy + dz * dz + dw * dw;
    s = block_red_sum(s, sbuf, 256);
    if (threadIdx.x == 0) part[blockIdx.x] = s;
}

__global__ void __launch_bounds__(256) loss_acc_kernel(const float* __restrict__ part,
                                                       float* __restrict__ loss) {
    __shared__ float sbuf[8];
    int tid = threadIdx.x;
    float s = part[tid] + part[tid + 256] + part[tid + 512] + part[tid + 768];
    s = block_red_sum(s, sbuf, 256);
    if (tid == 0) loss[0] += s;
}

// ---------------- generalized batched TF32 tensor-core GEMM ----------------
// C = alpha * A @ B (+bias)(+gelu)(+resid)
// A row-major [M,K] (row stride lda); B: BNM ? B[n][k] : B[k][n] (row stride ldb)
// batch z: offset(tensor) = (z/mod)*Outer + (z%mod)*Inner
// X3: 3xTF32 split (hi/lo) for ~fp32 accuracy.
// 8 warps as 2(m) x 4(n); warp tile = (TM/2) x (TN/4); MT=TM/32, NT=TN/32.
template<int TM, int TN, bool BNM, bool X3>
__global__ void __launch_bounds__(256) gmma_kernel(
    const float* __restrict__ A, const float* __restrict__ B, float* __restrict__ C,
    int M, int N, int K, int lda, int ldb, int ldc,
    size_t aO, size_t aI, size_t bO, size_t bI, size_t cO, size_t cI, int mod,
    float alpha, const float* __restrict__ bias,
    const float* __restrict__ resid, int act)
{
    constexpr int MT = TM / 32;
    constexpr int NT = TN / 32;
    constexpr int AVN = TM / 64;
    constexpr int BVN = TN / 64;
    __shared__ uint32_t AsH[TM][20];
    __shared__ uint32_t BsH[TN][20];
    __shared__ uint32_t AsL[X3 ? TM : 1][X3 ? 20 : 4];
    __shared__ uint32_t BsL[X3 ? TN : 1][X3 ? 20 : 4];

    const int z = blockIdx.z;
    const size_t aOff = (size_t)(z / mod) * aO + (size_t)(z % mod) * aI;
    const size_t bOff = (size_t)(z / mod) * bO + (size_t)(z % mod) * bI;
    const size_t cOff = (size_t)(z / mod) * cO + (size_t)(z % mod) * cI;
    const float* Ab = A + aOff;
    const float* Bb = B + bOff;
    float* Cb = C + cOff;

    const int tid = threadIdx.x;
    const int wid = tid >> 5, lane = tid & 31;
    const int wm = wid >> 2, wn = wid & 3;
    const int g = lane >> 2, tg = lane & 3;
    const int m0 = blockIdx.y * TM, n0 = blockIdx.x * TN;

    float acc[MT][NT][4];
    #pragma unroll
    for (int i = 0; i < MT; i++)
        #pragma unroll
        for (int j = 0; j < NT; j++)
            #pragma unroll
            for (int c = 0; c < 4; c++) acc[i][j][c] = 0.f;

    float4 pa[AVN], pb[BVN];
    #pragma unroll
    for (int v = 0; v < AVN; v++) {
        int idx4 = tid + v * 256;
        int row = idx4 >> 2, kg = (idx4 & 3) << 2;
        pa[v] = *(const float4*)(Ab + (size_t)(m0 + row) * lda + kg);
    }
    #pragma unroll
    for (int v = 0; v < BVN; v++) {
        int idx4 = tid + v * 256;
        if (BNM) {
            int row = idx4 >> 2, kg = (idx4 & 3) << 2;
            pb[v] = *(const float4*)(Bb + (size_t)(n0 + row) * ldb + kg);
        } else {
            int k = idx4 / (TN / 4), c = (idx4 % (TN / 4)) << 2;
            pb[v] = *(const float4*)(Bb + (size_t)k * ldb + n0 + c);
        }
    }

    for (int k0 = 0;; k0 += 16) {
        __syncthreads();
        #pragma unroll
        for (int v = 0; v < AVN; v++) {
            int idx4 = tid + v * 256;
            int row = idx4 >> 2, kg = (idx4 & 3) << 2;
            float f[4] = {pa[v].x, pa[v].y, pa[v].z, pa[v].w};
            #pragma unroll
            for (int j = 0; j < 4; j++) {
                uint32_t hi = f2tf32(f[j]);
                AsH[row][kg + j] = hi;
                if (X3) AsL[row][kg + j] = f2tf32(f[j] - __uint_as_float(hi));
            }
        }
        #pragma unroll
        for (int v = 0; v < BVN; v++) {
            int idx4 = tid + v * 256;
            float f[4] = {pb[v].x, pb[v].y, pb[v].z, pb[v].w};
            if (BNM) {
                int row = idx4 >> 2, kg = (idx4 & 3) << 2;
                #pragma unroll
                for (int j = 0; j < 4; j++) {
                    uint32_t hi = f2tf32(f[j]);
                    BsH[row][kg + j] = hi;
                    if (X3) BsL[row][kg + j] = f2tf32(f[j] - __uint_as_float(hi));
                }
            } else {
                int k = idx4 / (TN / 4), c = (idx4 % (TN / 4)) << 2;
                #pragma unroll
                for (int j = 0; j < 4; j++) {
                    uint32_t hi = f2tf32(f[j]);
                    BsH[c + j][k] = hi;
                    if (X3) BsL[c + j][k] = f2tf32(f[j] - __uint_as_float(hi));
                }
            }
        }
        __syncthreads();
        bool more = (k0 + 16 < K);
        if (more) {
            int kn = k0 + 16;
            #pragma unroll
            for (int v = 0; v < AVN; v++) {
                int idx4 = tid + v * 256;
                int row = idx4 >> 2, kg = (idx4 & 3) << 2;
                pa[v] = *(const float4*)(Ab + (size_t)(m0 + row) * lda + kn + kg);
            }
            #pragma unroll
            for (int v = 0; v < BVN; v++) {
                int idx4 = tid + v * 256;
                if (BNM) {
                    int row = idx4 >> 2, kg = (idx4 & 3) << 2;
                    pb[v] = *(const float4*)(Bb + (size_t)(n0 + row) * ldb + kn + kg);
                } else {
                    int k = idx4 / (TN / 4), c = (idx4 % (TN / 4)) << 2;
                    pb[v] = *(const float4*)(Bb + (size_t)(kn + k) * ldb + n0 + c);
                }
            }
        }
        #pragma unroll
        for (int kk = 0; kk < 16; kk += 8) {
            uint32_t afH[MT][4], bfH[NT][2];
            uint32_t afL[X3 ? MT : 1][4], bfL[X3 ? NT : 1][2];
            #pragma unroll
            for (int i = 0; i < MT; i++) {
                int r = wm * (TM / 2) + i * 16 + g;
                afH[i][0] = AsH[r][kk + tg];
                afH[i][1] = AsH[r + 8][kk + tg];
                afH[i][2] = AsH[r][kk + tg + 4];
                afH[i][3] = AsH[r + 8][kk + tg + 4];
                if (X3) {
                    afL[i][0] = AsL[r][kk + tg];
                    afL[i][1] = AsL[r + 8][kk + tg];
                    afL[i][2] = AsL[r][kk + tg + 4];
                    afL[i][3] = AsL[r + 8][kk + tg + 4];
                }
            }
            #pragma unroll
            for (int j = 0; j < NT; j++) {
                int n = wn * (TN / 4) + j * 8 + g;
                bfH[j][0] = BsH[n][kk + tg];
                bfH[j][1] = BsH[n][kk + tg + 4];
                if (X3) {
                    bfL[j][0] = BsL[n][kk + tg];
                    bfL[j][1] = BsL[n][kk + tg + 4];
                }
            }
            #pragma unroll
            for (int i = 0; i < MT; i++)
                #pragma unroll
                for (int j = 0; j < NT; j++) {
                    asm volatile(
                        "mma.sync.aligned.m16n8k8.row.col.f32.tf32.tf32.f32 "
                        "{%0,%1,%2,%3}, {%4,%5,%6,%7}, {%8,%9}, {%0,%1,%2,%3};\n"
                        : "+f"(acc[i][j][0]), "+f"(acc[i][j][1]),
                          "+f"(acc[i][j][2]), "+f"(acc[i][j][3])
                        : "r"(afH[i][0]), "r"(afH[i][1]), "r"(afH[i][2]), "r"(afH[i][3]),
                          "r"(bfH[j][0]), "r"(bfH[j][1]));
                    if (X3) {
                        asm volatile(
                            "mma.sync.aligned.m16n8k8.row.col.f32.tf32.tf32.f32 "
                            "{%0,%1,%2,%3}, {%4,%5,%6,%7}, {%8,%9}, {%0,%1,%2,%3};\n"
                            : "+f"(acc[i][j][0]), "+f"(acc[i][j][1]),
                              "+f"(acc[i][j][2]), "+f"(acc[i][j][3])
                            : "r"(afL[i][0]), "r"(afL[i][1]), "r"(afL[i][2]), "r"(afL[i][3]),
                              "r"(bfH[j][0]), "r"(bfH[j][1]));
                        asm volatile(
                            "mma.sync.aligned.m16n8k8.row.col.f32.tf32.tf32.f32 "
                            "{%0,%1,%2,%3}, {%4,%5,%6,%7}, {%8,%9}, {%0,%1,%2,%3};\n"
                            : "+f"(acc[i][j][0]), "+f"(acc[i][j][1]),
                              "+f"(acc[i][j][2]), "+f"(acc[i][j][3])
                            : "r"(afH[i][0]), "r"(afH[i][1]), "r"(afH[i][2]), "r"(afH[i][3]),
                              "r"(bfL[j][0]), "r"(bfL[j][1]));
                    }
                }
        }
        if (!more) break;
    }

    #pragma unroll
    for (int i = 0; i < MT; i++) {
        int m = m0 + wm * (TM / 2) + i * 16 + g;
        #pragma unroll
        for (int j = 0; j < NT; j++) {
            int n = n0 + wn * (TN / 4) + j * 8 + 2 * tg;
            float c0 = acc[i][j][0] * alpha, c1 = acc[i][j][1] * alpha;
            float c2 = acc[i][j][2] * alpha, c3 = acc[i][j][3] * alpha;
            if (bias) {
                float b0 = bias[n], b1 = bias[n + 1];
                c0 += b0; c1 += b1; c2 += b0; c3 += b1;
            }
            if (act) {
                c0 = 0.5f * c0 * (1.f + erff(c0 * 0.7071067811865475f));
                c1 = 0.5f * c1 * (1.f + erff(c1 * 0.7071067811865475f));
                c2 = 0.5f * c2 * (1.f + erff(c2 * 0.7071067811865475f));
                c3 = 0.5f * c3 * (1.f + erff(c3 * 0.7071067811865475f));
            }
            if (resid) {
                const float* Rb = resid + cOff;
                c0 += Rb[(size_t)m * ldc + n];
                c1 += Rb[(size_t)m * ldc + n + 1];
                c2 += Rb[(size_t)(m + 8) * ldc + n];
                c3 += Rb[(size_t)(m + 8) * ldc + n + 1];
            }
            float2 lo = {c0, c1}, hi = {c2, c3};
            *(float2*)(Cb + (size_t)m * ldc + n) = lo;
            *(float2*)(Cb + (size_t)(m + 8) * ldc + n) = hi;
        }
    }
}

// ---------------- softmax with optional fused shift()+pos add ----------------
template<bool POS>
__global__ void __launch_bounds__(128) softmax_kernel(float* __restrict__ S,
                                                      const float* __restrict__ P,
                                                      int klen) {
    __shared__ float sbuf[4];
    const int i = blockIdx.x, z = blockIdx.y, tid = threadIdx.x;
    float* row = S + ((size_t)z * 512 + i) * klen;
    const float* prow = POS ? (P + ((size_t)z * 512 + i) * KVN) : nullptr;
    float mx = -1e30f;
    for (int j = tid; j < klen; j += 128) {
        float v = row[j];
        if (POS) {
            int r = j + 511 - i;
            if (r < KVN) v += prow[r];
        }
        row[j] = v;
        mx = fmaxf(mx, v);
    }
    mx = block_red_max(mx, sbuf, 128);
    float sum = 0.f;
    for (int j = tid; j < klen; j += 128) {
        float e = expf(row[j] - mx);
        row[j] = e;
        sum += e;
    }
    sum = block_red_sum(sum, sbuf, 128);
    float inv = 1.f / sum;
    for (int j = tid; j < klen; j += 128) row[j] *= inv;
}

// ---------------- host wrappers ----------------
static void gemm_batched(const float* A, const float* B, float* C, int M, int N, int K,
                         int lda, int ldb, int ldc,
                         size_t aO, size_t aI, size_t bO, size_t bI, size_t cO, size_t cI,
                         int mod, int z, float alpha,
                         const float* bias, const float* resid, int act) {
    if ((M % 128 == 0) && (N % 128 == 0) && (size_t)(M / 128) * (N / 128) * z >= 120) {
        dim3 grid(N / 128, M / 128, z);
        gmma_kernel<128, 128, false, false><<<grid, 256>>>(A, B, C, M, N, K, lda, ldb, ldc,
            aO, aI, bO, bI, cO, cI, mod, alpha, bias, resid, act);
    } else if ((M % 128 == 0) && (N % 64 == 0) && (size_t)(M / 128) * (N / 64) * z >= 120) {
        dim3 grid(N / 64, M / 128, z);
        gmma_kernel<128, 64, false, false><<<grid, 256>>>(A, B, C, M, N, K, lda, ldb, ldc,
            aO, aI, bO, bI, cO, cI, mod, alpha, bias, resid, act);
    } else {
        dim3 grid(N / 64, M / 64, z);
        gmma_kernel<64, 64, false, false><<<grid, 256>>>(A, B, C, M, N, K, lda, ldb, ldc,
            aO, aI, bO, bI, cO, cI, mod, alpha, bias, resid, act);
    }
}

static void gemm_proj(const float* A, const float* B, float* C, int M, int N, int K,
                      const float* bias = nullptr, const float* resid = nullptr, int act = 0) {
    gemm_batched(A, B, C, M, N, K, K, N, N, 0, 0, 0, 0, 0, 0, 1, 1, 1.f, bias, resid, act);
}

// S[z][512][klen] = alpha * Q_h @ K_h^T ; z = b*8+h
static void gemm_scores(const float* q, size_t qOuter, const float* kbase, size_t kOuter,
                        float* Sb, int klen, float alpha) {
    dim3 grid(klen / 64, 512 / 128, 32);
    gmma_kernel<128, 64, true, true><<<grid, 256>>>(q, kbase, Sb, 512, klen, 64,
        512, 512, klen,
        qOuter, 64, kOuter, 64, (size_t)8 * 512 * klen, (size_t)512 * klen, 8,
        alpha, nullptr, nullptr, 0);
}

// P[z][512][1152] = 8 * Q_h @ pos[h]^T
static void gemm_pos(const float* q, size_t qOuter, const float* pos, float* Pb) {
    dim3 grid(KVN / 64, 512 / 128, 32);
    gmma_kernel<128, 64, true, true><<<grid, 256>>>(q, pos, Pb, 512, KVN, 64,
        512, 64, KVN,
        qOuter, 64, 0, (size_t)KVN * 64, (size_t)8 * 512 * KVN, (size_t)512 * KVN, 8,
        8.f, nullptr, nullptr, 0);
}

// out[b][i][h*64+d] = S_z @ V_h
static void gemm_av(const float* Sb, const float* vbase, size_t vOuter, float* out, int klen) {
    dim3 grid(1, 512 / 128, 32);
    gmma_kernel<128, 64, false, true><<<grid, 256>>>(Sb, vbase, out, 512, 64, klen,
        klen, 512, 512,
        (size_t)8 * 512 * klen, (size_t)512 * klen, vOuter, 64, (size_t)512 * 512, 64, 8,
        1.f, nullptr, nullptr, 0);
}

static void run_softmax(float* Sb, const float* Pb, int klen, bool pos) {
    dim3 grid(512, 32);
    if (pos) softmax_kernel<true><<<grid, 128>>>(Sb, Pb, klen);
    else     softmax_kernel<false><<<grid, 128>>>(Sb, nullptr, klen);
}

extern "C" void kernel_launch(void* const* d_in, const int* in_sizes, int n_in,
                              void* d_out, int out_size) {
    const int*   trg     = (const int*)  d_in[0];
    const float* latent  = (const float*)d_in[3];
    const float* mems    = (const float*)d_in[4];
    const float* cmems   = (const float*)d_in[5];
    const float* pos_emb = (const float*)d_in[6];
    const float* embed   = (const float*)d_in[7];
    const float* W_self  = (const float*)d_in[8];
    const float* ln1_g   = (const float*)d_in[9];
    const float* ln1_b   = (const float*)d_in[10];
    const float* conv_w  = (const float*)d_in[11];
    const float* conv_b  = (const float*)d_in[12];
    const float* W_src   = (const float*)d_in[13];
    const float* ln2_g   = (const float*)d_in[14];
    const float* ln2_b   = (const float*)d_in[15];
    const float* w1      = (const float*)d_in[16];
    const float* b1      = (const float*)d_in[17];
    const float* w2      = (const float*)d_in[18];
    const float* b2      = (const float*)d_in[19];

    float* Sc;
    cudaGetSymbolAddress((void**)&Sc, g_scratch);
    float* X    = Sc + O_X;
    float* KVb  = Sc + O_KV;
    float* QKV  = Sc + O_QKV;           // Q slab [4608,512]
    float* Kp   = QKV + EL_KV;          // K slab
    float* Vp   = QKV + 2 * EL_KV;      // V slab
    float* ATT  = Sc + O_ATT;
    float* A    = Sc + O_A;
    float* TMP  = Sc + O_TMP;
    float* QR   = Sc + O_QR;
    float* QR2  = Sc + O_QR2;
    float* KR   = Sc + O_KR;
    float* VR   = Sc + O_VR;
    float* KN   = Sc + O_KN;
    float* VN   = Sc + O_VN;
    float* TGT  = Sc + O_TGT;
    float* RNEW = Sc + O_RNEW;
    float* NCM  = Sc + O_NCM;
    float* CWT  = Sc + O_CWT;
    float* FF   = Sc + O_FF;
    float* Y    = Sc + O_Y;
    float* X1   = Sc + O_X1;
    float* PART = Sc + O_PART;
    float* LOSS = Sc + O_LOSS;
    float* SS   = Sc + O_S;
    float* PP   = Sc + O_P;

    zero_loss_kernel<<<1, 32>>>(LOSS);
    embed_kernel<<<(int)(EL_X / 256), 256>>>(trg, embed, X);

    for (int i = 0; i < NL; i++) {
        const float* mem = mems  + (size_t)i * BB * 512 * 512;
        const float* cm  = cmems + (size_t)i * BB * 128 * 512;
        const float* W0 = W_self + ((size_t)i * 4 + 0) * 512 * 512;
        const float* W1 = W_self + ((size_t)i * 4 + 1) * 512 * 512;
        const float* Ws0 = W_src + ((size_t)i * 4 + 0) * 512 * 512;
        const float* Ws1 = W_src + ((size_t)i * 4 + 1) * 512 * 512;
        const float* Ws3 = W_src + ((size_t)i * 4 + 3) * 512 * 512;
        const float* W3  = W_self + ((size_t)i * 4 + 3) * 512 * 512;

        // ---- self-attention over kv = [cmem, mem, x] ----
        kv_kernel<<<(int)(EL_KV / 256), 256>>>(cm, mem, X, KVb);
        // fused QKV: z=3 over contiguous weights {W0,W1,W2}; Q slab covers ALL kv rows,
        // the x-rows (640..1151 per batch) are the real queries.
        gemm_batched(KVb, W0, QKV, 4608, 512, 512, 512, 512, 512,
                     0, 0, 0, 262144ull, 0, EL_KV, 3, 3, 1.f, nullptr, nullptr, 0);
        const float* Qx = QKV + 640ull * 512;   // Q rows of x, aO = 1152*512 per batch
        gemm_pos(Qx, (size_t)KVN * 512, pos_emb, PP);
        gemm_scores(Qx, (size_t)KVN * 512, Kp, (size_t)KVN * 512, SS, KVN, 0.125f);
        run_softmax(SS, PP, KVN, true);
        gemm_av(SS, Vp, (size_t)KVN * 512, ATT, KVN);
        gemm_proj(ATT, W3, TMP, 2048, 512, 512, nullptr, X, 0);
        ln_kernel<<<2048, 128>>>(TMP, ln1_g + i * 512, ln1_b + i * 512, A);

        // ---- compressed-memory reconstruction loss ----
        tconv_kernel<<<4096, 256>>>(conv_w + (size_t)i * 512 * 512 * 4, CWT);
        gemm_proj(mem, CWT, NCM, 512, 512, 2048, conv_b + i * 512);
        // batched QR: z=0 -> A@W0 (rattn), z=1 -> A@Ws0 (cross)
        gemm_batched(A, W0, QR, 2048, 512, 512, 512, 512, 512,
                     0, 0, 0, (size_t)(Ws0 - W0), 0, (size_t)(QR2 - QR),
                     2, 2, 1.f, nullptr, nullptr, 0);
        // target: K/V over old_mem = kv rows [128,640) (same weights)
        gemm_scores(QR, (size_t)512 * 512, Kp + 128 * 512, (size_t)KVN * 512, SS, 512, 0.125f);
        run_softmax(SS, nullptr, 512, false);
        gemm_av(SS, Vp + 128 * 512, (size_t)KVN * 512, TGT, 512);
        // rnew: K/V over NCM (z=2 over contiguous {W1,W2})
        gemm_batched(NCM, W1, KN, 512, 512, 512, 512, 512, 512,
                     0, 0, 0, 262144ull, 0, 262144ull, 2, 2, 1.f, nullptr, nullptr, 0);
        gemm_scores(QR, (size_t)512 * 512, KN, (size_t)128 * 512, SS, 128, 0.125f);
        run_softmax(SS, nullptr, 128, false);
        gemm_av(SS, VN, (size_t)128 * 512, RNEW, 128);
        loss_part_kernel<<<1024, 256>>>(RNEW, TGT, PART);
        loss_acc_kernel<<<1, 256>>>(PART, LOSS);

        // ---- cross-attention to latent (no residual) ----
        gemm_batched(latent, Ws1, KR, 1024, 512, 512, 512, 512, 512,
                     0, 0, 0, 262144ull, 0, (size_t)(VR - KR), 2, 2, 1.f, nullptr, nullptr, 0);
        gemm_scores(QR2, (size_t)512 * 512, KR, (size_t)256 * 512, SS, 256, 0.125f);
        run_softmax(SS, nullptr, 256, false);
        gemm_av(SS, VR, (size_t)256 * 512, TMP, 256);
        gemm_proj(TMP, Ws3, X1, 2048, 512, 512);

        // ---- FFN: x = x1 + gelu(LN(x1)@w1+b1)@w2 + b2 ----
        ln_kernel<<<2048, 128>>>(X1, ln2_g + i * 512, ln2_b + i * 512, Y);
        gemm_proj(Y,  w1 + (size_t)i * 512 * 2048, FF, 2048, 2048, 512,  b1 + (size_t)i * 2048, nullptr, 1);
        gemm_proj(FF, w2 + (size_t)i * 2048 * 512, X,  2048, 512,  2048, b2 + (size_t)i * 512,  X1,      0);
    }

    size_t nout = (size_t)out_size;
    out_kernel<<<(int)((nout + 255) / 256), 256>>>((float*)d_out, X, LOSS, nout);
}

// round 11
// speedup vs baseline: 2.6250x; 1.2090x over previous
#include <cuda_runtime.h>
#include <math.h>
#include <stdint.h>

#define NL 4
#define BB 4
#define DD 512
#define HH 8
#define KVN 1152

#define EL_X   1048576ull
#define EL_KV  2359296ull
#define EL_S   18874368ull   // 32 * 512 * 1152

constexpr size_t O_X    = 0;
constexpr size_t O_KV   = O_X    + EL_X;
constexpr size_t O_QKV  = O_KV   + EL_KV;          // 3 x [4608,512]
constexpr size_t O_ATT  = O_QKV  + 3ull * EL_KV;
constexpr size_t O_A    = O_ATT  + EL_X;
constexpr size_t O_TMP  = O_A    + EL_X;
constexpr size_t O_QR   = O_TMP  + EL_X;
constexpr size_t O_QR2  = O_QR   + EL_X;
constexpr size_t O_KR   = O_QR2  + EL_X;
constexpr size_t O_VR   = O_KR   + EL_X;
constexpr size_t O_KN   = O_VR   + EL_X;
constexpr size_t O_VN   = O_KN   + 262144ull;
constexpr size_t O_TGT  = O_VN   + 262144ull;
constexpr size_t O_RNEW = O_TGT  + EL_X;
constexpr size_t O_NCM  = O_RNEW + EL_X;
constexpr size_t O_CWT  = O_NCM  + 262144ull;
constexpr size_t O_FF   = O_CWT  + EL_X;
constexpr size_t O_Y    = O_FF   + 4194304ull;
constexpr size_t O_X1   = O_Y    + EL_X;
constexpr size_t O_PART = O_X1   + EL_X;
constexpr size_t O_LOSS = O_PART + 1024ull;
constexpr size_t O_S    = O_LOSS + 16ull;
constexpr size_t O_P    = O_S    + EL_S;
constexpr size_t SCRATCH_TOTAL = O_P + EL_S;

__device__ float g_scratch[SCRATCH_TOTAL];

__device__ __forceinline__ uint32_t f2tf32(float f) {
    uint32_t u;
    asm("cvt.rna.tf32.f32 %0, %1;" : "=r"(u) : "f"(f));
    return u;
}

__device__ __forceinline__ float block_red_sum(float v, float* sbuf, int nthreads) {
    int lane = threadIdx.x & 31, w = threadIdx.x >> 5;
    #pragma unroll
    for (int o = 16; o; o >>= 1) v += __shfl_xor_sync(0xffffffffu, v, o);
    __syncthreads();
    if (lane == 0) sbuf[w] = v;
    __syncthreads();
    int nw = nthreads >> 5;
    float r = 0.f;
    for (int i = 0; i < nw; i++) r += sbuf[i];
    return r;
}

__device__ __forceinline__ float block_red_max(float v, float* sbuf, int nthreads) {
    int lane = threadIdx.x & 31, w = threadIdx.x >> 5;
    #pragma unroll
    for (int o = 16; o; o >>= 1) v = fmaxf(v, __shfl_xor_sync(0xffffffffu, v, o));
    __syncthreads();
    if (lane == 0) sbuf[w] = v;
    __syncthreads();
    int nw = nthreads >> 5;
    float r = -1e30f;
    for (int i = 0; i < nw; i++) r = fmaxf(r, sbuf[i]);
    return r;
}

__global__ void zero_loss_kernel(float* loss) { if (threadIdx.x == 0) loss[0] = 0.f; }

__global__ void embed_kernel(const int* __restrict__ trg, const float* __restrict__ emb,
                             float* __restrict__ x) {
    size_t idx = (size_t)blockIdx.x * blockDim.x + threadIdx.x;
    if (idx >= EL_X) return;
    int row = (int)(idx >> 9);
    int d   = (int)(idx & 511);
    x[idx] = emb[(size_t)trg[row] * 512 + d];
}

__global__ void kv_kernel(const float* __restrict__ cm, const float* __restrict__ mem,
                          const float* __restrict__ x, float* __restrict__ kv) {
    size_t idx = (size_t)blockIdx.x * blockDim.x + threadIdx.x;
    if (idx >= EL_KV) return;
    int b   = (int)(idx / ((size_t)KVN * DD));
    int rem = (int)(idx - (size_t)b * KVN * DD);
    int p = rem >> 9, d = rem & 511;
    float val;
    if (p < 128)       val = cm [(size_t)b * 128 * 512 + ((size_t)p << 9) + d];
    else if (p < 640)  val = mem[(size_t)b * 512 * 512 + ((size_t)(p - 128) << 9) + d];
    else               val = x  [(size_t)b * 512 * 512 + ((size_t)(p - 640) << 9) + d];
    kv[idx] = val;
}

__global__ void tconv_kernel(const float* __restrict__ cw, float* __restrict__ cwt) {
    size_t idx = (size_t)blockIdx.x * blockDim.x + threadIdx.x;
    if (idx >= 2048ull * 512ull) return;
    int o = (int)(idx & 511);
    int k = (int)(idx >> 9);
    int d = k & 511;
    int r = k >> 9;
    cwt[idx] = cw[((size_t)o * 512 + d) * 4 + r];
}

__global__ void out_kernel(float* __restrict__ o, const float* __restrict__ x,
                           const float* __restrict__ loss, size_t nout) {
    size_t i = (size_t)blockIdx.x * blockDim.x + threadIdx.x;
    if (i >= nout) return;
    if (i < EL_X) o[i] = x[i];
    else          o[i] = loss[0] * (1.f / (1048576.f * 4.f));
}

__global__ void __launch_bounds__(128) ln_kernel(const float* __restrict__ in,
                                                 const float* __restrict__ g,
                                                 const float* __restrict__ bb,
                                                 float* __restrict__ out) {
    __shared__ float sbuf[8];
    const int row = blockIdx.x, tid = threadIdx.x;
    const size_t base = (size_t)row * 512 + (size_t)tid * 4;
    float4 v4 = *(const float4*)(in + base);
    float v[4] = {v4.x, v4.y, v4.z, v4.w};
    float s = v[0] + v[1] + v[2] + v[3];
    s = block_red_sum(s, sbuf, 128);
    float mu = s * (1.f / 512.f);
    float d2 = 0.f;
    #pragma unroll
    for (int j = 0; j < 4; j++) { float t = v[j] - mu; d2 += t * t; }
    d2 = block_red_sum(d2, sbuf, 128);
    float rs = rsqrtf(d2 * (1.f / 512.f) + 1e-5f);
    int c = tid * 4;
    float4 o;
    o.x = (v[0] - mu) * rs * g[c + 0] + bb[c + 0];
    o.y = (v[1] - mu) * rs * g[c + 1] + bb[c + 1];
    o.z = (v[2] - mu) * rs * g[c + 2] + bb[c + 2];
    o.w = (v[3] - mu) * rs * g[c + 3] + bb[c + 3];
    *(float4*)(out + base) = o;
}

__global__ void __launch_bounds__(256) loss_part_kernel(const float* __restrict__ a,
                                                        const float* __restrict__ b,
                                                        float* __restrict__ part) {
    __shared__ float sbuf[8];
    size_t base = (size_t)blockIdx.x * 1024 + (size_t)threadIdx.x * 4;
    float4 x = *(const float4*)(a + base);
    float4 y = *(const float4*)(b + base);
    float dx = x.x - y.x, dy = x.y - y.y, dz = x.z - y.z, dw = x.w - y.w;
    float s = dx * dx + dy * dy + dz * dz + dw * dw;
    s = block_red_sum(s, sbuf, 256);
    if (threadIdx.x == 0) part[blockIdx.x] = s;
}

__global__ void __launch_bounds__(256) loss_acc_kernel(const float* __restrict__ part,
                                                       float* __restrict__ loss) {
    __shared__ float sbuf[8];
    int tid = threadIdx.x;
    float s = part[tid] + part[tid + 256] + part[tid + 512] + part[tid + 768];
    s = block_red_sum(s, sbuf, 256);
    if (tid == 0) loss[0] += s;
}

// ---------------- generalized batched TF32 tensor-core GEMM ----------------
// C = alpha * A @ B (+bias)(+gelu)(+resid)
// A row-major [M,K] (row stride lda); B: BNM ? B[n][k] : B[k][n] (row stride ldb)
// batch z: offset(tensor) = (z/mod)*Outer + (z%mod)*Inner
// X3: 3xTF32 split (hi/lo) for ~fp32 accuracy.
// smem layouts: A [m][k] stride 20 (conflict-free frag reads).
//   BNM B:  [n][k] stride 20 (same as A).
//   !BNM B: natural [k][n] stride TN+8 — no transpose on store (vector STS.128,
//           conflict-free) and frag reads hit banks 8*tg+g (conflict-free).
template<int TM, int TN, bool BNM, bool X3>
__global__ void __launch_bounds__(256) gmma_kernel(
    const float* __restrict__ A, const float* __restrict__ B, float* __restrict__ C,
    int M, int N, int K, int lda, int ldb, int ldc,
    size_t aO, size_t aI, size_t bO, size_t bI, size_t cO, size_t cI, int mod,
    float alpha, const float* __restrict__ bias,
    const float* __restrict__ resid, int act)
{
    constexpr int MT = TM / 32;
    constexpr int NT = TN / 32;
    constexpr int AVN = TM / 64;
    constexpr int BVN = TN / 64;
    constexpr int BST = BNM ? 20 : (TN + 8);
    constexpr int BSZ = BNM ? (TN * 20) : (16 * (TN + 8));
    __shared__ uint32_t AsH[TM * 20];
    __shared__ uint32_t BsH[BSZ];
    __shared__ uint32_t AsL[X3 ? TM * 20 : 4];
    __shared__ uint32_t BsL[X3 ? BSZ : 4];

    const int z = blockIdx.z;
    const size_t aOff = (size_t)(z / mod) * aO + (size_t)(z % mod) * aI;
    const size_t bOff = (size_t)(z / mod) * bO + (size_t)(z % mod) * bI;
    const size_t cOff = (size_t)(z / mod) * cO + (size_t)(z % mod) * cI;
    const float* Ab = A + aOff;
    const float* Bb = B + bOff;
    float* Cb = C + cOff;

    const int tid = threadIdx.x;
    const int wid = tid >> 5, lane = tid & 31;
    const int wm = wid >> 2, wn = wid & 3;
    const int g = lane >> 2, tg = lane & 3;
    const int m0 = blockIdx.y * TM, n0 = blockIdx.x * TN;

    float acc[MT][NT][4];
    #pragma unroll
    for (int i = 0; i < MT; i++)
        #pragma unroll
        for (int j = 0; j < NT; j++)
            #pragma unroll
            for (int c = 0; c < 4; c++) acc[i][j][c] = 0.f;

    float4 pa[AVN], pb[BVN];
    #pragma unroll
    for (int v = 0; v < AVN; v++) {
        int idx4 = tid + v * 256;
        int row = idx4 >> 2, kg = (idx4 & 3) << 2;
        pa[v] = *(const float4*)(Ab + (size_t)(m0 + row) * lda + kg);
    }
    #pragma unroll
    for (int v = 0; v < BVN; v++) {
        int idx4 = tid + v * 256;
        if (BNM) {
            int row = idx4 >> 2, kg = (idx4 & 3) << 2;
            pb[v] = *(const float4*)(Bb + (size_t)(n0 + row) * ldb + kg);
        } else {
            int k = idx4 / (TN / 4), c = (idx4 % (TN / 4)) << 2;
            pb[v] = *(const float4*)(Bb + (size_t)k * ldb + n0 + c);
        }
    }

    for (int k0 = 0;; k0 += 16) {
        __syncthreads();
        #pragma unroll
        for (int v = 0; v < AVN; v++) {
            int idx4 = tid + v * 256;
            int row = idx4 >> 2, kg = (idx4 & 3) << 2;
            float f[4] = {pa[v].x, pa[v].y, pa[v].z, pa[v].w};
            uint4 h, l;
            h.x = f2tf32(f[0]); h.y = f2tf32(f[1]); h.z = f2tf32(f[2]); h.w = f2tf32(f[3]);
            *(uint4*)&AsH[row * 20 + kg] = h;
            if (X3) {
                l.x = f2tf32(f[0] - __uint_as_float(h.x));
                l.y = f2tf32(f[1] - __uint_as_float(h.y));
                l.z = f2tf32(f[2] - __uint_as_float(h.z));
                l.w = f2tf32(f[3] - __uint_as_float(h.w));
                *(uint4*)&AsL[row * 20 + kg] = l;
            }
        }
        #pragma unroll
        for (int v = 0; v < BVN; v++) {
            int idx4 = tid + v * 256;
            float f[4] = {pb[v].x, pb[v].y, pb[v].z, pb[v].w};
            uint4 h, l;
            h.x = f2tf32(f[0]); h.y = f2tf32(f[1]); h.z = f2tf32(f[2]); h.w = f2tf32(f[3]);
            if (X3) {
                l.x = f2tf32(f[0] - __uint_as_float(h.x));
                l.y = f2tf32(f[1] - __uint_as_float(h.y));
                l.z = f2tf32(f[2] - __uint_as_float(h.z));
                l.w = f2tf32(f[3] - __uint_as_float(h.w));
            }
            if (BNM) {
                int row = idx4 >> 2, kg = (idx4 & 3) << 2;
                *(uint4*)&BsH[row * 20 + kg] = h;
                if (X3) *(uint4*)&BsL[row * 20 + kg] = l;
            } else {
                int k = idx4 / (TN / 4), c = (idx4 % (TN / 4)) << 2;
                *(uint4*)&BsH[k * BST + c] = h;
                if (X3) *(uint4*)&BsL[k * BST + c] = l;
            }
        }
        __syncthreads();
        bool more = (k0 + 16 < K);
        if (more) {
            int kn = k0 + 16;
            #pragma unroll
            for (int v = 0; v < AVN; v++) {
                int idx4 = tid + v * 256;
                int row = idx4 >> 2, kg = (idx4 & 3) << 2;
                pa[v] = *(const float4*)(Ab + (size_t)(m0 + row) * lda + kn + kg);
            }
            #pragma unroll
            for (int v = 0; v < BVN; v++) {
                int idx4 = tid + v * 256;
                if (BNM) {
                    int row = idx4 >> 2, kg = (idx4 & 3) << 2;
                    pb[v] = *(const float4*)(Bb + (size_t)(n0 + row) * ldb + kn + kg);
                } else {
                    int k = idx4 / (TN / 4), c = (idx4 % (TN / 4)) << 2;
                    pb[v] = *(const float4*)(Bb + (size_t)(kn + k) * ldb + n0 + c);
                }
            }
        }
        #pragma unroll
        for (int kk = 0; kk < 16; kk += 8) {
            uint32_t afH[MT][4], bfH[NT][2];
            uint32_t afL[X3 ? MT : 1][4], bfL[X3 ? NT : 1][2];
            #pragma unroll
            for (int i = 0; i < MT; i++) {
                int r = wm * (TM / 2) + i * 16 + g;
                afH[i][0] = AsH[r * 20 + kk + tg];
                afH[i][1] = AsH[(r + 8) * 20 + kk + tg];
                afH[i][2] = AsH[r * 20 + kk + tg + 4];
                afH[i][3] = AsH[(r + 8) * 20 + kk + tg + 4];
                if (X3) {
                    afL[i][0] = AsL[r * 20 + kk + tg];
                    afL[i][1] = AsL[(r + 8) * 20 + kk + tg];
                    afL[i][2] = AsL[r * 20 + kk + tg + 4];
                    afL[i][3] = AsL[(r + 8) * 20 + kk + tg + 4];
                }
            }
            #pragma unroll
            for (int j = 0; j < NT; j++) {
                int n = wn * (TN / 4) + j * 8 + g;
                if (BNM) {
                    bfH[j][0] = BsH[n * 20 + kk + tg];
                    bfH[j][1] = BsH[n * 20 + kk + tg + 4];
                    if (X3) {
                        bfL[j][0] = BsL[n * 20 + kk + tg];
                        bfL[j][1] = BsL[n * 20 + kk + tg + 4];
                    }
                } else {
                    bfH[j][0] = BsH[(kk + tg) * BST + n];
                    bfH[j][1] = BsH[(kk + tg + 4) * BST + n];
                    if (X3) {
                        bfL[j][0] = BsL[(kk + tg) * BST + n];
                        bfL[j][1] = BsL[(kk + tg + 4) * BST + n];
                    }
                }
            }
            #pragma unroll
            for (int i = 0; i < MT; i++)
                #pragma unroll
                for (int j = 0; j < NT; j++) {
                    asm volatile(
                        "mma.sync.aligned.m16n8k8.row.col.f32.tf32.tf32.f32 "
                        "{%0,%1,%2,%3}, {%4,%5,%6,%7}, {%8,%9}, {%0,%1,%2,%3};\n"
                        : "+f"(acc[i][j][0]), "+f"(acc[i][j][1]),
                          "+f"(acc[i][j][2]), "+f"(acc[i][j][3])
                        : "r"(afH[i][0]), "r"(afH[i][1]), "r"(afH[i][2]), "r"(afH[i][3]),
                          "r"(bfH[j][0]), "r"(bfH[j][1]));
                    if (X3) {
                        asm volatile(
                            "mma.sync.aligned.m16n8k8.row.col.f32.tf32.tf32.f32 "
                            "{%0,%1,%2,%3}, {%4,%5,%6,%7}, {%8,%9}, {%0,%1,%2,%3};\n"
                            : "+f"(acc[i][j][0]), "+f"(acc[i][j][1]),
                              "+f"(acc[i][j][2]), "+f"(acc[i][j][3])
                            : "r"(afL[i][0]), "r"(afL[i][1]), "r"(afL[i][2]), "r"(afL[i][3]),
                              "r"(bfH[j][0]), "r"(bfH[j][1]));
                        asm volatile(
                            "mma.sync.aligned.m16n8k8.row.col.f32.tf32.tf32.f32 "
                            "{%0,%1,%2,%3}, {%4,%5,%6,%7}, {%8,%9}, {%0,%1,%2,%3};\n"
                            : "+f"(acc[i][j][0]), "+f"(acc[i][j][1]),
                              "+f"(acc[i][j][2]), "+f"(acc[i][j][3])
                            : "r"(afH[i][0]), "r"(afH[i][1]), "r"(afH[i][2]), "r"(afH[i][3]),
                              "r"(bfL[j][0]), "r"(bfL[j][1]));
                    }
                }
        }
        if (!more) break;
    }

    #pragma unroll
    for (int i = 0; i < MT; i++) {
        int m = m0 + wm * (TM / 2) + i * 16 + g;
        #pragma unroll
        for (int j = 0; j < NT; j++) {
            int n = n0 + wn * (TN / 4) + j * 8 + 2 * tg;
            float c0 = acc[i][j][0] * alpha, c1 = acc[i][j][1] * alpha;
            float c2 = acc[i][j][2] * alpha, c3 = acc[i][j][3] * alpha;
            if (bias) {
                float b0 = bias[n], b1 = bias[n + 1];
                c0 += b0; c1 += b1; c2 += b0; c3 += b1;
            }
            if (act) {
                c0 = 0.5f * c0 * (1.f + erff(c0 * 0.7071067811865475f));
                c1 = 0.5f * c1 * (1.f + erff(c1 * 0.7071067811865475f));
                c2 = 0.5f * c2 * (1.f + erff(c2 * 0.7071067811865475f));
                c3 = 0.5f * c3 * (1.f + erff(c3 * 0.7071067811865475f));
            }
            if (resid) {
                const float* Rb = resid + cOff;
                c0 += Rb[(size_t)m * ldc + n];
                c1 += Rb[(size_t)m * ldc + n + 1];
                c2 += Rb[(size_t)(m + 8) * ldc + n];
                c3 += Rb[(size_t)(m + 8) * ldc + n + 1];
            }
            float2 lo = {c0, c1}, hi = {c2, c3};
            *(float2*)(Cb + (size_t)m * ldc + n) = lo;
            *(float2*)(Cb + (size_t)(m + 8) * ldc + n) = hi;
        }
    }
}

// ---------------- softmax with optional fused shift()+pos add ----------------
template<bool POS>
__global__ void __launch_bounds__(128) softmax_kernel(float* __restrict__ S,
                                                      const float* __restrict__ P,
                                                      int klen) {
    __shared__ float sbuf[4];
    const int i = blockIdx.x, z = blockIdx.y, tid = threadIdx.x;
    float* row = S + ((size_t)z * 512 + i) * klen;
    const float* prow = POS ? (P + ((size_t)z * 512 + i) * KVN) : nullptr;
    float mx = -1e30f;
    for (int j = tid; j < klen; j += 128) {
        float v = row[j];
        if (POS) {
            int r = j + 511 - i;
            if (r < KVN) v += prow[r];
        }
        row[j] = v;
        mx = fmaxf(mx, v);
    }
    mx = block_red_max(mx, sbuf, 128);
    float sum = 0.f;
    for (int j = tid; j < klen; j += 128) {
        float e = expf(row[j] - mx);
        row[j] = e;
        sum += e;
    }
    sum = block_red_sum(sum, sbuf, 128);
    float inv = 1.f / sum;
    for (int j = tid; j < klen; j += 128) row[j] *= inv;
}

// ---------------- host wrappers ----------------
static void gemm_batched(const float* A, const float* B, float* C, int M, int N, int K,
                         int lda, int ldb, int ldc,
                         size_t aO, size_t aI, size_t bO, size_t bI, size_t cO, size_t cI,
                         int mod, int z, float alpha,
                         const float* bias, const float* resid, int act) {
    if ((M % 128 == 0) && (N % 128 == 0) && (size_t)(M / 128) * (N / 128) * z >= 120) {
        dim3 grid(N / 128, M / 128, z);
        gmma_kernel<128, 128, false, false><<<grid, 256>>>(A, B, C, M, N, K, lda, ldb, ldc,
            aO, aI, bO, bI, cO, cI, mod, alpha, bias, resid, act);
    } else if ((M % 128 == 0) && (N % 64 == 0) && (size_t)(M / 128) * (N / 64) * z >= 120) {
        dim3 grid(N / 64, M / 128, z);
        gmma_kernel<128, 64, false, false><<<grid, 256>>>(A, B, C, M, N, K, lda, ldb, ldc,
            aO, aI, bO, bI, cO, cI, mod, alpha, bias, resid, act);
    } else {
        dim3 grid(N / 64, M / 64, z);
        gmma_kernel<64, 64, false, false><<<grid, 256>>>(A, B, C, M, N, K, lda, ldb, ldc,
            aO, aI, bO, bI, cO, cI, mod, alpha, bias, resid, act);
    }
}

static void gemm_proj(const float* A, const float* B, float* C, int M, int N, int K,
                      const float* bias = nullptr, const float* resid = nullptr, int act = 0) {
    gemm_batched(A, B, C, M, N, K, K, N, N, 0, 0, 0, 0, 0, 0, 1, 1, 1.f, bias, resid, act);
}

// S[z][512][klen] = alpha * Q_h @ K_h^T ; z = b*8+h
static void gemm_scores(const float* q, size_t qOuter, const float* kbase, size_t kOuter,
                        float* Sb, int klen, float alpha) {
    dim3 grid(klen / 64, 512 / 128, 32);
    gmma_kernel<128, 64, true, true><<<grid, 256>>>(q, kbase, Sb, 512, klen, 64,
        512, 512, klen,
        qOuter, 64, kOuter, 64, (size_t)8 * 512 * klen, (size_t)512 * klen, 8,
        alpha, nullptr, nullptr, 0);
}

// P[z][512][1152] = 8 * Q_h @ pos[h]^T
static void gemm_pos(const float* q, size_t qOuter, const float* pos, float* Pb) {
    dim3 grid(KVN / 64, 512 / 128, 32);
    gmma_kernel<128, 64, true, true><<<grid, 256>>>(q, pos, Pb, 512, KVN, 64,
        512, 64, KVN,
        qOuter, 64, 0, (size_t)KVN * 64, (size_t)8 * 512 * KVN, (size_t)512 * KVN, 8,
        8.f, nullptr, nullptr, 0);
}

// out[b][i][h*64+d] = S_z @ V_h
static void gemm_av(const float* Sb, const float* vbase, size_t vOuter, float* out, int klen) {
    dim3 grid(1, 512 / 128, 32);
    gmma_kernel<128, 64, false, true><<<grid, 256>>>(Sb, vbase, out, 512, 64, klen,
        klen, 512, 512,
        (size_t)8 * 512 * klen, (size_t)512 * klen, vOuter, 64, (size_t)512 * 512, 64, 8,
        1.f, nullptr, nullptr, 0);
}

static void run_softmax(float* Sb, const float* Pb, int klen, bool pos) {
    dim3 grid(512, 32);
    if (pos) softmax_kernel<true><<<grid, 128>>>(Sb, Pb, klen);
    else     softmax_kernel<false><<<grid, 128>>>(Sb, nullptr, klen);
}

extern "C" void kernel_launch(void* const* d_in, const int* in_sizes, int n_in,
                              void* d_out, int out_size) {
    const int*   trg     = (const int*)  d_in[0];
    const float* latent  = (const float*)d_in[3];
    const float* mems    = (const float*)d_in[4];
    const float* cmems   = (const float*)d_in[5];
    const float* pos_emb = (const float*)d_in[6];
    const float* embed   = (const float*)d_in[7];
    const float* W_self  = (const float*)d_in[8];
    const float* ln1_g   = (const float*)d_in[9];
    const float* ln1_b   = (const float*)d_in[10];
    const float* conv_w  = (const float*)d_in[11];
    const float* conv_b  = (const float*)d_in[12];
    const float* W_src   = (const float*)d_in[13];
    const float* ln2_g   = (const float*)d_in[14];
    const float* ln2_b   = (const float*)d_in[15];
    const float* w1      = (const float*)d_in[16];
    const float* b1      = (const float*)d_in[17];
    const float* w2      = (const float*)d_in[18];
    const float* b2      = (const float*)d_in[19];

    float* Sc;
    cudaGetSymbolAddress((void**)&Sc, g_scratch);
    float* X    = Sc + O_X;
    float* KVb  = Sc + O_KV;
    float* QKV  = Sc + O_QKV;           // Q slab [4608,512]
    float* Kp   = QKV + EL_KV;          // K slab
    float* Vp   = QKV + 2 * EL_KV;      // V slab
    float* ATT  = Sc + O_ATT;
    float* A    = Sc + O_A;
    float* TMP  = Sc + O_TMP;
    float* QR   = Sc + O_QR;
    float* QR2  = Sc + O_QR2;
    float* KR   = Sc + O_KR;
    float* VR   = Sc + O_VR;
    float* KN   = Sc + O_KN;
    float* VN   = Sc + O_VN;
    float* TGT  = Sc + O_TGT;
    float* RNEW = Sc + O_RNEW;
    float* NCM  = Sc + O_NCM;
    float* CWT  = Sc + O_CWT;
    float* FF   = Sc + O_FF;
    float* Y    = Sc + O_Y;
    float* X1   = Sc + O_X1;
    float* PART = Sc + O_PART;
    float* LOSS = Sc + O_LOSS;
    float* SS   = Sc + O_S;
    float* PP   = Sc + O_P;

    zero_loss_kernel<<<1, 32>>>(LOSS);
    embed_kernel<<<(int)(EL_X / 256), 256>>>(trg, embed, X);

    for (int i = 0; i < NL; i++) {
        const float* mem = mems  + (size_t)i * BB * 512 * 512;
        const float* cm  = cmems + (size_t)i * BB * 128 * 512;
        const float* W0 = W_self + ((size_t)i * 4 + 0) * 512 * 512;
        const float* W1 = W_self + ((size_t)i * 4 + 1) * 512 * 512;
        const float* Ws0 = W_src + ((size_t)i * 4 + 0) * 512 * 512;
        const float* Ws1 = W_src + ((size_t)i * 4 + 1) * 512 * 512;
        const float* Ws3 = W_src + ((size_t)i * 4 + 3) * 512 * 512;
        const float* W3  = W_self + ((size_t)i * 4 + 3) * 512 * 512;

        // ---- self-attention over kv = [cmem, mem, x] ----
        kv_kernel<<<(int)(EL_KV / 256), 256>>>(cm, mem, X, KVb);
        // fused QKV: z=3 over contiguous weights {W0,W1,W2}; Q slab covers ALL kv rows,
        // the x-rows (640..1151 per batch) are the real queries.
        gemm_batched(KVb, W0, QKV, 4608, 512, 512, 512, 512, 512,
                     0, 0, 0, 262144ull, 0, EL_KV, 3, 3, 1.f, nullptr, nullptr, 0);
        const float* Qx = QKV + 640ull * 512;   // Q rows of x, aO = 1152*512 per batch
        gemm_pos(Qx, (size_t)KVN * 512, pos_emb, PP);
        gemm_scores(Qx, (size_t)KVN * 512, Kp, (size_t)KVN * 512, SS, KVN, 0.125f);
        run_softmax(SS, PP, KVN, true);
        gemm_av(SS, Vp, (size_t)KVN * 512, ATT, KVN);
        gemm_proj(ATT, W3, TMP, 2048, 512, 512, nullptr, X, 0);
        ln_kernel<<<2048, 128>>>(TMP, ln1_g + i * 512, ln1_b + i * 512, A);

        // ---- compressed-memory reconstruction loss ----
        tconv_kernel<<<4096, 256>>>(conv_w + (size_t)i * 512 * 512 * 4, CWT);
        gemm_proj(mem, CWT, NCM, 512, 512, 2048, conv_b + i * 512);
        // batched QR: z=0 -> A@W0 (rattn), z=1 -> A@Ws0 (cross)
        gemm_batched(A, W0, QR, 2048, 512, 512, 512, 512, 512,
                     0, 0, 0, (size_t)(Ws0 - W0), 0, (size_t)(QR2 - QR),
                     2, 2, 1.f, nullptr, nullptr, 0);
        // target: K/V over old_mem = kv rows [128,640) (same weights)
        gemm_scores(QR, (size_t)512 * 512, Kp + 128 * 512, (size_t)KVN * 512, SS, 512, 0.125f);
        run_softmax(SS, nullptr, 512, false);
        gemm_av(SS, Vp + 128 * 512, (size_t)KVN * 512, TGT, 512);
        // rnew: K/V over NCM (z=2 over contiguous {W1,W2})
        gemm_batched(NCM, W1, KN, 512, 512, 512, 512, 512, 512,
                     0, 0, 0, 262144ull, 0, 262144ull, 2, 2, 1.f, nullptr, nullptr, 0);
        gemm_scores(QR, (size_t)512 * 512, KN, (size_t)128 * 512, SS, 128, 0.125f);
        run_softmax(SS, nullptr, 128, false);
        gemm_av(SS, VN, (size_t)128 * 512, RNEW, 128);
        loss_part_kernel<<<1024, 256>>>(RNEW, TGT, PART);
        loss_acc_kernel<<<1, 256>>>(PART, LOSS);

        // ---- cross-attention to latent (no residual) ----
        gemm_batched(latent, Ws1, KR, 1024, 512, 512, 512, 512, 512,
                     0, 0, 0, 262144ull, 0, (size_t)(VR - KR), 2, 2, 1.f, nullptr, nullptr, 0);
        gemm_scores(QR2, (size_t)512 * 512, KR, (size_t)256 * 512, SS, 256, 0.125f);
        run_softmax(SS, nullptr, 256, false);
        gemm_av(SS, VR, (size_t)256 * 512, TMP, 256);
        gemm_proj(TMP, Ws3, X1, 2048, 512, 512);

        // ---- FFN: x = x1 + gelu(LN(x1)@w1+b1)@w2 + b2 ----
        ln_kernel<<<2048, 128>>>(X1, ln2_g + i * 512, ln2_b + i * 512, Y);
        gemm_proj(Y,  w1 + (size_t)i * 512 * 2048, FF, 2048, 2048, 512,  b1 + (size_t)i * 2048, nullptr, 1);
        gemm_proj(FF, w2 + (size_t)i * 2048 * 512, X,  2048, 512,  2048, b2 + (size_t)i * 512,  X1,      0);
    }

    size_t nout = (size_t)out_size;
    out_kernel<<<(int)((nout + 255) / 256), 256>>>((float*)d_out, X, LOSS, nout);
}

// round 14
// speedup vs baseline: 2.7919x; 1.0636x over previous
#include <cuda_runtime.h>
#include <math.h>
#include <stdint.h>

#define NL 4
#define BB 4
#define DD 512
#define HH 8
#define KVN 1152

#define EL_X   1048576ull
#define EL_KV  2359296ull
#define EL_S   18874368ull   // 32 * 512 * 1152

constexpr size_t O_X    = 0;
constexpr size_t O_KV   = O_X    + EL_X;
constexpr size_t O_QKV  = O_KV   + EL_KV;          // 3 x [4608,512]
constexpr size_t O_ATT  = O_QKV  + 3ull * EL_KV;
constexpr size_t O_A    = O_ATT  + EL_X;
constexpr size_t O_TMP  = O_A    + EL_X;
constexpr size_t O_QR   = O_TMP  + EL_X;
constexpr size_t O_QR2  = O_QR   + EL_X;
constexpr size_t O_KR   = O_QR2  + EL_X;
constexpr size_t O_VR   = O_KR   + EL_X;
constexpr size_t O_KN   = O_VR   + EL_X;
constexpr size_t O_VN   = O_KN   + 262144ull;
constexpr size_t O_TGT  = O_VN   + 262144ull;
constexpr size_t O_RNEW = O_TGT  + EL_X;
constexpr size_t O_NCM  = O_RNEW + EL_X;
constexpr size_t O_CWT  = O_NCM  + 262144ull;
constexpr size_t O_FF   = O_CWT  + EL_X;
constexpr size_t O_Y    = O_FF   + 4194304ull;
constexpr size_t O_X1   = O_Y    + EL_X;
constexpr size_t O_PART = O_X1   + EL_X;
constexpr size_t O_LOSS = O_PART + 1024ull;
constexpr size_t O_S    = O_LOSS + 16ull;
constexpr size_t O_P    = O_S    + EL_S;
constexpr size_t SCRATCH_TOTAL = O_P + EL_S;

__device__ float g_scratch[SCRATCH_TOTAL];

__device__ __forceinline__ uint32_t f2tf32(float f) {
    uint32_t u;
    asm("cvt.rna.tf32.f32 %0, %1;" : "=r"(u) : "f"(f));
    return u;
}

__device__ __forceinline__ float block_red_sum(float v, float* sbuf, int nthreads) {
    int lane = threadIdx.x & 31, w = threadIdx.x >> 5;
    #pragma unroll
    for (int o = 16; o; o >>= 1) v += __shfl_xor_sync(0xffffffffu, v, o);
    __syncthreads();
    if (lane == 0) sbuf[w] = v;
    __syncthreads();
    int nw = nthreads >> 5;
    float r = 0.f;
    for (int i = 0; i < nw; i++) r += sbuf[i];
    return r;
}

__device__ __forceinline__ float block_red_max(float v, float* sbuf, int nthreads) {
    int lane = threadIdx.x & 31, w = threadIdx.x >> 5;
    #pragma unroll
    for (int o = 16; o; o >>= 1) v = fmaxf(v, __shfl_xor_sync(0xffffffffu, v, o));
    __syncthreads();
    if (lane == 0) sbuf[w] = v;
    __syncthreads();
    int nw = nthreads >> 5;
    float r = -1e30f;
    for (int i = 0; i < nw; i++) r = fmaxf(r, sbuf[i]);
    return r;
}

__global__ void zero_loss_kernel(float* loss) { if (threadIdx.x == 0) loss[0] = 0.f; }

__global__ void embed_kernel(const int* __restrict__ trg, const float* __restrict__ emb,
                             float* __restrict__ x) {
    size_t idx = (size_t)blockIdx.x * blockDim.x + threadIdx.x;
    if (idx >= EL_X) return;
    int row = (int)(idx >> 9);
    int d   = (int)(idx & 511);
    x[idx] = emb[(size_t)trg[row] * 512 + d];
}

__global__ void kv_kernel(const float* __restrict__ cm, const float* __restrict__ mem,
                          const float* __restrict__ x, float* __restrict__ kv) {
    size_t idx = (size_t)blockIdx.x * blockDim.x + threadIdx.x;
    if (idx >= EL_KV) return;
    int b   = (int)(idx / ((size_t)KVN * DD));
    int rem = (int)(idx - (size_t)b * KVN * DD);
    int p = rem >> 9, d = rem & 511;
    float val;
    if (p < 128)       val = cm [(size_t)b * 128 * 512 + ((size_t)p << 9) + d];
    else if (p < 640)  val = mem[(size_t)b * 512 * 512 + ((size_t)(p - 128) << 9) + d];
    else               val = x  [(size_t)b * 512 * 512 + ((size_t)(p - 640) << 9) + d];
    kv[idx] = val;
}

__global__ void tconv_kernel(const float* __restrict__ cw, float* __restrict__ cwt) {
    size_t idx = (size_t)blockIdx.x * blockDim.x + threadIdx.x;
    if (idx >= 2048ull * 512ull) return;
    int o = (int)(idx & 511);
    int k = (int)(idx >> 9);
    int d = k & 511;
    int r = k >> 9;
    cwt[idx] = cw[((size_t)o * 512 + d) * 4 + r];
}

__global__ void out_kernel(float* __restrict__ o, const float* __restrict__ x,
                           const float* __restrict__ loss, size_t nout) {
    size_t i = (size_t)blockIdx.x * blockDim.x + threadIdx.x;
    if (i >= nout) return;
    if (i < EL_X) o[i] = x[i];
    else          o[i] = loss[0] * (1.f / (1048576.f * 4.f));
}

__global__ void __launch_bounds__(128) ln_kernel(const float* __restrict__ in,
                                                 const float* __restrict__ g,
                                                 const float* __restrict__ bb,
                                                 float* __restrict__ out) {
    __shared__ float sbuf[8];
    const int row = blockIdx.x, tid = threadIdx.x;
    const size_t base = (size_t)row * 512 + (size_t)tid * 4;
    float4 v4 = *(const float4*)(in + base);
    float v[4] = {v4.x, v4.y, v4.z, v4.w};
    float s = v[0] + v[1] + v[2] + v[3];
    s = block_red_sum(s, sbuf, 128);
    float mu = s * (1.f / 512.f);
    float d2 = 0.f;
    #pragma unroll
    for (int j = 0; j < 4; j++) { float t = v[j] - mu; d2 += t * t; }
    d2 = block_red_sum(d2, sbuf, 128);
    float rs = rsqrtf(d2 * (1.f / 512.f) + 1e-5f);
    int c = tid * 4;
    float4 o;
    o.x = (v[0] - mu) * rs * g[c + 0] + bb[c + 0];
    o.y = (v[1] - mu) * rs * g[c + 1] + bb[c + 1];
    o.z = (v[2] - mu) * rs * g[c + 2] + bb[c + 2];
    o.w = (v[3] - mu) * rs * g[c + 3] + bb[c + 3];
    *(float4*)(out + base) = o;
}

__global__ void __launch_bounds__(256) loss_part_kernel(const float* __restrict__ a,
                                                        const float* __restrict__ b,
                                                        float* __restrict__ part) {
    __shared__ float sbuf[8];
    size_t base = (size_t)blockIdx.x * 1024 + (size_t)threadIdx.x * 4;
    float4 x = *(const float4*)(a + base);
    float4 y = *(const float4*)(b + base);
    float dx = x.x - y.x, dy = x.y - y.y, dz = x.z - y.z, dw = x.w - y.w;
    float s = dx * dx + dy * dy + dz * dz + dw * dw;
    s = block_red_sum(s, sbuf, 256);
    if (threadIdx.x == 0) part[blockIdx.x] = s;
}

__global__ void __launch_bounds__(256) loss_acc_kernel(const float* __restrict__ part,
                                                       float* __restrict__ loss) {
    __shared__ float sbuf[8];
    int tid = threadIdx.x;
    float s = part[tid] + part[tid + 256] + part[tid + 512] + part[tid + 768];
    s = block_red_sum(s, sbuf, 256);
    if (tid == 0) loss[0] += s;
}

// ---------------- generalized batched TF32 tensor-core GEMM ----------------
// Double-buffered (2-stage) smem pipeline, one __syncthreads per k-chunk.
// C = alpha * A @ B (+bias)(+gelu)(+resid)
// A row-major [M,K]; B: BNM ? B[n][k] : B[k][n].
// batch z: offset = (z/mod)*Outer + (z%mod)*Inner
// X3: 3xTF32 split for ~fp32 accuracy.
template<int TM, int TN, bool BNM, bool X3>
__global__ void __launch_bounds__(256, 2) gmma_kernel(
    const float* __restrict__ A, const float* __restrict__ B, float* __restrict__ C,
    int M, int N, int K, int lda, int ldb, int ldc,
    size_t aO, size_t aI, size_t bO, size_t bI, size_t cO, size_t cI, int mod,
    float alpha, const float* __restrict__ bias,
    const float* __restrict__ resid, int act)
{
    constexpr int MT = TM / 32;
    constexpr int NT = TN / 32;
    constexpr int AVN = TM / 64;
    constexpr int BVN = TN / 64;
    constexpr int BST = BNM ? 20 : (TN + 8);
    constexpr int ABSZ = TM * 20;
    constexpr int BBSZ = BNM ? (TN * 20) : (16 * (TN + 8));
    constexpr int STAGE = (ABSZ + BBSZ) * (X3 ? 2 : 1);
    extern __shared__ uint32_t dynsm[];

    const int z = blockIdx.z;
    const size_t aOff = (size_t)(z / mod) * aO + (size_t)(z % mod) * aI;
    const size_t bOff = (size_t)(z / mod) * bO + (size_t)(z % mod) * bI;
    const size_t cOff = (size_t)(z / mod) * cO + (size_t)(z % mod) * cI;
    const float* Ab = A + aOff;
    const float* Bb = B + bOff;
    float* Cb = C + cOff;

    const int tid = threadIdx.x;
    const int wid = tid >> 5, lane = tid & 31;
    const int wm = wid >> 2, wn = wid & 3;
    const int g = lane >> 2, tg = lane & 3;
    const int m0 = blockIdx.y * TM, n0 = blockIdx.x * TN;

    const int a_row = tid >> 2, a_kg = (tid & 3) << 2;

    float acc[MT][NT][4];
    #pragma unroll
    for (int i = 0; i < MT; i++)
        #pragma unroll
        for (int j = 0; j < NT; j++)
            #pragma unroll
            for (int c = 0; c < 4; c++) acc[i][j][c] = 0.f;

    float4 pa[AVN], pb[BVN];
    #pragma unroll
    for (int v = 0; v < AVN; v++)
        pa[v] = *(const float4*)(Ab + (size_t)(m0 + a_row + v * 64) * lda + a_kg);
    #pragma unroll
    for (int v = 0; v < BVN; v++) {
        int idx4 = tid + v * 256;
        if (BNM) {
            int row = idx4 >> 2, kg = (idx4 & 3) << 2;
            pb[v] = *(const float4*)(Bb + (size_t)(n0 + row) * ldb + kg);
        } else {
            int k = idx4 / (TN / 4), c = (idx4 % (TN / 4)) << 2;
            pb[v] = *(const float4*)(Bb + (size_t)k * ldb + n0 + c);
        }
    }

    auto store_stage = [&](uint32_t* SM) {
        uint32_t* AsH = SM;
        uint32_t* AsL = SM + ABSZ;
        uint32_t* BsH = SM + ABSZ * (X3 ? 2 : 1);
        uint32_t* BsL = BsH + BBSZ;
        #pragma unroll
        for (int v = 0; v < AVN; v++) {
            float f[4] = {pa[v].x, pa[v].y, pa[v].z, pa[v].w};
            uint4 h, l;
            h.x = f2tf32(f[0]); h.y = f2tf32(f[1]); h.z = f2tf32(f[2]); h.w = f2tf32(f[3]);
            *(uint4*)&AsH[(a_row + v * 64) * 20 + a_kg] = h;
            if (X3) {
                l.x = f2tf32(f[0] - __uint_as_float(h.x));
                l.y = f2tf32(f[1] - __uint_as_float(h.y));
                l.z = f2tf32(f[2] - __uint_as_float(h.z));
                l.w = f2tf32(f[3] - __uint_as_float(h.w));
                *(uint4*)&AsL[(a_row + v * 64) * 20 + a_kg] = l;
            }
        }
        #pragma unroll
        for (int v = 0; v < BVN; v++) {
            int idx4 = tid + v * 256;
            float f[4] = {pb[v].x, pb[v].y, pb[v].z, pb[v].w};
            uint4 h, l;
            h.x = f2tf32(f[0]); h.y = f2tf32(f[1]); h.z = f2tf32(f[2]); h.w = f2tf32(f[3]);
            if (X3) {
                l.x = f2tf32(f[0] - __uint_as_float(h.x));
                l.y = f2tf32(f[1] - __uint_as_float(h.y));
                l.z = f2tf32(f[2] - __uint_as_float(h.z));
                l.w = f2tf32(f[3] - __uint_as_float(h.w));
            }
            if (BNM) {
                int row = idx4 >> 2, kg = (idx4 & 3) << 2;
                *(uint4*)&BsH[row * 20 + kg] = h;
                if (X3) *(uint4*)&BsL[row * 20 + kg] = l;
            } else {
                int k = idx4 / (TN / 4), c = (idx4 % (TN / 4)) << 2;
                *(uint4*)&BsH[k * BST + c] = h;
                if (X3) *(uint4*)&BsL[k * BST + c] = l;
            }
        }
    };

    store_stage(dynsm);
    __syncthreads();

    const int nChunks = K >> 4;
    for (int c = 0; c < nChunks; c++) {
        const int cur = c & 1;
        uint32_t* SM = dynsm + cur * STAGE;
        uint32_t* AsH = SM;
        uint32_t* AsL = SM + ABSZ;
        uint32_t* BsH = SM + ABSZ * (X3 ? 2 : 1);
        uint32_t* BsL = BsH + BBSZ;
        const bool more = (c + 1 < nChunks);
        if (more) {
            int kn = (c + 1) << 4;
            #pragma unroll
            for (int v = 0; v < AVN; v++)
                pa[v] = *(const float4*)(Ab + (size_t)(m0 + a_row + v * 64) * lda + kn + a_kg);
            #pragma unroll
            for (int v = 0; v < BVN; v++) {
                int idx4 = tid + v * 256;
                if (BNM) {
                    int row = idx4 >> 2, kg = (idx4 & 3) << 2;
                    pb[v] = *(const float4*)(Bb + (size_t)(n0 + row) * ldb + kn + kg);
                } else {
                    int k = idx4 / (TN / 4), cc = (idx4 % (TN / 4)) << 2;
                    pb[v] = *(const float4*)(Bb + (size_t)(kn + k) * ldb + n0 + cc);
                }
            }
        }
        #pragma unroll
        for (int kk = 0; kk < 16; kk += 8) {
            uint32_t afH[MT][4], bfH[NT][2];
            uint32_t afL[X3 ? MT : 1][4], bfL[X3 ? NT : 1][2];
            #pragma unroll
            for (int i = 0; i < MT; i++) {
                int r = wm * (TM / 2) + i * 16 + g;
                afH[i][0] = AsH[r * 20 + kk + tg];
                afH[i][1] = AsH[(r + 8) * 20 + kk + tg];
                afH[i][2] = AsH[r * 20 + kk + tg + 4];
                afH[i][3] = AsH[(r + 8) * 20 + kk + tg + 4];
                if (X3) {
                    afL[i][0] = AsL[r * 20 + kk + tg];
                    afL[i][1] = AsL[(r + 8) * 20 + kk + tg];
                    afL[i][2] = AsL[r * 20 + kk + tg + 4];
                    afL[i][3] = AsL[(r + 8) * 20 + kk + tg + 4];
                }
            }
            #pragma unroll
            for (int j = 0; j < NT; j++) {
                int n = wn * (TN / 4) + j * 8 + g;
                if (BNM) {
                    bfH[j][0] = BsH[n * 20 + kk + tg];
                    bfH[j][1] = BsH[n * 20 + kk + tg + 4];
                    if (X3) {
                        bfL[j][0] = BsL[n * 20 + kk + tg];
                        bfL[j][1] = BsL[n * 20 + kk + tg + 4];
                    }
                } else {
                    bfH[j][0] = BsH[(kk + tg) * BST + n];
                    bfH[j][1] = BsH[(kk + tg + 4) * BST + n];
                    if (X3) {
                        bfL[j][0] = BsL[(kk + tg) * BST + n];
                        bfL[j][1] = BsL[(kk + tg + 4) * BST + n];
                    }
                }
            }
            #pragma unroll
            for (int i = 0; i < MT; i++)
                #pragma unroll
                for (int j = 0; j < NT; j++) {
                    asm volatile(
                        "mma.sync.aligned.m16n8k8.row.col.f32.tf32.tf32.f32 "
                        "{%0,%1,%2,%3}, {%4,%5,%6,%7}, {%8,%9}, {%0,%1,%2,%3};\n"
                        : "+f"(acc[i][j][0]), "+f"(acc[i][j][1]),
                          "+f"(acc[i][j][2]), "+f"(acc[i][j][3])
                        : "r"(afH[i][0]), "r"(afH[i][1]), "r"(afH[i][2]), "r"(afH[i][3]),
                          "r"(bfH[j][0]), "r"(bfH[j][1]));
                    if (X3) {
                        asm volatile(
                            "mma.sync.aligned.m16n8k8.row.col.f32.tf32.tf32.f32 "
                            "{%0,%1,%2,%3}, {%4,%5,%6,%7}, {%8,%9}, {%0,%1,%2,%3};\n"
                            : "+f"(acc[i][j][0]), "+f"(acc[i][j][1]),
                              "+f"(acc[i][j][2]), "+f"(acc[i][j][3])
                            : "r"(afL[i][0]), "r"(afL[i][1]), "r"(afL[i][2]), "r"(afL[i][3]),
                              "r"(bfH[j][0]), "r"(bfH[j][1]));
                        asm volatile(
                            "mma.sync.aligned.m16n8k8.row.col.f32.tf32.tf32.f32 "
                            "{%0,%1,%2,%3}, {%4,%5,%6,%7}, {%8,%9}, {%0,%1,%2,%3};\n"
                            : "+f"(acc[i][j][0]), "+f"(acc[i][j][1]),
                              "+f"(acc[i][j][2]), "+f"(acc[i][j][3])
                            : "r"(afH[i][0]), "r"(afH[i][1]), "r"(afH[i][2]), "r"(afH[i][3]),
                              "r"(bfL[j][0]), "r"(bfL[j][1]));
                    }
                }
        }
        if (more) {
            store_stage(dynsm + (cur ^ 1) * STAGE);
            __syncthreads();
        }
    }

    #pragma unroll
    for (int i = 0; i < MT; i++) {
        int m = m0 + wm * (TM / 2) + i * 16 + g;
        #pragma unroll
        for (int j = 0; j < NT; j++) {
            int n = n0 + wn * (TN / 4) + j * 8 + 2 * tg;
            float c0 = acc[i][j][0] * alpha, c1 = acc[i][j][1] * alpha;
            float c2 = acc[i][j][2] * alpha, c3 = acc[i][j][3] * alpha;
            if (bias) {
                float b0 = bias[n], b1 = bias[n + 1];
                c0 += b0; c1 += b1; c2 += b0; c3 += b1;
            }
            if (act) {
                c0 = 0.5f * c0 * (1.f + erff(c0 * 0.7071067811865475f));
                c1 = 0.5f * c1 * (1.f + erff(c1 * 0.7071067811865475f));
                c2 = 0.5f * c2 * (1.f + erff(c2 * 0.7071067811865475f));
                c3 = 0.5f * c3 * (1.f + erff(c3 * 0.7071067811865475f));
            }
            if (resid) {
                const float* Rb = resid + cOff;
                c0 += Rb[(size_t)m * ldc + n];
                c1 += Rb[(size_t)m * ldc + n + 1];
                c2 += Rb[(size_t)(m + 8) * ldc + n];
                c3 += Rb[(size_t)(m + 8) * ldc + n + 1];
            }
            float2 lo = {c0, c1}, hi = {c2, c3};
            *(float2*)(Cb + (size_t)m * ldc + n) = lo;
            *(float2*)(Cb + (size_t)(m + 8) * ldc + n) = hi;
        }
    }
}

template<int TM, int TN, bool BNM, bool X3>
constexpr int gmma_smem_bytes() {
    constexpr int ABSZ = TM * 20;
    constexpr int BBSZ = BNM ? (TN * 20) : (16 * (TN + 8));
    return 2 * (ABSZ + BBSZ) * (X3 ? 2 : 1) * 4;
}

// ---------------- softmax with optional fused shift()+pos add ----------------
template<bool POS>
__global__ void __launch_bounds__(128) softmax_kernel(float* __restrict__ S,
                                                      const float* __restrict__ P,
                                                      int klen) {
    __shared__ float sbuf[4];
    const int i = blockIdx.x, z = blockIdx.y, tid = threadIdx.x;
    float* row = S + ((size_t)z * 512 + i) * klen;
    const float* prow = POS ? (P + ((size_t)z * 512 + i) * KVN) : nullptr;
    float mx = -1e30f;
    for (int j = tid; j < klen; j += 128) {
        float v = row[j];
        if (POS) {
            int r = j + 511 - i;
            if (r < KVN) v += prow[r];
        }
        row[j] = v;
        mx = fmaxf(mx, v);
    }
    mx = block_red_max(mx, sbuf, 128);
    float sum = 0.f;
    for (int j = tid; j < klen; j += 128) {
        float e = expf(row[j] - mx);
        row[j] = e;
        sum += e;
    }
    sum = block_red_sum(sum, sbuf, 128);
    float inv = 1.f / sum;
    for (int j = tid; j < klen; j += 128) row[j] *= inv;
}

// ---------------- host wrappers ----------------
#define SET_SMEM(TMv, TNv, BNMv, X3v) \
    cudaFuncSetAttribute((const void*)gmma_kernel<TMv, TNv, BNMv, X3v>, \
        cudaFuncAttributeMaxDynamicSharedMemorySize, gmma_smem_bytes<TMv, TNv, BNMv, X3v>())

static void gemm_batched(const float* A, const float* B, float* C, int M, int N, int K,
                         int lda, int ldb, int ldc,
                         size_t aO, size_t aI, size_t bO, size_t bI, size_t cO, size_t cI,
                         int mod, int z, float alpha,
                         const float* bias, const float* resid, int act) {
    if ((M % 128 == 0) && (N % 128 == 0) && (size_t)(M / 128) * (N / 128) * z >= 120) {
        dim3 grid(N / 128, M / 128, z);
        gmma_kernel<128, 128, false, false>
            <<<grid, 256, gmma_smem_bytes<128, 128, false, false>()>>>(A, B, C, M, N, K, lda, ldb, ldc,
            aO, aI, bO, bI, cO, cI, mod, alpha, bias, resid, act);
    } else if ((M % 128 == 0) && (N % 64 == 0) && (size_t)(M / 128) * (N / 64) * z >= 120) {
        dim3 grid(N / 64, M / 128, z);
        gmma_kernel<128, 64, false, false>
            <<<grid, 256, gmma_smem_bytes<128, 64, false, false>()>>>(A, B, C, M, N, K, lda, ldb, ldc,
            aO, aI, bO, bI, cO, cI, mod, alpha, bias, resid, act);
    } else {
        dim3 grid(N / 64, M / 64, z);
        gmma_kernel<64, 64, false, false>
            <<<grid, 256, gmma_smem_bytes<64, 64, false, false>()>>>(A, B, C, M, N, K, lda, ldb, ldc,
            aO, aI, bO, bI, cO, cI, mod, alpha, bias, resid, act);
    }
}

static void gemm_proj(const float* A, const float* B, float* C, int M, int N, int K,
                      const float* bias = nullptr, const float* resid = nullptr, int act = 0) {
    gemm_batched(A, B, C, M, N, K, K, N, N, 0, 0, 0, 0, 0, 0, 1, 1, 1.f, bias, resid, act);
}

// S[z][512][klen] = alpha * Q_h @ K_h^T ; z = b*8+h
static void gemm_scores(const float* q, size_t qOuter, const float* kbase, size_t kOuter,
                        float* Sb, int klen, float alpha, bool x3) {
    dim3 grid(klen / 64, 512 / 128, 32);
    if (x3)
        gmma_kernel<128, 64, true, true>
            <<<grid, 256, gmma_smem_bytes<128, 64, true, true>()>>>(q, kbase, Sb, 512, klen, 64,
            512, 512, klen, qOuter, 64, kOuter, 64, (size_t)8 * 512 * klen, (size_t)512 * klen, 8,
            alpha, nullptr, nullptr, 0);
    else
        gmma_kernel<128, 64, true, false>
            <<<grid, 256, gmma_smem_bytes<128, 64, true, false>()>>>(q, kbase, Sb, 512, klen, 64,
            512, 512, klen, qOuter, 64, kOuter, 64, (size_t)8 * 512 * klen, (size_t)512 * klen, 8,
            alpha, nullptr, nullptr, 0);
}

// P[z][512][1152] = 8 * Q_h @ pos[h]^T
static void gemm_pos(const float* q, size_t qOuter, const float* pos, float* Pb) {
    dim3 grid(KVN / 64, 512 / 128, 32);
    gmma_kernel<128, 64, true, true>
        <<<grid, 256, gmma_smem_bytes<128, 64, true, true>()>>>(q, pos, Pb, 512, KVN, 64,
        512, 64, KVN, qOuter, 64, 0, (size_t)KVN * 64, (size_t)8 * 512 * KVN, (size_t)512 * KVN, 8,
        8.f, nullptr, nullptr, 0);
}

// out[b][i][h*64+d] = S_z @ V_h
static void gemm_av(const float* Sb, const float* vbase, size_t vOuter, float* out, int klen,
                    bool x3) {
    dim3 grid(1, 512 / 128, 32);
    if (x3)
        gmma_kernel<128, 64, false, true>
            <<<grid, 256, gmma_smem_bytes<128, 64, false, true>()>>>(Sb, vbase, out, 512, 64, klen,
            klen, 512, 512, (size_t)8 * 512 * klen, (size_t)512 * klen, vOuter, 64,
            (size_t)512 * 512, 64, 8, 1.f, nullptr, nullptr, 0);
    else
        gmma_kernel<128, 64, false, false>
            <<<grid, 256, gmma_smem_bytes<128, 64, false, false>()>>>(Sb, vbase, out, 512, 64, klen,
            klen, 512, 512, (size_t)8 * 512 * klen, (size_t)512 * klen, vOuter, 64,
            (size_t)512 * 512, 64, 8, 1.f, nullptr, nullptr, 0);
}

static void run_softmax(float* Sb, const float* Pb, int klen, bool pos) {
    dim3 grid(512, 32);
    if (pos) softmax_kernel<true><<<grid, 128>>>(Sb, Pb, klen);
    else     softmax_kernel<false><<<grid, 128>>>(Sb, nullptr, klen);
}

extern "C" void kernel_launch(void* const* d_in, const int* in_sizes, int n_in,
                              void* d_out, int out_size) {
    const int*   trg     = (const int*)  d_in[0];
    const float* latent  = (const float*)d_in[3];
    const float* mems    = (const float*)d_in[4];
    const float* cmems   = (const float*)d_in[5];
    const float* pos_emb = (const float*)d_in[6];
    const float* embed   = (const float*)d_in[7];
    const float* W_self  = (const float*)d_in[8];
    const float* ln1_g   = (const float*)d_in[9];
    const float* ln1_b   = (const float*)d_in[10];
    const float* conv_w  = (const float*)d_in[11];
    const float* conv_b  = (const float*)d_in[12];
    const float* W_src   = (const float*)d_in[13];
    const float* ln2_g   = (const float*)d_in[14];
    const float* ln2_b   = (const float*)d_in[15];
    const float* w1      = (const float*)d_in[16];
    const float* b1      = (const float*)d_in[17];
    const float* w2      = (const float*)d_in[18];
    const float* b2      = (const float*)d_in[19];

    SET_SMEM(128, 128, false, false);
    SET_SMEM(128, 64, false, false);
    SET_SMEM(64, 64, false, false);
    SET_SMEM(128, 64, true, true);
    SET_SMEM(128, 64, true, false);
    SET_SMEM(128, 64, false, true);

    float* Sc;
    cudaGetSymbolAddress((void**)&Sc, g_scratch);
    float* X    = Sc + O_X;
    float* KVb  = Sc + O_KV;
    float* QKV  = Sc + O_QKV;           // Q slab [4608,512]
    float* Kp   = QKV + EL_KV;          // K slab
    float* Vp   = QKV + 2 * EL_KV;      // V slab
    float* ATT  = Sc + O_ATT;
    float* A    = Sc + O_A;
    float* TMP  = Sc + O_TMP;
    float* QR   = Sc + O_QR;
    float* QR2  = Sc + O_QR2;
    float* KR   = Sc + O_KR;
    float* VR   = Sc + O_VR;
    float* KN   = Sc + O_KN;
    float* VN   = Sc + O_VN;
    float* TGT  = Sc + O_TGT;
    float* RNEW = Sc + O_RNEW;
    float* NCM  = Sc + O_NCM;
    float* CWT  = Sc + O_CWT;
    float* FF   = Sc + O_FF;
    float* Y    = Sc + O_Y;
    float* X1   = Sc + O_X1;
    float* PART = Sc + O_PART;
    float* LOSS = Sc + O_LOSS;
    float* SS   = Sc + O_S;
    float* PP   = Sc + O_P;

    zero_loss_kernel<<<1, 32>>>(LOSS);
    embed_kernel<<<(int)(EL_X / 256), 256>>>(trg, embed, X);

    for (int i = 0; i < NL; i++) {
        const float* mem = mems  + (size_t)i * BB * 512 * 512;
        const float* cm  = cmems + (size_t)i * BB * 128 * 512;
        const float* W0 = W_self + ((size_t)i * 4 + 0) * 512 * 512;
        const float* W1 = W_self + ((size_t)i * 4 + 1) * 512 * 512;
        const float* Ws0 = W_src + ((size_t)i * 4 + 0) * 512 * 512;
        const float* Ws1 = W_src + ((size_t)i * 4 + 1) * 512 * 512;
        const float* Ws3 = W_src + ((size_t)i * 4 + 3) * 512 * 512;
        const float* W3  = W_self + ((size_t)i * 4 + 3) * 512 * 512;

        // ---- self-attention over kv = [cmem, mem, x] ----
        kv_kernel<<<(int)(EL_KV / 256), 256>>>(cm, mem, X, KVb);
        gemm_batched(KVb, W0, QKV, 4608, 512, 512, 512, 512, 512,
                     0, 0, 0, 262144ull, 0, EL_KV, 3, 3, 1.f, nullptr, nullptr, 0);
        const float* Qx = QKV + 640ull * 512;
        gemm_pos(Qx, (size_t)KVN * 512, pos_emb, PP);
        gemm_scores(Qx, (size_t)KVN * 512, Kp, (size_t)KVN * 512, SS, KVN, 0.125f, true);
        run_softmax(SS, PP, KVN, true);
        gemm_av(SS, Vp, (size_t)KVN * 512, ATT, KVN, true);
        gemm_proj(ATT, W3, TMP, 2048, 512, 512, nullptr, X, 0);
        ln_kernel<<<2048, 128>>>(TMP, ln1_g + i * 512, ln1_b + i * 512, A);

        // ---- compressed-memory reconstruction loss (loss scalar only:
        //      single-TF32 per round-3 evidence) ----
        tconv_kernel<<<4096, 256>>>(conv_w + (size_t)i * 512 * 512 * 4, CWT);
        gemm_proj(mem, CWT, NCM, 512, 512, 2048, conv_b + i * 512);
        gemm_batched(A, W0, QR, 2048, 512, 512, 512, 512, 512,
                     0, 0, 0, (size_t)(Ws0 - W0), 0, (size_t)(QR2 - QR),
                     2, 2, 1.f, nullptr, nullptr, 0);
        gemm_scores(QR, (size_t)512 * 512, Kp + 128 * 512, (size_t)KVN * 512, SS, 512, 0.125f, false);
        run_softmax(SS, nullptr, 512, false);
        gemm_av(SS, Vp + 128 * 512, (size_t)KVN * 512, TGT, 512, false);
        gemm_batched(NCM, W1, KN, 512, 512, 512, 512, 512, 512,
                     0, 0, 0, 262144ull, 0, 262144ull, 2, 2, 1.f, nullptr, nullptr, 0);
        gemm_scores(QR, (size_t)512 * 512, KN, (size_t)128 * 512, SS, 128, 0.125f, false);
        run_softmax(SS, nullptr, 128, false);
        gemm_av(SS, VN, (size_t)128 * 512, RNEW, 128, false);
        loss_part_kernel<<<1024, 256>>>(RNEW, TGT, PART);
        loss_acc_kernel<<<1, 256>>>(PART, LOSS);

        // ---- cross-attention to latent (feeds x: keep X3) ----
        gemm_batched(latent, Ws1, KR, 1024, 512, 512, 512, 512, 512,
                     0, 0, 0, 262144ull, 0, (size_t)(VR - KR), 2, 2, 1.f, nullptr, nullptr, 0);
        gemm_scores(QR2, (size_t)512 * 512, KR, (size_t)256 * 512, SS, 256, 0.125f, true);
        run_softmax(SS, nullptr, 256, false);
        gemm_av(SS, VR, (size_t)256 * 512, TMP, 256, true);
        gemm_proj(TMP, Ws3, X1, 2048, 512, 512);

        // ---- FFN: x = x1 + gelu(LN(x1)@w1+b1)@w2 + b2 ----
        ln_kernel<<<2048, 128>>>(X1, ln2_g + i * 512, ln2_b + i * 512, Y);
        gemm_proj(Y,  w1 + (size_t)i * 512 * 2048, FF, 2048, 2048, 512,  b1 + (size_t)i * 2048, nullptr, 1);
        gemm_proj(FF, w2 + (size_t)i * 2048 * 512, X,  2048, 512,  2048, b2 + (size_t)i * 512,  X1,      0);
    }

    size_t nout = (size_t)out_size;
    out_kernel<<<(int)((nout + 255) / 256), 256>>>((float*)d_out, X, LOSS, nout);
}